// round 2
// baseline (speedup 1.0000x reference)
#include <cuda_runtime.h>

#define BB 8192
#define DD 2048
#define EE 16
#define PP 1024
#define CC0 64
#define CC1 128
#define LN_EPS 1e-5f

// output layout: flattened tuple concat (parent_logits, cl0, cl1, parent_proj, cp0, cp1)
#define OFF_PL  0
#define OFF_CL0 (BB*EE)
#define OFF_CL1 (OFF_CL0 + BB*CC0)
#define OFF_PP  (OFF_CL1 + BB*CC1)
#define OFF_CP0 (OFF_PP + BB*PP)
#define OFF_CP1 (OFF_CP0 + BB*PP)

// scratch (no allocation allowed -> device globals)
__device__ int g_class[BB];
__device__ int g_cnt[EE];
__device__ int g_cur[EE];
__device__ int g_off[EE + 1];
__device__ int g_sidx[BB];

__global__ void k_init() {
    int t = threadIdx.x;
    if (t < EE) { g_cnt[t] = 0; g_cur[t] = 0; }
}

// ---------------------------------------------------------------------------
// Parent FC: z = x @ pw_fc^T + pb_fc ; parent_logits = LN(z) ; class = argmax(z)
// BM=64 rows/block, 128 threads, intra-block 4-way K split.
// ---------------------------------------------------------------------------
__global__ __launch_bounds__(128) void k_parent_fc(
    const float* __restrict__ x, const float* __restrict__ w,
    const float* __restrict__ bias, float* __restrict__ out_pl)
{
    __shared__ __align__(16) float xs[32][68];
    __shared__ __align__(16) float ws[32][20];
    __shared__ float spart[4][64][17];

    const int t = threadIdx.x;
    const int rowg = t & 7;
    const int eg = (t >> 3) & 3;
    const int kg = t >> 5;
    const int brow = blockIdx.x * 64;

    float acc[8][4];
    #pragma unroll
    for (int i = 0; i < 8; i++)
        #pragma unroll
        for (int j = 0; j < 4; j++) acc[i][j] = 0.f;

    for (int kt = 0; kt < DD / 32; kt++) {
        float4 rx[4];
        float4 rw;
        #pragma unroll
        for (int i = 0; i < 4; i++) {
            int s = t + i * 128;
            int row = s >> 3, kq = s & 7;
            rx[i] = *(const float4*)&x[(size_t)(brow + row) * DD + kt * 32 + kq * 4];
        }
        {
            int e2 = t >> 3, kq = t & 7;
            rw = *(const float4*)&w[(size_t)e2 * DD + kt * 32 + kq * 4];
        }
        __syncthreads();
        #pragma unroll
        for (int i = 0; i < 4; i++) {
            int s = t + i * 128;
            int row = s >> 3, kq = s & 7;
            xs[kq * 4 + 0][row] = rx[i].x;
            xs[kq * 4 + 1][row] = rx[i].y;
            xs[kq * 4 + 2][row] = rx[i].z;
            xs[kq * 4 + 3][row] = rx[i].w;
        }
        {
            int e2 = t >> 3, kq = t & 7;
            ws[kq * 4 + 0][e2] = rw.x;
            ws[kq * 4 + 1][e2] = rw.y;
            ws[kq * 4 + 2][e2] = rw.z;
            ws[kq * 4 + 3][e2] = rw.w;
        }
        __syncthreads();
        #pragma unroll
        for (int kk2 = 0; kk2 < 8; kk2++) {
            int kk = kg * 8 + kk2;
            float4 a0 = *(const float4*)&xs[kk][rowg * 4];
            float4 a1 = *(const float4*)&xs[kk][32 + rowg * 4];
            float4 bq = *(const float4*)&ws[kk][eg * 4];
            float av[8] = {a0.x, a0.y, a0.z, a0.w, a1.x, a1.y, a1.z, a1.w};
            float bv[4] = {bq.x, bq.y, bq.z, bq.w};
            #pragma unroll
            for (int i = 0; i < 8; i++)
                #pragma unroll
                for (int j = 0; j < 4; j++) acc[i][j] += av[i] * bv[j];
        }
        __syncthreads();
    }

    #pragma unroll
    for (int i = 0; i < 8; i++) {
        int r = (i < 4) ? (rowg * 4 + i) : (32 + rowg * 4 + (i - 4));
        #pragma unroll
        for (int j = 0; j < 4; j++) spart[kg][r][eg * 4 + j] = acc[i][j];
    }
    __syncthreads();

    if (t < 64) {
        int r = t;
        int b = brow + r;
        float z[16];
        float mu = 0.f;
        #pragma unroll
        for (int e2 = 0; e2 < 16; e2++) {
            float v = spart[0][r][e2] + spart[1][r][e2] + spart[2][r][e2] + spart[3][r][e2]
                      + bias[e2];
            z[e2] = v;
            mu += v;
        }
        mu *= (1.f / 16.f);
        float var = 0.f;
        #pragma unroll
        for (int e2 = 0; e2 < 16; e2++) { float d = z[e2] - mu; var += d * d; }
        var *= (1.f / 16.f);
        float rs = rsqrtf(var + LN_EPS);

        float best = z[0];
        int cls = 0;
        #pragma unroll
        for (int e2 = 1; e2 < 16; e2++)
            if (z[e2] > best) { best = z[e2]; cls = e2; }  // first-max (jnp.argmax)

        #pragma unroll
        for (int q = 0; q < 4; q++) {
            float4 o = make_float4((z[q * 4 + 0] - mu) * rs, (z[q * 4 + 1] - mu) * rs,
                                   (z[q * 4 + 2] - mu) * rs, (z[q * 4 + 3] - mu) * rs);
            *(float4*)&out_pl[(size_t)b * 16 + q * 4] = o;
        }
        g_class[b] = cls;
        atomicAdd(&g_cnt[cls], 1);
    }
}

__global__ void k_scan() {
    if (threadIdx.x == 0) {
        int o = 0;
        for (int e = 0; e < EE; e++) { g_off[e] = o; o += g_cnt[e]; }
        g_off[EE] = o;
    }
}

__global__ void k_scatter() {
    int b = blockIdx.x * 256 + threadIdx.x;
    if (b < BB) {
        int e = g_class[b];
        int pos = g_off[e] + atomicAdd(&g_cur[e], 1);
        g_sidx[pos] = b;
    }
}

// ---------------------------------------------------------------------------
// Parent proj: out[b,p] = sum_e pl[b,e] * pw_proj[p,e] + pb_proj[p]
// ---------------------------------------------------------------------------
__global__ __launch_bounds__(256) void k_parent_proj(
    const float* __restrict__ pl, const float* __restrict__ w,
    const float* __restrict__ bias, float* __restrict__ out)
{
    __shared__ __align__(16) float spl[64][20];
    const int t = threadIdx.x;
    const int brow = blockIdx.x * 64;

    {
        int row = t >> 2, q = t & 3;
        float4 g = *(const float4*)&pl[(size_t)(brow + row) * 16 + q * 4];
        spl[row][q * 4 + 0] = g.x;
        spl[row][q * 4 + 1] = g.y;
        spl[row][q * 4 + 2] = g.z;
        spl[row][q * 4 + 3] = g.w;
    }
    __syncthreads();

    for (int pass = 0; pass < 2; pass++) {
        int p0 = pass * 512 + t * 2;
        float w0[16], w1[16];
        #pragma unroll
        for (int q = 0; q < 4; q++) {
            float4 a = *(const float4*)&w[(size_t)p0 * 16 + q * 4];
            w0[q * 4 + 0] = a.x; w0[q * 4 + 1] = a.y; w0[q * 4 + 2] = a.z; w0[q * 4 + 3] = a.w;
            float4 c = *(const float4*)&w[(size_t)(p0 + 1) * 16 + q * 4];
            w1[q * 4 + 0] = c.x; w1[q * 4 + 1] = c.y; w1[q * 4 + 2] = c.z; w1[q * 4 + 3] = c.w;
        }
        float b0 = bias[p0], b1 = bias[p0 + 1];

        for (int r = 0; r < 64; r++) {
            float a0 = b0, a1 = b1;
            #pragma unroll
            for (int q = 0; q < 4; q++) {
                float4 v = *(const float4*)&spl[r][q * 4];
                a0 += v.x * w0[q * 4 + 0] + v.y * w0[q * 4 + 1] + v.z * w0[q * 4 + 2] + v.w * w0[q * 4 + 3];
                a1 += v.x * w1[q * 4 + 0] + v.y * w1[q * 4 + 1] + v.z * w1[q * 4 + 2] + v.w * w1[q * 4 + 3];
            }
            float2 o = make_float2(a0, a1);
            *(float2*)&out[(size_t)(brow + r) * PP + p0] = o;
        }
    }
}

// ---------------------------------------------------------------------------
// Child FC + LN (grouped gather GEMM). BM=64, BN=C, BK=16, 128 threads,
// double-buffered smem, LN fused in-block.
// ---------------------------------------------------------------------------
template <int BN>
__global__ __launch_bounds__(128) void k_child_fc(
    const float* __restrict__ x, const float* __restrict__ w,
    const float* __restrict__ bias, float* __restrict__ out)
{
    constexpr int NC = BN / 64;
    constexpr int NW = BN / 32;
    const int e = blockIdx.y;
    const int start = g_off[e] + blockIdx.x * 64;
    const int end = g_off[e + 1];
    if (start >= end) return;

    __shared__ __align__(16) float xs[2][16][68];
    __shared__ __align__(16) float ws[2][16][BN + 4];
    __shared__ int sidx[64];
    __shared__ float sred[2][64][17];

    const int t = threadIdx.x;
    const int ty = t >> 4, tx = t & 15;

    if (t < 64) {
        int gi = start + t;
        sidx[t] = g_sidx[gi < end ? gi : start];
    }
    __syncthreads();

    float4 rx[2];
    float4 rw[NW];

    auto ldg_tile = [&](int kt) {
        #pragma unroll
        for (int i = 0; i < 2; i++) {
            int s = t + i * 128;
            int row = s >> 2, kq = s & 3;
            rx[i] = *(const float4*)&x[(size_t)sidx[row] * DD + kt * 16 + kq * 4];
        }
        #pragma unroll
        for (int i = 0; i < NW; i++) {
            int s = t + i * 128;
            int n = s >> 2, kq = s & 3;
            rw[i] = *(const float4*)&w[((size_t)e * BN + n) * DD + kt * 16 + kq * 4];
        }
    };
    auto sts_tile = [&](int buf) {
        #pragma unroll
        for (int i = 0; i < 2; i++) {
            int s = t + i * 128;
            int row = s >> 2, kq = s & 3;
            xs[buf][kq * 4 + 0][row] = rx[i].x;
            xs[buf][kq * 4 + 1][row] = rx[i].y;
            xs[buf][kq * 4 + 2][row] = rx[i].z;
            xs[buf][kq * 4 + 3][row] = rx[i].w;
        }
        #pragma unroll
        for (int i = 0; i < NW; i++) {
            int s = t + i * 128;
            int n = s >> 2, kq = s & 3;
            ws[buf][kq * 4 + 0][n] = rw[i].x;
            ws[buf][kq * 4 + 1][n] = rw[i].y;
            ws[buf][kq * 4 + 2][n] = rw[i].z;
            ws[buf][kq * 4 + 3][n] = rw[i].w;
        }
    };

    float acc[8][NC][4];
    #pragma unroll
    for (int i = 0; i < 8; i++)
        #pragma unroll
        for (int c = 0; c < NC; c++)
            #pragma unroll
            for (int j = 0; j < 4; j++) acc[i][c][j] = 0.f;

    ldg_tile(0);
    sts_tile(0);
    __syncthreads();

    const int NKT = DD / 16;
    for (int kt = 0; kt < NKT; kt++) {
        int cur = kt & 1;
        if (kt + 1 < NKT) ldg_tile(kt + 1);
        #pragma unroll
        for (int kk = 0; kk < 16; kk++) {
            float4 a0 = *(const float4*)&xs[cur][kk][ty * 8];
            float4 a1 = *(const float4*)&xs[cur][kk][ty * 8 + 4];
            float av[8] = {a0.x, a0.y, a0.z, a0.w, a1.x, a1.y, a1.z, a1.w};
            #pragma unroll
            for (int c = 0; c < NC; c++) {
                float4 bq = *(const float4*)&ws[cur][kk][c * 64 + tx * 4];
                float bv[4] = {bq.x, bq.y, bq.z, bq.w};
                #pragma unroll
                for (int i = 0; i < 8; i++)
                    #pragma unroll
                    for (int j = 0; j < 4; j++) acc[i][c][j] += av[i] * bv[j];
            }
        }
        __syncthreads();
        if (kt + 1 < NKT) {
            sts_tile(cur ^ 1);
            __syncthreads();
        }
    }

    float bf[NC][4];
    #pragma unroll
    for (int c = 0; c < NC; c++)
        #pragma unroll
        for (int j = 0; j < 4; j++) bf[c][j] = bias[(size_t)e * BN + c * 64 + tx * 4 + j];

    #pragma unroll
    for (int i = 0; i < 8; i++) {
        float ps = 0.f, pq = 0.f;
        #pragma unroll
        for (int c = 0; c < NC; c++)
            #pragma unroll
            for (int j = 0; j < 4; j++) {
                float v = acc[i][c][j] + bf[c][j];
                acc[i][c][j] = v;
                ps += v;
                pq += v * v;
            }
        sred[0][ty * 8 + i][tx] = ps;
        sred[1][ty * 8 + i][tx] = pq;
    }
    __syncthreads();

    if (t < 64) {
        float s = 0.f, q = 0.f;
        #pragma unroll
        for (int c = 0; c < 16; c++) { s += sred[0][t][c]; q += sred[1][t][c]; }
        float mu = s / (float)BN;
        float var = q / (float)BN - mu * mu;
        sred[0][t][16] = mu;
        sred[1][t][16] = rsqrtf(var + LN_EPS);
    }
    __syncthreads();

    #pragma unroll
    for (int i = 0; i < 8; i++) {
        int r = ty * 8 + i;
        if (start + r < end) {
            int b = sidx[r];
            float mu = sred[0][r][16], rs = sred[1][r][16];
            #pragma unroll
            for (int c = 0; c < NC; c++) {
                float4 o = make_float4((acc[i][c][0] - mu) * rs, (acc[i][c][1] - mu) * rs,
                                       (acc[i][c][2] - mu) * rs, (acc[i][c][3] - mu) * rs);
                *(float4*)&out[(size_t)b * BN + c * 64 + tx * 4] = o;
            }
        }
    }
}

// ---------------------------------------------------------------------------
// Child proj (grouped gather GEMM): out[b,p] = h[b] @ cw_proj[e]^T + cb_proj[e]
// BM=64, BN=128 (grid.z tiles over P=1024), K=CK, BK=16.
// ---------------------------------------------------------------------------
template <int CK>
__global__ __launch_bounds__(128) void k_child_proj(
    const float* __restrict__ h, const float* __restrict__ w,
    const float* __restrict__ bias, float* __restrict__ out)
{
    const int e = blockIdx.y;
    const int start = g_off[e] + blockIdx.x * 64;
    const int end = g_off[e + 1];
    if (start >= end) return;
    const int pbase = blockIdx.z * 128;

    __shared__ __align__(16) float hs[2][16][68];
    __shared__ __align__(16) float wsp[2][16][132];
    __shared__ int sidx[64];

    const int t = threadIdx.x;
    const int ty = t >> 4, tx = t & 15;

    if (t < 64) {
        int gi = start + t;
        sidx[t] = g_sidx[gi < end ? gi : start];
    }
    __syncthreads();

    float4 rh[2];
    float4 rw[4];

    auto ldg_tile = [&](int kt) {
        #pragma unroll
        for (int i = 0; i < 2; i++) {
            int s = t + i * 128;
            int row = s >> 2, kq = s & 3;
            rh[i] = *(const float4*)&h[(size_t)sidx[row] * CK + kt * 16 + kq * 4];
        }
        #pragma unroll
        for (int i = 0; i < 4; i++) {
            int s = t + i * 128;
            int n = s >> 2, kq = s & 3;
            rw[i] = *(const float4*)&w[(size_t)(e * PP + pbase + n) * CK + kt * 16 + kq * 4];
        }
    };
    auto sts_tile = [&](int buf) {
        #pragma unroll
        for (int i = 0; i < 2; i++) {
            int s = t + i * 128;
            int row = s >> 2, kq = s & 3;
            hs[buf][kq * 4 + 0][row] = rh[i].x;
            hs[buf][kq * 4 + 1][row] = rh[i].y;
            hs[buf][kq * 4 + 2][row] = rh[i].z;
            hs[buf][kq * 4 + 3][row] = rh[i].w;
        }
        #pragma unroll
        for (int i = 0; i < 4; i++) {
            int s = t + i * 128;
            int n = s >> 2, kq = s & 3;
            wsp[buf][kq * 4 + 0][n] = rw[i].x;
            wsp[buf][kq * 4 + 1][n] = rw[i].y;
            wsp[buf][kq * 4 + 2][n] = rw[i].z;
            wsp[buf][kq * 4 + 3][n] = rw[i].w;
        }
    };

    float acc[8][2][4];
    #pragma unroll
    for (int i = 0; i < 8; i++)
        #pragma unroll
        for (int c = 0; c < 2; c++)
            #pragma unroll
            for (int j = 0; j < 4; j++) acc[i][c][j] = 0.f;

    ldg_tile(0);
    sts_tile(0);
    __syncthreads();

    const int NKT = CK / 16;
    for (int kt = 0; kt < NKT; kt++) {
        int cur = kt & 1;
        if (kt + 1 < NKT) ldg_tile(kt + 1);
        #pragma unroll
        for (int kk = 0; kk < 16; kk++) {
            float4 a0 = *(const float4*)&hs[cur][kk][ty * 8];
            float4 a1 = *(const float4*)&hs[cur][kk][ty * 8 + 4];
            float av[8] = {a0.x, a0.y, a0.z, a0.w, a1.x, a1.y, a1.z, a1.w};
            #pragma unroll
            for (int c = 0; c < 2; c++) {
                float4 bq = *(const float4*)&wsp[cur][kk][c * 64 + tx * 4];
                float bv[4] = {bq.x, bq.y, bq.z, bq.w};
                #pragma unroll
                for (int i = 0; i < 8; i++)
                    #pragma unroll
                    for (int j = 0; j < 4; j++) acc[i][c][j] += av[i] * bv[j];
            }
        }
        __syncthreads();
        if (kt + 1 < NKT) {
            sts_tile(cur ^ 1);
            __syncthreads();
        }
    }

    #pragma unroll
    for (int i = 0; i < 8; i++) {
        int r = ty * 8 + i;
        if (start + r < end) {
            int b = sidx[r];
            #pragma unroll
            for (int c = 0; c < 2; c++) {
                int p = pbase + c * 64 + tx * 4;
                float4 bb = *(const float4*)&bias[(size_t)e * PP + p];
                float4 o = make_float4(acc[i][c][0] + bb.x, acc[i][c][1] + bb.y,
                                       acc[i][c][2] + bb.z, acc[i][c][3] + bb.w);
                *(float4*)&out[(size_t)b * PP + p] = o;
            }
        }
    }
}

// ---------------------------------------------------------------------------

extern "C" void kernel_launch(void* const* d_in, const int* in_sizes, int n_in,
                              void* d_out, int out_size) {
    const float* x       = (const float*)d_in[0];
    const float* pw_fc   = (const float*)d_in[1];
    const float* pb_fc   = (const float*)d_in[2];
    const float* pw_proj = (const float*)d_in[3];
    const float* pb_proj = (const float*)d_in[4];
    const float* cw_fc0  = (const float*)d_in[5];
    const float* cb_fc0  = (const float*)d_in[6];
    const float* cw_pr0  = (const float*)d_in[7];
    const float* cb_pr0  = (const float*)d_in[8];
    const float* cw_fc1  = (const float*)d_in[9];
    const float* cb_fc1  = (const float*)d_in[10];
    const float* cw_pr1  = (const float*)d_in[11];
    const float* cb_pr1  = (const float*)d_in[12];
    float* out = (float*)d_out;

    k_init<<<1, 32>>>();
    k_parent_fc<<<BB / 64, 128>>>(x, pw_fc, pb_fc, out + OFF_PL);
    k_scan<<<1, 32>>>();
    k_scatter<<<BB / 256, 256>>>();
    k_parent_proj<<<BB / 64, 256>>>(out + OFF_PL, pw_proj, pb_proj, out + OFF_PP);

    // Grouped child GEMMs. Worst case one expert holds all B rows, so grid.x
    // must cover ceil(B/64) blocks per expert; empty tail blocks exit early
    // (start >= end).
    dim3 gfc(BB / 64, EE);
    k_child_fc<CC0><<<gfc, 128>>>(x, cw_fc0, cb_fc0, out + OFF_CL0);
    k_child_fc<CC1><<<gfc, 128>>>(x, cw_fc1, cb_fc1, out + OFF_CL1);

    dim3 gpr(BB / 64, EE, PP / 128);
    k_child_proj<CC0><<<gpr, 128>>>(out + OFF_CL0, cw_pr0, cb_pr0, out + OFF_CP0);
    k_child_proj<CC1><<<gpr, 128>>>(out + OFF_CL1, cw_pr1, cb_pr1, out + OFF_CP1);
}

// round 3
// speedup vs baseline: 1.0201x; 1.0201x over previous
#include <cuda_runtime.h>

#define BB 8192
#define DD 2048
#define EE 16
#define PP 1024
#define CC0 64
#define CC1 128
#define LN_EPS 1e-5f

// output layout: flattened tuple concat (parent_logits, cl0, cl1, parent_proj, cp0, cp1)
#define OFF_PL  0
#define OFF_CL0 (BB*EE)
#define OFF_CL1 (OFF_CL0 + BB*CC0)
#define OFF_PP  (OFF_CL1 + BB*CC1)
#define OFF_CP0 (OFF_PP + BB*PP)
#define OFF_CP1 (OFF_CP0 + BB*PP)

typedef unsigned long long u64t;

// packed f32x2 helpers (FFMA2 — 2x fp32 FMA throughput, exact fp32 per lane)
__device__ __forceinline__ u64t pk2(float lo, float hi) {
    u64t r;
    asm("mov.b64 %0, {%1, %2};" : "=l"(r) : "f"(lo), "f"(hi));
    return r;
}
__device__ __forceinline__ void upk2(u64t v, float& lo, float& hi) {
    asm("mov.b64 {%0, %1}, %2;" : "=f"(lo), "=f"(hi) : "l"(v));
}
__device__ __forceinline__ void ffma2(u64t& d, u64t a, u64t b) {
    asm("fma.rn.f32x2 %0, %1, %2, %0;" : "+l"(d) : "l"(a), "l"(b));
}

// scratch (no allocation allowed -> device globals)
__device__ int g_class[BB];
__device__ int g_cnt[EE];
__device__ int g_cur[EE];
__device__ int g_off[EE + 1];
__device__ int g_sidx[BB];

__global__ void k_init() {
    int t = threadIdx.x;
    if (t < EE) { g_cnt[t] = 0; g_cur[t] = 0; }
}

// ---------------------------------------------------------------------------
// Parent FC (exact fp32 — gates argmax): z = x @ pw_fc^T + pb_fc ;
// parent_logits = LN(z) ; class = argmax(z)
// ---------------------------------------------------------------------------
__global__ __launch_bounds__(128) void k_parent_fc(
    const float* __restrict__ x, const float* __restrict__ w,
    const float* __restrict__ bias, float* __restrict__ out_pl)
{
    __shared__ __align__(16) float xs[32][68];
    __shared__ __align__(16) float ws[32][20];
    __shared__ float spart[4][64][17];

    const int t = threadIdx.x;
    const int rowg = t & 7;
    const int eg = (t >> 3) & 3;
    const int kg = t >> 5;
    const int brow = blockIdx.x * 64;

    float acc[8][4];
    #pragma unroll
    for (int i = 0; i < 8; i++)
        #pragma unroll
        for (int j = 0; j < 4; j++) acc[i][j] = 0.f;

    for (int kt = 0; kt < DD / 32; kt++) {
        float4 rx[4];
        float4 rw;
        #pragma unroll
        for (int i = 0; i < 4; i++) {
            int s = t + i * 128;
            int row = s >> 3, kq = s & 7;
            rx[i] = *(const float4*)&x[(size_t)(brow + row) * DD + kt * 32 + kq * 4];
        }
        {
            int e2 = t >> 3, kq = t & 7;
            rw = *(const float4*)&w[(size_t)e2 * DD + kt * 32 + kq * 4];
        }
        __syncthreads();
        #pragma unroll
        for (int i = 0; i < 4; i++) {
            int s = t + i * 128;
            int row = s >> 3, kq = s & 7;
            xs[kq * 4 + 0][row] = rx[i].x;
            xs[kq * 4 + 1][row] = rx[i].y;
            xs[kq * 4 + 2][row] = rx[i].z;
            xs[kq * 4 + 3][row] = rx[i].w;
        }
        {
            int e2 = t >> 3, kq = t & 7;
            ws[kq * 4 + 0][e2] = rw.x;
            ws[kq * 4 + 1][e2] = rw.y;
            ws[kq * 4 + 2][e2] = rw.z;
            ws[kq * 4 + 3][e2] = rw.w;
        }
        __syncthreads();
        #pragma unroll
        for (int kk2 = 0; kk2 < 8; kk2++) {
            int kk = kg * 8 + kk2;
            float4 a0 = *(const float4*)&xs[kk][rowg * 4];
            float4 a1 = *(const float4*)&xs[kk][32 + rowg * 4];
            float4 bq = *(const float4*)&ws[kk][eg * 4];
            float av[8] = {a0.x, a0.y, a0.z, a0.w, a1.x, a1.y, a1.z, a1.w};
            float bv[4] = {bq.x, bq.y, bq.z, bq.w};
            #pragma unroll
            for (int i = 0; i < 8; i++)
                #pragma unroll
                for (int j = 0; j < 4; j++) acc[i][j] += av[i] * bv[j];
        }
        __syncthreads();
    }

    #pragma unroll
    for (int i = 0; i < 8; i++) {
        int r = (i < 4) ? (rowg * 4 + i) : (32 + rowg * 4 + (i - 4));
        #pragma unroll
        for (int j = 0; j < 4; j++) spart[kg][r][eg * 4 + j] = acc[i][j];
    }
    __syncthreads();

    if (t < 64) {
        int r = t;
        int b = brow + r;
        float z[16];
        float mu = 0.f;
        #pragma unroll
        for (int e2 = 0; e2 < 16; e2++) {
            float v = spart[0][r][e2] + spart[1][r][e2] + spart[2][r][e2] + spart[3][r][e2]
                      + bias[e2];
            z[e2] = v;
            mu += v;
        }
        mu *= (1.f / 16.f);
        float var = 0.f;
        #pragma unroll
        for (int e2 = 0; e2 < 16; e2++) { float d = z[e2] - mu; var += d * d; }
        var *= (1.f / 16.f);
        float rs = rsqrtf(var + LN_EPS);

        float best = z[0];
        int cls = 0;
        #pragma unroll
        for (int e2 = 1; e2 < 16; e2++)
            if (z[e2] > best) { best = z[e2]; cls = e2; }  // first-max (jnp.argmax)

        #pragma unroll
        for (int q = 0; q < 4; q++) {
            float4 o = make_float4((z[q * 4 + 0] - mu) * rs, (z[q * 4 + 1] - mu) * rs,
                                   (z[q * 4 + 2] - mu) * rs, (z[q * 4 + 3] - mu) * rs);
            *(float4*)&out_pl[(size_t)b * 16 + q * 4] = o;
        }
        g_class[b] = cls;
        atomicAdd(&g_cnt[cls], 1);
    }
}

__global__ void k_scan() {
    if (threadIdx.x == 0) {
        int o = 0;
        for (int e = 0; e < EE; e++) { g_off[e] = o; o += g_cnt[e]; }
        g_off[EE] = o;
    }
}

__global__ void k_scatter() {
    int b = blockIdx.x * 256 + threadIdx.x;
    if (b < BB) {
        int e = g_class[b];
        int pos = g_off[e] + atomicAdd(&g_cur[e], 1);
        g_sidx[pos] = b;
    }
}

// ---------------------------------------------------------------------------
// Parent proj: out[b,p] = sum_e pl[b,e] * pw_proj[p,e] + pb_proj[p]
// ---------------------------------------------------------------------------
__global__ __launch_bounds__(256) void k_parent_proj(
    const float* __restrict__ pl, const float* __restrict__ w,
    const float* __restrict__ bias, float* __restrict__ out)
{
    __shared__ __align__(16) float spl[64][20];
    const int t = threadIdx.x;
    const int brow = blockIdx.x * 64;

    {
        int row = t >> 2, q = t & 3;
        float4 g = *(const float4*)&pl[(size_t)(brow + row) * 16 + q * 4];
        spl[row][q * 4 + 0] = g.x;
        spl[row][q * 4 + 1] = g.y;
        spl[row][q * 4 + 2] = g.z;
        spl[row][q * 4 + 3] = g.w;
    }
    __syncthreads();

    for (int pass = 0; pass < 2; pass++) {
        int p0 = pass * 512 + t * 2;
        float w0[16], w1[16];
        #pragma unroll
        for (int q = 0; q < 4; q++) {
            float4 a = *(const float4*)&w[(size_t)p0 * 16 + q * 4];
            w0[q * 4 + 0] = a.x; w0[q * 4 + 1] = a.y; w0[q * 4 + 2] = a.z; w0[q * 4 + 3] = a.w;
            float4 c = *(const float4*)&w[(size_t)(p0 + 1) * 16 + q * 4];
            w1[q * 4 + 0] = c.x; w1[q * 4 + 1] = c.y; w1[q * 4 + 2] = c.z; w1[q * 4 + 3] = c.w;
        }
        float b0 = bias[p0], b1 = bias[p0 + 1];

        for (int r = 0; r < 64; r++) {
            float a0 = b0, a1 = b1;
            #pragma unroll
            for (int q = 0; q < 4; q++) {
                float4 v = *(const float4*)&spl[r][q * 4];
                a0 += v.x * w0[q * 4 + 0] + v.y * w0[q * 4 + 1] + v.z * w0[q * 4 + 2] + v.w * w0[q * 4 + 3];
                a1 += v.x * w1[q * 4 + 0] + v.y * w1[q * 4 + 1] + v.z * w1[q * 4 + 2] + v.w * w1[q * 4 + 3];
            }
            float2 o = make_float2(a0, a1);
            *(float2*)&out[(size_t)(brow + r) * PP + p0] = o;
        }
    }
}

// ---------------------------------------------------------------------------
// Child FC + LN (grouped gather GEMM), FFMA2 inner loop.
// BM=64, BN=C, BK=16, 128 threads, double-buffered smem, single sync/tile,
// row-paired f32x2 accumulators, LN fused in-block.
// ---------------------------------------------------------------------------
template <int BN>
__global__ __launch_bounds__(128) void k_child_fc(
    const float* __restrict__ x, const float* __restrict__ w,
    const float* __restrict__ bias, float* __restrict__ out)
{
    constexpr int NC = BN / 64;
    constexpr int NW = BN / 32;
    const int e = blockIdx.y;
    const int start = g_off[e] + blockIdx.x * 64;
    const int end = g_off[e + 1];
    if (start >= end) return;

    __shared__ __align__(16) float xs[2][16][68];
    __shared__ __align__(16) float ws[2][16][BN + 4];
    __shared__ int sidx[64];
    __shared__ float sred[2][64][17];

    const int t = threadIdx.x;
    const int ty = t >> 4, tx = t & 15;

    if (t < 64) {
        int gi = start + t;
        sidx[t] = g_sidx[gi < end ? gi : start];
    }
    __syncthreads();

    float4 rx[2];
    float4 rw[NW];

    auto ldg_tile = [&](int kt) {
        #pragma unroll
        for (int i = 0; i < 2; i++) {
            int s = t + i * 128;
            int row = s >> 2, kq = s & 3;
            rx[i] = *(const float4*)&x[(size_t)sidx[row] * DD + kt * 16 + kq * 4];
        }
        #pragma unroll
        for (int i = 0; i < NW; i++) {
            int s = t + i * 128;
            int n = s >> 2, kq = s & 3;
            rw[i] = *(const float4*)&w[((size_t)e * BN + n) * DD + kt * 16 + kq * 4];
        }
    };
    auto sts_tile = [&](int buf) {
        #pragma unroll
        for (int i = 0; i < 2; i++) {
            int s = t + i * 128;
            int row = s >> 2, kq = s & 3;
            xs[buf][kq * 4 + 0][row] = rx[i].x;
            xs[buf][kq * 4 + 1][row] = rx[i].y;
            xs[buf][kq * 4 + 2][row] = rx[i].z;
            xs[buf][kq * 4 + 3][row] = rx[i].w;
        }
        #pragma unroll
        for (int i = 0; i < NW; i++) {
            int s = t + i * 128;
            int n = s >> 2, kq = s & 3;
            ws[buf][kq * 4 + 0][n] = rw[i].x;
            ws[buf][kq * 4 + 1][n] = rw[i].y;
            ws[buf][kq * 4 + 2][n] = rw[i].z;
            ws[buf][kq * 4 + 3][n] = rw[i].w;
        }
    };

    // row-paired accumulators: acc2[ip][c][j] holds rows (ty*8+2ip, ty*8+2ip+1)
    u64t acc2[4][NC][4];
    #pragma unroll
    for (int ip = 0; ip < 4; ip++)
        #pragma unroll
        for (int c = 0; c < NC; c++)
            #pragma unroll
            for (int j = 0; j < 4; j++) acc2[ip][c][j] = 0ull;

    ldg_tile(0);
    sts_tile(0);
    __syncthreads();

    const int NKT = DD / 16;
    for (int kt = 0; kt < NKT; kt++) {
        int cur = kt & 1;
        if (kt + 1 < NKT) ldg_tile(kt + 1);
        #pragma unroll
        for (int kk = 0; kk < 16; kk++) {
            ulonglong2 a01 = *(const ulonglong2*)&xs[cur][kk][ty * 8];
            ulonglong2 a23 = *(const ulonglong2*)&xs[cur][kk][ty * 8 + 4];
            u64t ap[4] = {a01.x, a01.y, a23.x, a23.y};
            #pragma unroll
            for (int c = 0; c < NC; c++) {
                float4 bq = *(const float4*)&ws[cur][kk][c * 64 + tx * 4];
                u64t bb[4] = {pk2(bq.x, bq.x), pk2(bq.y, bq.y),
                              pk2(bq.z, bq.z), pk2(bq.w, bq.w)};
                #pragma unroll
                for (int ip = 0; ip < 4; ip++)
                    #pragma unroll
                    for (int j = 0; j < 4; j++) ffma2(acc2[ip][c][j], ap[ip], bb[j]);
            }
        }
        if (kt + 1 < NKT) sts_tile((kt + 1) & 1);
        __syncthreads();
    }

    float bf[NC][4];
    #pragma unroll
    for (int c = 0; c < NC; c++)
        #pragma unroll
        for (int j = 0; j < 4; j++) bf[c][j] = bias[(size_t)e * BN + c * 64 + tx * 4 + j];

    // unpack + bias, LN partial sums
    float accf[8][NC][4];
    #pragma unroll
    for (int ip = 0; ip < 4; ip++) {
        float psl = 0.f, pql = 0.f, psh = 0.f, pqh = 0.f;
        #pragma unroll
        for (int c = 0; c < NC; c++)
            #pragma unroll
            for (int j = 0; j < 4; j++) {
                float vl, vh;
                upk2(acc2[ip][c][j], vl, vh);
                vl += bf[c][j];
                vh += bf[c][j];
                accf[2 * ip + 0][c][j] = vl;
                accf[2 * ip + 1][c][j] = vh;
                psl += vl; pql += vl * vl;
                psh += vh; pqh += vh * vh;
            }
        sred[0][ty * 8 + 2 * ip + 0][tx] = psl;
        sred[1][ty * 8 + 2 * ip + 0][tx] = pql;
        sred[0][ty * 8 + 2 * ip + 1][tx] = psh;
        sred[1][ty * 8 + 2 * ip + 1][tx] = pqh;
    }
    __syncthreads();

    if (t < 64) {
        float s = 0.f, q = 0.f;
        #pragma unroll
        for (int c = 0; c < 16; c++) { s += sred[0][t][c]; q += sred[1][t][c]; }
        float mu = s / (float)BN;
        float var = q / (float)BN - mu * mu;
        sred[0][t][16] = mu;
        sred[1][t][16] = rsqrtf(var + LN_EPS);
    }
    __syncthreads();

    #pragma unroll
    for (int i = 0; i < 8; i++) {
        int r = ty * 8 + i;
        if (start + r < end) {
            int b = sidx[r];
            float mu = sred[0][r][16], rs = sred[1][r][16];
            #pragma unroll
            for (int c = 0; c < NC; c++) {
                float4 o = make_float4((accf[i][c][0] - mu) * rs, (accf[i][c][1] - mu) * rs,
                                       (accf[i][c][2] - mu) * rs, (accf[i][c][3] - mu) * rs);
                *(float4*)&out[(size_t)b * BN + c * 64 + tx * 4] = o;
            }
        }
    }
}

// ---------------------------------------------------------------------------
// Child proj (both levels in ONE launch): out[b,p] = h[b] @ w[e]^T + bias[e]
// grid.z in [0,16): z<8 -> level0 (CK=64), z>=8 -> level1 (CK=128).
// BM=64, BN=128 p-tile, BK=16, FFMA2 inner loop.
// ---------------------------------------------------------------------------
__global__ __launch_bounds__(128) void k_child_proj(
    const float* __restrict__ h0, const float* __restrict__ w0,
    const float* __restrict__ b0, float* __restrict__ o0,
    const float* __restrict__ h1, const float* __restrict__ w1,
    const float* __restrict__ b1, float* __restrict__ o1)
{
    const int e = blockIdx.y;
    const int start = g_off[e] + blockIdx.x * 64;
    const int end = g_off[e + 1];
    if (start >= end) return;

    const int level = blockIdx.z >> 3;
    const int pbase = (blockIdx.z & 7) * 128;
    const int CK = level ? CC1 : CC0;
    const float* __restrict__ h = level ? h1 : h0;
    const float* __restrict__ w = level ? w1 : w0;
    const float* __restrict__ bias = level ? b1 : b0;
    float* __restrict__ out = level ? o1 : o0;

    __shared__ __align__(16) float hs[2][16][68];
    __shared__ __align__(16) float wsp[2][16][132];
    __shared__ int sidx[64];

    const int t = threadIdx.x;
    const int ty = t >> 4, tx = t & 15;

    if (t < 64) {
        int gi = start + t;
        sidx[t] = g_sidx[gi < end ? gi : start];
    }
    __syncthreads();

    float4 rh[2];
    float4 rw[4];

    auto ldg_tile = [&](int kt) {
        #pragma unroll
        for (int i = 0; i < 2; i++) {
            int s = t + i * 128;
            int row = s >> 2, kq = s & 3;
            rh[i] = *(const float4*)&h[(size_t)sidx[row] * CK + kt * 16 + kq * 4];
        }
        #pragma unroll
        for (int i = 0; i < 4; i++) {
            int s = t + i * 128;
            int n = s >> 2, kq = s & 3;
            rw[i] = *(const float4*)&w[(size_t)(e * PP + pbase + n) * CK + kt * 16 + kq * 4];
        }
    };
    auto sts_tile = [&](int buf) {
        #pragma unroll
        for (int i = 0; i < 2; i++) {
            int s = t + i * 128;
            int row = s >> 2, kq = s & 3;
            hs[buf][kq * 4 + 0][row] = rh[i].x;
            hs[buf][kq * 4 + 1][row] = rh[i].y;
            hs[buf][kq * 4 + 2][row] = rh[i].z;
            hs[buf][kq * 4 + 3][row] = rh[i].w;
        }
        #pragma unroll
        for (int i = 0; i < 4; i++) {
            int s = t + i * 128;
            int n = s >> 2, kq = s & 3;
            wsp[buf][kq * 4 + 0][n] = rw[i].x;
            wsp[buf][kq * 4 + 1][n] = rw[i].y;
            wsp[buf][kq * 4 + 2][n] = rw[i].z;
            wsp[buf][kq * 4 + 3][n] = rw[i].w;
        }
    };

    u64t acc2[4][2][4];
    #pragma unroll
    for (int ip = 0; ip < 4; ip++)
        #pragma unroll
        for (int c = 0; c < 2; c++)
            #pragma unroll
            for (int j = 0; j < 4; j++) acc2[ip][c][j] = 0ull;

    ldg_tile(0);
    sts_tile(0);
    __syncthreads();

    const int NKT = CK / 16;
    for (int kt = 0; kt < NKT; kt++) {
        int cur = kt & 1;
        if (kt + 1 < NKT) ldg_tile(kt + 1);
        #pragma unroll
        for (int kk = 0; kk < 16; kk++) {
            ulonglong2 a01 = *(const ulonglong2*)&hs[cur][kk][ty * 8];
            ulonglong2 a23 = *(const ulonglong2*)&hs[cur][kk][ty * 8 + 4];
            u64t ap[4] = {a01.x, a01.y, a23.x, a23.y};
            #pragma unroll
            for (int c = 0; c < 2; c++) {
                float4 bq = *(const float4*)&wsp[cur][kk][c * 64 + tx * 4];
                u64t bb[4] = {pk2(bq.x, bq.x), pk2(bq.y, bq.y),
                              pk2(bq.z, bq.z), pk2(bq.w, bq.w)};
                #pragma unroll
                for (int ip = 0; ip < 4; ip++)
                    #pragma unroll
                    for (int j = 0; j < 4; j++) ffma2(acc2[ip][c][j], ap[ip], bb[j]);
            }
        }
        if (kt + 1 < NKT) sts_tile((kt + 1) & 1);
        __syncthreads();
    }

    #pragma unroll
    for (int ip = 0; ip < 4; ip++) {
        int r0 = ty * 8 + 2 * ip;
        #pragma unroll
        for (int half = 0; half < 2; half++) {
            int r = r0 + half;
            if (start + r < end) {
                int b = sidx[r];
                #pragma unroll
                for (int c = 0; c < 2; c++) {
                    int p = pbase + c * 64 + tx * 4;
                    float4 bb4 = *(const float4*)&bias[(size_t)e * PP + p];
                    float v0l, v0h, v1l, v1h, v2l, v2h, v3l, v3h;
                    upk2(acc2[ip][c][0], v0l, v0h);
                    upk2(acc2[ip][c][1], v1l, v1h);
                    upk2(acc2[ip][c][2], v2l, v2h);
                    upk2(acc2[ip][c][3], v3l, v3h);
                    float4 o = half
                        ? make_float4(v0h + bb4.x, v1h + bb4.y, v2h + bb4.z, v3h + bb4.w)
                        : make_float4(v0l + bb4.x, v1l + bb4.y, v2l + bb4.z, v3l + bb4.w);
                    *(float4*)&out[(size_t)b * PP + p] = o;
                }
            }
        }
    }
}

// ---------------------------------------------------------------------------

extern "C" void kernel_launch(void* const* d_in, const int* in_sizes, int n_in,
                              void* d_out, int out_size) {
    const float* x       = (const float*)d_in[0];
    const float* pw_fc   = (const float*)d_in[1];
    const float* pb_fc   = (const float*)d_in[2];
    const float* pw_proj = (const float*)d_in[3];
    const float* pb_proj = (const float*)d_in[4];
    const float* cw_fc0  = (const float*)d_in[5];
    const float* cb_fc0  = (const float*)d_in[6];
    const float* cw_pr0  = (const float*)d_in[7];
    const float* cb_pr0  = (const float*)d_in[8];
    const float* cw_fc1  = (const float*)d_in[9];
    const float* cb_fc1  = (const float*)d_in[10];
    const float* cw_pr1  = (const float*)d_in[11];
    const float* cb_pr1  = (const float*)d_in[12];
    float* out = (float*)d_out;

    k_init<<<1, 32>>>();
    k_parent_fc<<<BB / 64, 128>>>(x, pw_fc, pb_fc, out + OFF_PL);
    k_scan<<<1, 32>>>();
    k_scatter<<<BB / 256, 256>>>();
    k_parent_proj<<<BB / 64, 256>>>(out + OFF_PL, pw_proj, pb_proj, out + OFF_PP);

    dim3 gfc(BB / 64, EE);
    k_child_fc<CC0><<<gfc, 128>>>(x, cw_fc0, cb_fc0, out + OFF_CL0);
    k_child_fc<CC1><<<gfc, 128>>>(x, cw_fc1, cb_fc1, out + OFF_CL1);

    dim3 gpr(BB / 64, EE, 16);
    k_child_proj<<<gpr, 128>>>(out + OFF_CL0, cw_pr0, cb_pr0, out + OFF_CP0,
                               out + OFF_CL1, cw_pr1, cb_pr1, out + OFF_CP1);
}

// round 4
// speedup vs baseline: 1.2351x; 1.2107x over previous
#include <cuda_runtime.h>

#define BB 8192
#define DD 2048
#define EE 16
#define PP 1024
#define CC0 64
#define CC1 128
#define LN_EPS 1e-5f

// output layout: flattened tuple concat (parent_logits, cl0, cl1, parent_proj, cp0, cp1)
#define OFF_PL  0
#define OFF_CL0 (BB*EE)
#define OFF_CL1 (OFF_CL0 + BB*CC0)
#define OFF_PP  (OFF_CL1 + BB*CC1)
#define OFF_CP0 (OFF_PP + BB*PP)
#define OFF_CP1 (OFF_CP0 + BB*PP)

typedef unsigned long long u64t;

// packed f32x2 helpers (FFMA2 — 2x fp32 throughput, exact fp32 per lane)
__device__ __forceinline__ u64t pk2(float lo, float hi) {
    u64t r;
    asm("mov.b64 %0, {%1, %2};" : "=l"(r) : "f"(lo), "f"(hi));
    return r;
}
__device__ __forceinline__ void upk2(u64t v, float& lo, float& hi) {
    asm("mov.b64 {%0, %1}, %2;" : "=f"(lo), "=f"(hi) : "l"(v));
}
__device__ __forceinline__ void ffma2(u64t& d, u64t a, u64t b) {
    asm("fma.rn.f32x2 %0, %1, %2, %0;" : "+l"(d) : "l"(a), "l"(b));
}

// scratch (no allocation allowed -> device globals)
__device__ int g_class[BB];
__device__ int g_cnt[EE];
__device__ int g_cur[EE];
__device__ int g_off[EE + 1];
__device__ int g_sidx[BB];

__global__ void k_init() {
    int t = threadIdx.x;
    if (t < EE) { g_cnt[t] = 0; g_cur[t] = 0; }
}

// ---------------------------------------------------------------------------
// Parent FC (exact fp32 — gates argmax)
// ---------------------------------------------------------------------------
__global__ __launch_bounds__(128) void k_parent_fc(
    const float* __restrict__ x, const float* __restrict__ w,
    const float* __restrict__ bias, float* __restrict__ out_pl)
{
    __shared__ __align__(16) float xs[32][68];
    __shared__ __align__(16) float ws[32][20];
    __shared__ float spart[4][64][17];

    const int t = threadIdx.x;
    const int rowg = t & 7;
    const int eg = (t >> 3) & 3;
    const int kg = t >> 5;
    const int brow = blockIdx.x * 64;

    float acc[8][4];
    #pragma unroll
    for (int i = 0; i < 8; i++)
        #pragma unroll
        for (int j = 0; j < 4; j++) acc[i][j] = 0.f;

    for (int kt = 0; kt < DD / 32; kt++) {
        float4 rx[4];
        float4 rw;
        #pragma unroll
        for (int i = 0; i < 4; i++) {
            int s = t + i * 128;
            int row = s >> 3, kq = s & 7;
            rx[i] = *(const float4*)&x[(size_t)(brow + row) * DD + kt * 32 + kq * 4];
        }
        {
            int e2 = t >> 3, kq = t & 7;
            rw = *(const float4*)&w[(size_t)e2 * DD + kt * 32 + kq * 4];
        }
        __syncthreads();
        #pragma unroll
        for (int i = 0; i < 4; i++) {
            int s = t + i * 128;
            int row = s >> 3, kq = s & 7;
            xs[kq * 4 + 0][row] = rx[i].x;
            xs[kq * 4 + 1][row] = rx[i].y;
            xs[kq * 4 + 2][row] = rx[i].z;
            xs[kq * 4 + 3][row] = rx[i].w;
        }
        {
            int e2 = t >> 3, kq = t & 7;
            ws[kq * 4 + 0][e2] = rw.x;
            ws[kq * 4 + 1][e2] = rw.y;
            ws[kq * 4 + 2][e2] = rw.z;
            ws[kq * 4 + 3][e2] = rw.w;
        }
        __syncthreads();
        #pragma unroll
        for (int kk2 = 0; kk2 < 8; kk2++) {
            int kk = kg * 8 + kk2;
            float4 a0 = *(const float4*)&xs[kk][rowg * 4];
            float4 a1 = *(const float4*)&xs[kk][32 + rowg * 4];
            float4 bq = *(const float4*)&ws[kk][eg * 4];
            float av[8] = {a0.x, a0.y, a0.z, a0.w, a1.x, a1.y, a1.z, a1.w};
            float bv[4] = {bq.x, bq.y, bq.z, bq.w};
            #pragma unroll
            for (int i = 0; i < 8; i++)
                #pragma unroll
                for (int j = 0; j < 4; j++) acc[i][j] += av[i] * bv[j];
        }
        __syncthreads();
    }

    #pragma unroll
    for (int i = 0; i < 8; i++) {
        int r = (i < 4) ? (rowg * 4 + i) : (32 + rowg * 4 + (i - 4));
        #pragma unroll
        for (int j = 0; j < 4; j++) spart[kg][r][eg * 4 + j] = acc[i][j];
    }
    __syncthreads();

    if (t < 64) {
        int r = t;
        int b = brow + r;
        float z[16];
        float mu = 0.f;
        #pragma unroll
        for (int e2 = 0; e2 < 16; e2++) {
            float v = spart[0][r][e2] + spart[1][r][e2] + spart[2][r][e2] + spart[3][r][e2]
                      + bias[e2];
            z[e2] = v;
            mu += v;
        }
        mu *= (1.f / 16.f);
        float var = 0.f;
        #pragma unroll
        for (int e2 = 0; e2 < 16; e2++) { float d = z[e2] - mu; var += d * d; }
        var *= (1.f / 16.f);
        float rs = rsqrtf(var + LN_EPS);

        float best = z[0];
        int cls = 0;
        #pragma unroll
        for (int e2 = 1; e2 < 16; e2++)
            if (z[e2] > best) { best = z[e2]; cls = e2; }  // first-max

        #pragma unroll
        for (int q = 0; q < 4; q++) {
            float4 o = make_float4((z[q * 4 + 0] - mu) * rs, (z[q * 4 + 1] - mu) * rs,
                                   (z[q * 4 + 2] - mu) * rs, (z[q * 4 + 3] - mu) * rs);
            *(float4*)&out_pl[(size_t)b * 16 + q * 4] = o;
        }
        g_class[b] = cls;
        atomicAdd(&g_cnt[cls], 1);
    }
}

__global__ void k_scan() {
    if (threadIdx.x == 0) {
        int o = 0;
        for (int e = 0; e < EE; e++) { g_off[e] = o; o += g_cnt[e]; }
        g_off[EE] = o;
    }
}

__global__ void k_scatter() {
    int b = blockIdx.x * 256 + threadIdx.x;
    if (b < BB) {
        int e = g_class[b];
        int pos = g_off[e] + atomicAdd(&g_cur[e], 1);
        g_sidx[pos] = b;
    }
}

// ---------------------------------------------------------------------------
// Parent proj
// ---------------------------------------------------------------------------
__global__ __launch_bounds__(256) void k_parent_proj(
    const float* __restrict__ pl, const float* __restrict__ w,
    const float* __restrict__ bias, float* __restrict__ out)
{
    __shared__ __align__(16) float spl[64][20];
    const int t = threadIdx.x;
    const int brow = blockIdx.x * 64;

    {
        int row = t >> 2, q = t & 3;
        float4 g = *(const float4*)&pl[(size_t)(brow + row) * 16 + q * 4];
        spl[row][q * 4 + 0] = g.x;
        spl[row][q * 4 + 1] = g.y;
        spl[row][q * 4 + 2] = g.z;
        spl[row][q * 4 + 3] = g.w;
    }
    __syncthreads();

    for (int pass = 0; pass < 2; pass++) {
        int p0 = pass * 512 + t * 2;
        float w0[16], w1[16];
        #pragma unroll
        for (int q = 0; q < 4; q++) {
            float4 a = *(const float4*)&w[(size_t)p0 * 16 + q * 4];
            w0[q * 4 + 0] = a.x; w0[q * 4 + 1] = a.y; w0[q * 4 + 2] = a.z; w0[q * 4 + 3] = a.w;
            float4 c = *(const float4*)&w[(size_t)(p0 + 1) * 16 + q * 4];
            w1[q * 4 + 0] = c.x; w1[q * 4 + 1] = c.y; w1[q * 4 + 2] = c.z; w1[q * 4 + 3] = c.w;
        }
        float b0 = bias[p0], b1 = bias[p0 + 1];

        for (int r = 0; r < 64; r++) {
            float a0 = b0, a1 = b1;
            #pragma unroll
            for (int q = 0; q < 4; q++) {
                float4 v = *(const float4*)&spl[r][q * 4];
                a0 += v.x * w0[q * 4 + 0] + v.y * w0[q * 4 + 1] + v.z * w0[q * 4 + 2] + v.w * w0[q * 4 + 3];
                a1 += v.x * w1[q * 4 + 0] + v.y * w1[q * 4 + 1] + v.z * w1[q * 4 + 2] + v.w * w1[q * 4 + 3];
            }
            float2 o = make_float2(a0, a1);
            *(float2*)&out[(size_t)(brow + r) * PP + p0] = o;
        }
    }
}

// ---------------------------------------------------------------------------
// Child FC + LN, both levels in ONE launch (grid.z = level), BM=32.
// A-tile duplicated in smem as (v,v) pairs -> zero splat MOVs in inner loop;
// accumulators paired over COLUMNS (B col-pairs free from 64-bit LDS of ws).
// ---------------------------------------------------------------------------
template <int BN>
__device__ __forceinline__ void child_fc_impl(
    const float* __restrict__ x, const float* __restrict__ w,
    const float* __restrict__ bias, float* __restrict__ out,
    float (*xs2)[16][68], float (*ws)[16][132],
    int* sidx, float (*sred)[32][17])
{
    constexpr int NC = BN / 64;       // 64-col chunks
    constexpr int NWL = BN / 32;      // float4 w-loads per thread
    const int e = blockIdx.y;
    const int start = g_off[e] + blockIdx.x * 32;
    const int end = g_off[e + 1];
    if (start >= end) return;

    const int t = threadIdx.x;
    const int ty = t >> 4, tx = t & 15;

    if (t < 32) {
        int gi = start + t;
        sidx[t] = g_sidx[gi < end ? gi : start];
    }
    __syncthreads();

    float4 rx;
    float4 rw[NWL];

    auto ldg_tile = [&](int kt) {
        {
            int row = t >> 2, kq = t & 3;
            rx = *(const float4*)&x[(size_t)sidx[row] * DD + kt * 16 + kq * 4];
        }
        #pragma unroll
        for (int i = 0; i < NWL; i++) {
            int s = t + i * 128;
            int n = s >> 2, kq = s & 3;
            rw[i] = *(const float4*)&w[((size_t)e * BN + n) * DD + kt * 16 + kq * 4];
        }
    };
    auto sts_tile = [&](int buf) {
        {
            int row = t >> 2, kq = t & 3;
            *(u64t*)&xs2[buf][kq * 4 + 0][row * 2] = pk2(rx.x, rx.x);
            *(u64t*)&xs2[buf][kq * 4 + 1][row * 2] = pk2(rx.y, rx.y);
            *(u64t*)&xs2[buf][kq * 4 + 2][row * 2] = pk2(rx.z, rx.z);
            *(u64t*)&xs2[buf][kq * 4 + 3][row * 2] = pk2(rx.w, rx.w);
        }
        #pragma unroll
        for (int i = 0; i < NWL; i++) {
            int s = t + i * 128;
            int n = s >> 2, kq = s & 3;
            ws[buf][kq * 4 + 0][n] = rw[i].x;
            ws[buf][kq * 4 + 1][n] = rw[i].y;
            ws[buf][kq * 4 + 2][n] = rw[i].z;
            ws[buf][kq * 4 + 3][n] = rw[i].w;
        }
    };

    // acc2[r][c][jp]: rows ty*4+r, col pair (tx*4+2jp, tx*4+2jp+1) of chunk c
    u64t acc2[4][NC][2];
    #pragma unroll
    for (int r = 0; r < 4; r++)
        #pragma unroll
        for (int c = 0; c < NC; c++)
            #pragma unroll
            for (int jp = 0; jp < 2; jp++) acc2[r][c][jp] = 0ull;

    ldg_tile(0);
    sts_tile(0);
    __syncthreads();

    const int NKT = DD / 16;
    for (int kt = 0; kt < NKT; kt++) {
        int cur = kt & 1;
        if (kt + 1 < NKT) ldg_tile(kt + 1);
        #pragma unroll
        for (int kk = 0; kk < 16; kk++) {
            // duplicated A: (r0,r0,r1,r1) and (r2,r2,r3,r3)
            ulonglong2 a01 = *(const ulonglong2*)&xs2[cur][kk][ty * 8];
            ulonglong2 a23 = *(const ulonglong2*)&xs2[cur][kk][ty * 8 + 4];
            u64t ap[4] = {a01.x, a01.y, a23.x, a23.y};
            #pragma unroll
            for (int c = 0; c < NC; c++) {
                ulonglong2 bp = *(const ulonglong2*)&ws[cur][kk][c * 64 + tx * 4];
                #pragma unroll
                for (int r = 0; r < 4; r++) {
                    ffma2(acc2[r][c][0], ap[r], bp.x);
                    ffma2(acc2[r][c][1], ap[r], bp.y);
                }
            }
        }
        if (kt + 1 < NKT) sts_tile((kt + 1) & 1);
        __syncthreads();
    }

    float bf[NC][4];
    #pragma unroll
    for (int c = 0; c < NC; c++)
        #pragma unroll
        for (int j = 0; j < 4; j++) bf[c][j] = bias[(size_t)e * BN + c * 64 + tx * 4 + j];

    float accf[4][NC][4];
    #pragma unroll
    for (int r = 0; r < 4; r++) {
        float ps = 0.f, pq = 0.f;
        #pragma unroll
        for (int c = 0; c < NC; c++) {
            float v0, v1, v2, v3;
            upk2(acc2[r][c][0], v0, v1);
            upk2(acc2[r][c][1], v2, v3);
            v0 += bf[c][0]; v1 += bf[c][1]; v2 += bf[c][2]; v3 += bf[c][3];
            accf[r][c][0] = v0; accf[r][c][1] = v1; accf[r][c][2] = v2; accf[r][c][3] = v3;
            ps += v0 + v1 + v2 + v3;
            pq += v0 * v0 + v1 * v1 + v2 * v2 + v3 * v3;
        }
        sred[0][ty * 4 + r][tx] = ps;
        sred[1][ty * 4 + r][tx] = pq;
    }
    __syncthreads();

    if (t < 32) {
        float s = 0.f, q = 0.f;
        #pragma unroll
        for (int c = 0; c < 16; c++) { s += sred[0][t][c]; q += sred[1][t][c]; }
        float mu = s / (float)BN;
        float var = q / (float)BN - mu * mu;
        sred[0][t][16] = mu;
        sred[1][t][16] = rsqrtf(var + LN_EPS);
    }
    __syncthreads();

    #pragma unroll
    for (int r = 0; r < 4; r++) {
        int rr = ty * 4 + r;
        if (start + rr < end) {
            int b = sidx[rr];
            float mu = sred[0][rr][16], rs = sred[1][rr][16];
            #pragma unroll
            for (int c = 0; c < NC; c++) {
                float4 o = make_float4((accf[r][c][0] - mu) * rs, (accf[r][c][1] - mu) * rs,
                                       (accf[r][c][2] - mu) * rs, (accf[r][c][3] - mu) * rs);
                *(float4*)&out[(size_t)b * BN + c * 64 + tx * 4] = o;
            }
        }
    }
}

__global__ __launch_bounds__(128) void k_child_fc_all(
    const float* __restrict__ x,
    const float* __restrict__ w0, const float* __restrict__ b0, float* __restrict__ o0,
    const float* __restrict__ w1, const float* __restrict__ b1, float* __restrict__ o1)
{
    __shared__ __align__(16) float xs2[2][16][68];
    __shared__ __align__(16) float ws[2][16][132];
    __shared__ int sidx[32];
    __shared__ float sred[2][32][17];

    if (blockIdx.z == 0)
        child_fc_impl<CC0>(x, w0, b0, o0, xs2, ws, sidx, sred);
    else
        child_fc_impl<CC1>(x, w1, b1, o1, xs2, ws, sidx, sred);
}

// ---------------------------------------------------------------------------
// Child proj, both levels in ONE launch. BM=64, BN=128 p-tile, BK=16.
// Duplicated-h smem (zero splats), column-paired FFMA2 accumulators.
// ---------------------------------------------------------------------------
__global__ __launch_bounds__(128) void k_child_proj(
    const float* __restrict__ h0, const float* __restrict__ w0,
    const float* __restrict__ b0, float* __restrict__ o0,
    const float* __restrict__ h1, const float* __restrict__ w1,
    const float* __restrict__ b1, float* __restrict__ o1)
{
    const int e = blockIdx.y;
    const int start = g_off[e] + blockIdx.x * 64;
    const int end = g_off[e + 1];
    if (start >= end) return;

    const int level = blockIdx.z >> 3;
    const int pbase = (blockIdx.z & 7) * 128;
    const int CK = level ? CC1 : CC0;
    const float* __restrict__ h = level ? h1 : h0;
    const float* __restrict__ w = level ? w1 : w0;
    const float* __restrict__ bias = level ? b1 : b0;
    float* __restrict__ out = level ? o1 : o0;

    __shared__ __align__(16) float hs2[2][16][132];
    __shared__ __align__(16) float wsp[2][16][132];
    __shared__ int sidx[64];

    const int t = threadIdx.x;
    const int ty = t >> 4, tx = t & 15;

    if (t < 64) {
        int gi = start + t;
        sidx[t] = g_sidx[gi < end ? gi : start];
    }
    __syncthreads();

    float4 rh[2];
    float4 rw[4];

    auto ldg_tile = [&](int kt) {
        #pragma unroll
        for (int i = 0; i < 2; i++) {
            int s = t + i * 128;
            int row = s >> 2, kq = s & 3;
            rh[i] = *(const float4*)&h[(size_t)sidx[row] * CK + kt * 16 + kq * 4];
        }
        #pragma unroll
        for (int i = 0; i < 4; i++) {
            int s = t + i * 128;
            int n = s >> 2, kq = s & 3;
            rw[i] = *(const float4*)&w[(size_t)(e * PP + pbase + n) * CK + kt * 16 + kq * 4];
        }
    };
    auto sts_tile = [&](int buf) {
        #pragma unroll
        for (int i = 0; i < 2; i++) {
            int s = t + i * 128;
            int row = s >> 2, kq = s & 3;
            *(u64t*)&hs2[buf][kq * 4 + 0][row * 2] = pk2(rh[i].x, rh[i].x);
            *(u64t*)&hs2[buf][kq * 4 + 1][row * 2] = pk2(rh[i].y, rh[i].y);
            *(u64t*)&hs2[buf][kq * 4 + 2][row * 2] = pk2(rh[i].z, rh[i].z);
            *(u64t*)&hs2[buf][kq * 4 + 3][row * 2] = pk2(rh[i].w, rh[i].w);
        }
        #pragma unroll
        for (int i = 0; i < 4; i++) {
            int s = t + i * 128;
            int n = s >> 2, kq = s & 3;
            wsp[buf][kq * 4 + 0][n] = rw[i].x;
            wsp[buf][kq * 4 + 1][n] = rw[i].y;
            wsp[buf][kq * 4 + 2][n] = rw[i].z;
            wsp[buf][kq * 4 + 3][n] = rw[i].w;
        }
    };

    // acc2[r][c][jp]: rows ty*8+r, col pair (tx*4+2jp,+1) of chunk c
    u64t acc2[8][2][2];
    #pragma unroll
    for (int r = 0; r < 8; r++)
        #pragma unroll
        for (int c = 0; c < 2; c++)
            #pragma unroll
            for (int jp = 0; jp < 2; jp++) acc2[r][c][jp] = 0ull;

    ldg_tile(0);
    sts_tile(0);
    __syncthreads();

    const int NKT = CK / 16;
    for (int kt = 0; kt < NKT; kt++) {
        int cur = kt & 1;
        if (kt + 1 < NKT) ldg_tile(kt + 1);
        #pragma unroll
        for (int kk = 0; kk < 16; kk++) {
            ulonglong2 a01 = *(const ulonglong2*)&hs2[cur][kk][ty * 16];
            ulonglong2 a23 = *(const ulonglong2*)&hs2[cur][kk][ty * 16 + 4];
            ulonglong2 a45 = *(const ulonglong2*)&hs2[cur][kk][ty * 16 + 8];
            ulonglong2 a67 = *(const ulonglong2*)&hs2[cur][kk][ty * 16 + 12];
            u64t ap[8] = {a01.x, a01.y, a23.x, a23.y, a45.x, a45.y, a67.x, a67.y};
            #pragma unroll
            for (int c = 0; c < 2; c++) {
                ulonglong2 bp = *(const ulonglong2*)&wsp[cur][kk][c * 64 + tx * 4];
                #pragma unroll
                for (int r = 0; r < 8; r++) {
                    ffma2(acc2[r][c][0], ap[r], bp.x);
                    ffma2(acc2[r][c][1], ap[r], bp.y);
                }
            }
        }
        if (kt + 1 < NKT) sts_tile((kt + 1) & 1);
        __syncthreads();
    }

    #pragma unroll
    for (int r = 0; r < 8; r++) {
        int rr = ty * 8 + r;
        if (start + rr < end) {
            int b = sidx[rr];
            #pragma unroll
            for (int c = 0; c < 2; c++) {
                int p = pbase + c * 64 + tx * 4;
                float4 bb4 = *(const float4*)&bias[(size_t)e * PP + p];
                float v0, v1, v2, v3;
                upk2(acc2[r][c][0], v0, v1);
                upk2(acc2[r][c][1], v2, v3);
                float4 o = make_float4(v0 + bb4.x, v1 + bb4.y, v2 + bb4.z, v3 + bb4.w);
                *(float4*)&out[(size_t)b * PP + p] = o;
            }
        }
    }
}

// ---------------------------------------------------------------------------

extern "C" void kernel_launch(void* const* d_in, const int* in_sizes, int n_in,
                              void* d_out, int out_size) {
    const float* x       = (const float*)d_in[0];
    const float* pw_fc   = (const float*)d_in[1];
    const float* pb_fc   = (const float*)d_in[2];
    const float* pw_proj = (const float*)d_in[3];
    const float* pb_proj = (const float*)d_in[4];
    const float* cw_fc0  = (const float*)d_in[5];
    const float* cb_fc0  = (const float*)d_in[6];
    const float* cw_pr0  = (const float*)d_in[7];
    const float* cb_pr0  = (const float*)d_in[8];
    const float* cw_fc1  = (const float*)d_in[9];
    const float* cb_fc1  = (const float*)d_in[10];
    const float* cw_pr1  = (const float*)d_in[11];
    const float* cb_pr1  = (const float*)d_in[12];
    float* out = (float*)d_out;

    k_init<<<1, 32>>>();
    k_parent_fc<<<BB / 64, 128>>>(x, pw_fc, pb_fc, out + OFF_PL);
    k_scan<<<1, 32>>>();
    k_scatter<<<BB / 256, 256>>>();
    k_parent_proj<<<BB / 64, 256>>>(out + OFF_PL, pw_proj, pb_proj, out + OFF_PP);

    // combined child fc (both levels concurrent, BM=32 -> 512 working blocks)
    dim3 gfc(BB / 32, EE, 2);
    k_child_fc_all<<<gfc, 128>>>(x, cw_fc0, cb_fc0, out + OFF_CL0,
                                 cw_fc1, cb_fc1, out + OFF_CL1);

    // combined child proj (both levels, 2048 working blocks)
    dim3 gpr(BB / 64, EE, 16);
    k_child_proj<<<gpr, 128>>>(out + OFF_CL0, cw_pr0, cb_pr0, out + OFF_CP0,
                               out + OFF_CL1, cw_pr1, cb_pr1, out + OFF_CP1);
}

// round 5
// speedup vs baseline: 1.2441x; 1.0072x over previous
#include <cuda_runtime.h>

#define BB 8192
#define DD 2048
#define EE 16
#define PP 1024
#define CC0 64
#define CC1 128
#define LN_EPS 1e-5f

// output layout: flattened tuple concat (parent_logits, cl0, cl1, parent_proj, cp0, cp1)
#define OFF_PL  0
#define OFF_CL0 (BB*EE)
#define OFF_CL1 (OFF_CL0 + BB*CC0)
#define OFF_PP  (OFF_CL1 + BB*CC1)
#define OFF_CP0 (OFF_PP + BB*PP)
#define OFF_CP1 (OFF_CP0 + BB*PP)

typedef unsigned long long u64t;

// packed f32x2 helpers (FFMA2 — 2x fp32 throughput, exact fp32 per lane)
__device__ __forceinline__ u64t pk2(float lo, float hi) {
    u64t r;
    asm("mov.b64 %0, {%1, %2};" : "=l"(r) : "f"(lo), "f"(hi));
    return r;
}
__device__ __forceinline__ void upk2(u64t v, float& lo, float& hi) {
    asm("mov.b64 {%0, %1}, %2;" : "=f"(lo), "=f"(hi) : "l"(v));
}
__device__ __forceinline__ void ffma2(u64t& d, u64t a, u64t b) {
    asm("fma.rn.f32x2 %0, %1, %2, %0;" : "+l"(d) : "l"(a), "l"(b));
}

// scratch (no allocation allowed -> device globals)
__device__ int g_class[BB];
__device__ int g_cnt[EE];
__device__ int g_cur[EE];
__device__ int g_off[EE + 1];
__device__ int g_sidx[BB];

__global__ void k_init() {
    int t = threadIdx.x;
    if (t < EE) { g_cnt[t] = 0; g_cur[t] = 0; }
}

// ---------------------------------------------------------------------------
// Parent FC (exact fp32 — gates argmax)
// ---------------------------------------------------------------------------
__global__ __launch_bounds__(128) void k_parent_fc(
    const float* __restrict__ x, const float* __restrict__ w,
    const float* __restrict__ bias, float* __restrict__ out_pl)
{
    __shared__ __align__(16) float xs[32][68];
    __shared__ __align__(16) float ws[32][20];
    __shared__ float spart[4][64][17];

    const int t = threadIdx.x;
    const int rowg = t & 7;
    const int eg = (t >> 3) & 3;
    const int kg = t >> 5;
    const int brow = blockIdx.x * 64;

    float acc[8][4];
    #pragma unroll
    for (int i = 0; i < 8; i++)
        #pragma unroll
        for (int j = 0; j < 4; j++) acc[i][j] = 0.f;

    for (int kt = 0; kt < DD / 32; kt++) {
        float4 rx[4];
        float4 rw;
        #pragma unroll
        for (int i = 0; i < 4; i++) {
            int s = t + i * 128;
            int row = s >> 3, kq = s & 7;
            rx[i] = *(const float4*)&x[(size_t)(brow + row) * DD + kt * 32 + kq * 4];
        }
        {
            int e2 = t >> 3, kq = t & 7;
            rw = *(const float4*)&w[(size_t)e2 * DD + kt * 32 + kq * 4];
        }
        __syncthreads();
        #pragma unroll
        for (int i = 0; i < 4; i++) {
            int s = t + i * 128;
            int row = s >> 3, kq = s & 7;
            xs[kq * 4 + 0][row] = rx[i].x;
            xs[kq * 4 + 1][row] = rx[i].y;
            xs[kq * 4 + 2][row] = rx[i].z;
            xs[kq * 4 + 3][row] = rx[i].w;
        }
        {
            int e2 = t >> 3, kq = t & 7;
            ws[kq * 4 + 0][e2] = rw.x;
            ws[kq * 4 + 1][e2] = rw.y;
            ws[kq * 4 + 2][e2] = rw.z;
            ws[kq * 4 + 3][e2] = rw.w;
        }
        __syncthreads();
        #pragma unroll
        for (int kk2 = 0; kk2 < 8; kk2++) {
            int kk = kg * 8 + kk2;
            float4 a0 = *(const float4*)&xs[kk][rowg * 4];
            float4 a1 = *(const float4*)&xs[kk][32 + rowg * 4];
            float4 bq = *(const float4*)&ws[kk][eg * 4];
            float av[8] = {a0.x, a0.y, a0.z, a0.w, a1.x, a1.y, a1.z, a1.w};
            float bv[4] = {bq.x, bq.y, bq.z, bq.w};
            #pragma unroll
            for (int i = 0; i < 8; i++)
                #pragma unroll
                for (int j = 0; j < 4; j++) acc[i][j] += av[i] * bv[j];
        }
        __syncthreads();
    }

    #pragma unroll
    for (int i = 0; i < 8; i++) {
        int r = (i < 4) ? (rowg * 4 + i) : (32 + rowg * 4 + (i - 4));
        #pragma unroll
        for (int j = 0; j < 4; j++) spart[kg][r][eg * 4 + j] = acc[i][j];
    }
    __syncthreads();

    if (t < 64) {
        int r = t;
        int b = brow + r;
        float z[16];
        float mu = 0.f;
        #pragma unroll
        for (int e2 = 0; e2 < 16; e2++) {
            float v = spart[0][r][e2] + spart[1][r][e2] + spart[2][r][e2] + spart[3][r][e2]
                      + bias[e2];
            z[e2] = v;
            mu += v;
        }
        mu *= (1.f / 16.f);
        float var = 0.f;
        #pragma unroll
        for (int e2 = 0; e2 < 16; e2++) { float d = z[e2] - mu; var += d * d; }
        var *= (1.f / 16.f);
        float rs = rsqrtf(var + LN_EPS);

        float best = z[0];
        int cls = 0;
        #pragma unroll
        for (int e2 = 1; e2 < 16; e2++)
            if (z[e2] > best) { best = z[e2]; cls = e2; }  // first-max

        #pragma unroll
        for (int q = 0; q < 4; q++) {
            float4 o = make_float4((z[q * 4 + 0] - mu) * rs, (z[q * 4 + 1] - mu) * rs,
                                   (z[q * 4 + 2] - mu) * rs, (z[q * 4 + 3] - mu) * rs);
            *(float4*)&out_pl[(size_t)b * 16 + q * 4] = o;
        }
        g_class[b] = cls;
        atomicAdd(&g_cnt[cls], 1);
    }
}

__global__ void k_scan() {
    if (threadIdx.x == 0) {
        int o = 0;
        for (int e = 0; e < EE; e++) { g_off[e] = o; o += g_cnt[e]; }
        g_off[EE] = o;
    }
}

__global__ void k_scatter() {
    int b = blockIdx.x * 256 + threadIdx.x;
    if (b < BB) {
        int e = g_class[b];
        int pos = g_off[e] + atomicAdd(&g_cur[e], 1);
        g_sidx[pos] = b;
    }
}

// ---------------------------------------------------------------------------
// Parent proj
// ---------------------------------------------------------------------------
__global__ __launch_bounds__(256) void k_parent_proj(
    const float* __restrict__ pl, const float* __restrict__ w,
    const float* __restrict__ bias, float* __restrict__ out)
{
    __shared__ __align__(16) float spl[64][20];
    const int t = threadIdx.x;
    const int brow = blockIdx.x * 64;

    {
        int row = t >> 2, q = t & 3;
        float4 g = *(const float4*)&pl[(size_t)(brow + row) * 16 + q * 4];
        spl[row][q * 4 + 0] = g.x;
        spl[row][q * 4 + 1] = g.y;
        spl[row][q * 4 + 2] = g.z;
        spl[row][q * 4 + 3] = g.w;
    }
    __syncthreads();

    for (int pass = 0; pass < 2; pass++) {
        int p0 = pass * 512 + t * 2;
        float w0[16], w1[16];
        #pragma unroll
        for (int q = 0; q < 4; q++) {
            float4 a = *(const float4*)&w[(size_t)p0 * 16 + q * 4];
            w0[q * 4 + 0] = a.x; w0[q * 4 + 1] = a.y; w0[q * 4 + 2] = a.z; w0[q * 4 + 3] = a.w;
            float4 c = *(const float4*)&w[(size_t)(p0 + 1) * 16 + q * 4];
            w1[q * 4 + 0] = c.x; w1[q * 4 + 1] = c.y; w1[q * 4 + 2] = c.z; w1[q * 4 + 3] = c.w;
        }
        float b0 = bias[p0], b1 = bias[p0 + 1];

        for (int r = 0; r < 64; r++) {
            float a0 = b0, a1 = b1;
            #pragma unroll
            for (int q = 0; q < 4; q++) {
                float4 v = *(const float4*)&spl[r][q * 4];
                a0 += v.x * w0[q * 4 + 0] + v.y * w0[q * 4 + 1] + v.z * w0[q * 4 + 2] + v.w * w0[q * 4 + 3];
                a1 += v.x * w1[q * 4 + 0] + v.y * w1[q * 4 + 1] + v.z * w1[q * 4 + 2] + v.w * w1[q * 4 + 3];
            }
            float2 o = make_float2(a0, a1);
            *(float2*)&out[(size_t)(brow + r) * PP + p0] = o;
        }
    }
}

// ---------------------------------------------------------------------------
// Child FC + LN, both levels in ONE launch, BM=32, BK=32 (full 128B rows ->
// halved L1tex wavefronts). Duplicated-A smem, column-paired FFMA2.
// Dynamic smem layout (floats):
//   xs2 [2][32][68]   @ 0        (4352)
//   ws  [2][32][132]  @ 4352     (8448)
//   sidx[32] (int)    @ 12800    (32)
//   sred[2][32][17]   @ 12832    (1088)
// total 13920 floats = 55680 B
// ---------------------------------------------------------------------------
#define FC_SMEM_BYTES 55680

template <int BN>
__device__ __forceinline__ void child_fc_impl(
    const float* __restrict__ x, const float* __restrict__ w,
    const float* __restrict__ bias, float* __restrict__ out, float* sm)
{
    constexpr int NC = BN / 64;        // 64-col chunks
    constexpr int NWL = BN / 16;       // float4 w-loads per thread (BK=32)
    float (*xs2)[32][68]  = (float(*)[32][68])sm;
    float (*ws)[32][132]  = (float(*)[32][132])(sm + 4352);
    int*   sidx           = (int*)(sm + 12800);
    float (*sred)[32][17] = (float(*)[32][17])(sm + 12832);

    const int e = blockIdx.y;
    const int start = g_off[e] + blockIdx.x * 32;
    const int end = g_off[e + 1];
    if (start >= end) return;

    const int t = threadIdx.x;
    const int ty = t >> 4, tx = t & 15;

    if (t < 32) {
        int gi = start + t;
        sidx[t] = g_sidx[gi < end ? gi : start];
    }
    __syncthreads();

    float4 rx[2];
    float4 rw[NWL];

    auto ldg_tile = [&](int kt) {
        #pragma unroll
        for (int i = 0; i < 2; i++) {
            int s = t + i * 128;
            int row = s >> 3, kq = s & 7;   // 8 threads per 128B row
            rx[i] = *(const float4*)&x[(size_t)sidx[row] * DD + kt * 32 + kq * 4];
        }
        #pragma unroll
        for (int i = 0; i < NWL; i++) {
            int s = t + i * 128;
            int n = s >> 3, kq = s & 7;
            rw[i] = *(const float4*)&w[((size_t)e * BN + n) * DD + kt * 32 + kq * 4];
        }
    };
    auto sts_tile = [&](int buf) {
        #pragma unroll
        for (int i = 0; i < 2; i++) {
            int s = t + i * 128;
            int row = s >> 3, kq = s & 7;
            *(u64t*)&xs2[buf][kq * 4 + 0][row * 2] = pk2(rx[i].x, rx[i].x);
            *(u64t*)&xs2[buf][kq * 4 + 1][row * 2] = pk2(rx[i].y, rx[i].y);
            *(u64t*)&xs2[buf][kq * 4 + 2][row * 2] = pk2(rx[i].z, rx[i].z);
            *(u64t*)&xs2[buf][kq * 4 + 3][row * 2] = pk2(rx[i].w, rx[i].w);
        }
        #pragma unroll
        for (int i = 0; i < NWL; i++) {
            int s = t + i * 128;
            int n = s >> 3, kq = s & 7;
            ws[buf][kq * 4 + 0][n] = rw[i].x;
            ws[buf][kq * 4 + 1][n] = rw[i].y;
            ws[buf][kq * 4 + 2][n] = rw[i].z;
            ws[buf][kq * 4 + 3][n] = rw[i].w;
        }
    };

    // acc2[r][c][jp]: row ty*4+r, col pair (tx*4+2jp,+1) of chunk c
    u64t acc2[4][NC][2];
    #pragma unroll
    for (int r = 0; r < 4; r++)
        #pragma unroll
        for (int c = 0; c < NC; c++)
            #pragma unroll
            for (int jp = 0; jp < 2; jp++) acc2[r][c][jp] = 0ull;

    ldg_tile(0);
    sts_tile(0);
    __syncthreads();

    const int NKT = DD / 32;
    for (int kt = 0; kt < NKT; kt++) {
        int cur = kt & 1;
        if (kt + 1 < NKT) ldg_tile(kt + 1);
        #pragma unroll
        for (int kk = 0; kk < 32; kk++) {
            ulonglong2 a01 = *(const ulonglong2*)&xs2[cur][kk][ty * 8];
            ulonglong2 a23 = *(const ulonglong2*)&xs2[cur][kk][ty * 8 + 4];
            u64t ap[4] = {a01.x, a01.y, a23.x, a23.y};
            #pragma unroll
            for (int c = 0; c < NC; c++) {
                ulonglong2 bp = *(const ulonglong2*)&ws[cur][kk][c * 64 + tx * 4];
                #pragma unroll
                for (int r = 0; r < 4; r++) {
                    ffma2(acc2[r][c][0], ap[r], bp.x);
                    ffma2(acc2[r][c][1], ap[r], bp.y);
                }
            }
        }
        if (kt + 1 < NKT) sts_tile((kt + 1) & 1);
        __syncthreads();
    }

    float bf[NC][4];
    #pragma unroll
    for (int c = 0; c < NC; c++)
        #pragma unroll
        for (int j = 0; j < 4; j++) bf[c][j] = bias[(size_t)e * BN + c * 64 + tx * 4 + j];

    float accf[4][NC][4];
    #pragma unroll
    for (int r = 0; r < 4; r++) {
        float ps = 0.f, pq = 0.f;
        #pragma unroll
        for (int c = 0; c < NC; c++) {
            float v0, v1, v2, v3;
            upk2(acc2[r][c][0], v0, v1);
            upk2(acc2[r][c][1], v2, v3);
            v0 += bf[c][0]; v1 += bf[c][1]; v2 += bf[c][2]; v3 += bf[c][3];
            accf[r][c][0] = v0; accf[r][c][1] = v1; accf[r][c][2] = v2; accf[r][c][3] = v3;
            ps += v0 + v1 + v2 + v3;
            pq += v0 * v0 + v1 * v1 + v2 * v2 + v3 * v3;
        }
        sred[0][ty * 4 + r][tx] = ps;
        sred[1][ty * 4 + r][tx] = pq;
    }
    __syncthreads();

    if (t < 32) {
        float s = 0.f, q = 0.f;
        #pragma unroll
        for (int c = 0; c < 16; c++) { s += sred[0][t][c]; q += sred[1][t][c]; }
        float mu = s / (float)BN;
        float var = q / (float)BN - mu * mu;
        sred[0][t][16] = mu;
        sred[1][t][16] = rsqrtf(var + LN_EPS);
    }
    __syncthreads();

    #pragma unroll
    for (int r = 0; r < 4; r++) {
        int rr = ty * 4 + r;
        if (start + rr < end) {
            int b = sidx[rr];
            float mu = sred[0][rr][16], rs = sred[1][rr][16];
            #pragma unroll
            for (int c = 0; c < NC; c++) {
                float4 o = make_float4((accf[r][c][0] - mu) * rs, (accf[r][c][1] - mu) * rs,
                                       (accf[r][c][2] - mu) * rs, (accf[r][c][3] - mu) * rs);
                *(float4*)&out[(size_t)b * BN + c * 64 + tx * 4] = o;
            }
        }
    }
}

__global__ __launch_bounds__(128) void k_child_fc_all(
    const float* __restrict__ x,
    const float* __restrict__ w0, const float* __restrict__ b0, float* __restrict__ o0,
    const float* __restrict__ w1, const float* __restrict__ b1, float* __restrict__ o1)
{
    extern __shared__ __align__(16) float sm_fc[];
    if (blockIdx.z == 0)
        child_fc_impl<CC0>(x, w0, b0, o0, sm_fc);
    else
        child_fc_impl<CC1>(x, w1, b1, o1, sm_fc);
}

// ---------------------------------------------------------------------------
// Child proj, both levels in ONE launch. BM=32, BN=128 p-tile, BK=32.
// Dynamic smem: hs2[2][32][68] @0 (4352), wsp[2][32][132] @4352 (8448),
// sidx[32] @12800 -> 12832 floats = 51328 B
// ---------------------------------------------------------------------------
#define PROJ_SMEM_BYTES 51328

__global__ __launch_bounds__(128) void k_child_proj(
    const float* __restrict__ h0, const float* __restrict__ w0,
    const float* __restrict__ b0, float* __restrict__ o0,
    const float* __restrict__ h1, const float* __restrict__ w1,
    const float* __restrict__ b1, float* __restrict__ o1)
{
    extern __shared__ __align__(16) float sm_pr[];
    float (*hs2)[32][68]  = (float(*)[32][68])sm_pr;
    float (*wsp)[32][132] = (float(*)[32][132])(sm_pr + 4352);
    int*   sidx           = (int*)(sm_pr + 12800);

    const int e = blockIdx.y;
    const int start = g_off[e] + blockIdx.x * 32;
    const int end = g_off[e + 1];
    if (start >= end) return;

    const int level = blockIdx.z >> 3;
    const int pbase = (blockIdx.z & 7) * 128;
    const int CK = level ? CC1 : CC0;
    const float* __restrict__ h = level ? h1 : h0;
    const float* __restrict__ w = level ? w1 : w0;
    const float* __restrict__ bias = level ? b1 : b0;
    float* __restrict__ out = level ? o1 : o0;

    const int t = threadIdx.x;
    const int ty = t >> 4, tx = t & 15;

    if (t < 32) {
        int gi = start + t;
        sidx[t] = g_sidx[gi < end ? gi : start];
    }
    __syncthreads();

    float4 rh[2];
    float4 rw[8];

    auto ldg_tile = [&](int kt) {
        #pragma unroll
        for (int i = 0; i < 2; i++) {
            int s = t + i * 128;
            int row = s >> 3, kq = s & 7;
            rh[i] = *(const float4*)&h[(size_t)sidx[row] * CK + kt * 32 + kq * 4];
        }
        #pragma unroll
        for (int i = 0; i < 8; i++) {
            int s = t + i * 128;
            int n = s >> 3, kq = s & 7;
            rw[i] = *(const float4*)&w[(size_t)(e * PP + pbase + n) * CK + kt * 32 + kq * 4];
        }
    };
    auto sts_tile = [&](int buf) {
        #pragma unroll
        for (int i = 0; i < 2; i++) {
            int s = t + i * 128;
            int row = s >> 3, kq = s & 7;
            *(u64t*)&hs2[buf][kq * 4 + 0][row * 2] = pk2(rh[i].x, rh[i].x);
            *(u64t*)&hs2[buf][kq * 4 + 1][row * 2] = pk2(rh[i].y, rh[i].y);
            *(u64t*)&hs2[buf][kq * 4 + 2][row * 2] = pk2(rh[i].z, rh[i].z);
            *(u64t*)&hs2[buf][kq * 4 + 3][row * 2] = pk2(rh[i].w, rh[i].w);
        }
        #pragma unroll
        for (int i = 0; i < 8; i++) {
            int s = t + i * 128;
            int n = s >> 3, kq = s & 7;
            wsp[buf][kq * 4 + 0][n] = rw[i].x;
            wsp[buf][kq * 4 + 1][n] = rw[i].y;
            wsp[buf][kq * 4 + 2][n] = rw[i].z;
            wsp[buf][kq * 4 + 3][n] = rw[i].w;
        }
    };

    u64t acc2[4][2][2];
    #pragma unroll
    for (int r = 0; r < 4; r++)
        #pragma unroll
        for (int c = 0; c < 2; c++)
            #pragma unroll
            for (int jp = 0; jp < 2; jp++) acc2[r][c][jp] = 0ull;

    ldg_tile(0);
    sts_tile(0);
    __syncthreads();

    const int NKT = CK / 32;
    for (int kt = 0; kt < NKT; kt++) {
        int cur = kt & 1;
        if (kt + 1 < NKT) ldg_tile(kt + 1);
        #pragma unroll
        for (int kk = 0; kk < 32; kk++) {
            ulonglong2 a01 = *(const ulonglong2*)&hs2[cur][kk][ty * 8];
            ulonglong2 a23 = *(const ulonglong2*)&hs2[cur][kk][ty * 8 + 4];
            u64t ap[4] = {a01.x, a01.y, a23.x, a23.y};
            #pragma unroll
            for (int c = 0; c < 2; c++) {
                ulonglong2 bp = *(const ulonglong2*)&wsp[cur][kk][c * 64 + tx * 4];
                #pragma unroll
                for (int r = 0; r < 4; r++) {
                    ffma2(acc2[r][c][0], ap[r], bp.x);
                    ffma2(acc2[r][c][1], ap[r], bp.y);
                }
            }
        }
        if (kt + 1 < NKT) sts_tile((kt + 1) & 1);
        __syncthreads();
    }

    #pragma unroll
    for (int r = 0; r < 4; r++) {
        int rr = ty * 4 + r;
        if (start + rr < end) {
            int b = sidx[rr];
            #pragma unroll
            for (int c = 0; c < 2; c++) {
                int p = pbase + c * 64 + tx * 4;
                float4 bb4 = *(const float4*)&bias[(size_t)e * PP + p];
                float v0, v1, v2, v3;
                upk2(acc2[r][c][0], v0, v1);
                upk2(acc2[r][c][1], v2, v3);
                float4 o = make_float4(v0 + bb4.x, v1 + bb4.y, v2 + bb4.z, v3 + bb4.w);
                *(float4*)&out[(size_t)b * PP + p] = o;
            }
        }
    }
}

// ---------------------------------------------------------------------------

extern "C" void kernel_launch(void* const* d_in, const int* in_sizes, int n_in,
                              void* d_out, int out_size) {
    const float* x       = (const float*)d_in[0];
    const float* pw_fc   = (const float*)d_in[1];
    const float* pb_fc   = (const float*)d_in[2];
    const float* pw_proj = (const float*)d_in[3];
    const float* pb_proj = (const float*)d_in[4];
    const float* cw_fc0  = (const float*)d_in[5];
    const float* cb_fc0  = (const float*)d_in[6];
    const float* cw_pr0  = (const float*)d_in[7];
    const float* cb_pr0  = (const float*)d_in[8];
    const float* cw_fc1  = (const float*)d_in[9];
    const float* cb_fc1  = (const float*)d_in[10];
    const float* cw_pr1  = (const float*)d_in[11];
    const float* cb_pr1  = (const float*)d_in[12];
    float* out = (float*)d_out;

    cudaFuncSetAttribute(k_child_fc_all,
                         cudaFuncAttributeMaxDynamicSharedMemorySize, FC_SMEM_BYTES);
    cudaFuncSetAttribute(k_child_proj,
                         cudaFuncAttributeMaxDynamicSharedMemorySize, PROJ_SMEM_BYTES);

    k_init<<<1, 32>>>();
    k_parent_fc<<<BB / 64, 128>>>(x, pw_fc, pb_fc, out + OFF_PL);
    k_scan<<<1, 32>>>();
    k_scatter<<<BB / 256, 256>>>();
    k_parent_proj<<<BB / 64, 256>>>(out + OFF_PL, pw_proj, pb_proj, out + OFF_PP);

    // combined child fc (both levels, BM=32 -> 512 working blocks)
    dim3 gfc(BB / 32, EE, 2);
    k_child_fc_all<<<gfc, 128, FC_SMEM_BYTES>>>(x, cw_fc0, cb_fc0, out + OFF_CL0,
                                                cw_fc1, cb_fc1, out + OFF_CL1);

    // combined child proj (both levels, BM=32 -> 4096 working blocks)
    dim3 gpr(BB / 32, EE, 16);
    k_child_proj<<<gpr, 128, PROJ_SMEM_BYTES>>>(out + OFF_CL0, cw_pr0, cb_pr0, out + OFF_CP0,
                                                out + OFF_CL1, cw_pr1, cb_pr1, out + OFF_CP1);
}

// round 7
// speedup vs baseline: 2.3847x; 1.9168x over previous
#include <cuda_runtime.h>
#include <cuda_bf16.h>
#include <cstdint>

#define BB 8192
#define DD 2048
#define EE 16
#define PP 1024
#define CC0 64
#define CC1 128
#define LN_EPS 1e-5f

#define OFF_PL  0
#define OFF_CL0 (BB*EE)
#define OFF_CL1 (OFF_CL0 + BB*CC0)
#define OFF_PP  (OFF_CL1 + BB*CC1)
#define OFF_CP0 (OFF_PP + BB*PP)
#define OFF_CP1 (OFF_CP0 + BB*PP)

typedef unsigned long long u64t;

// ------------------------- scratch globals -------------------------
__device__ int g_class[BB];
__device__ int g_cnt[EE];
__device__ int g_cur[EE];
__device__ int g_off[EE + 1];
__device__ int g_sidx[BB];

// bf16 hi/lo precomputed operands
__device__ __nv_bfloat16 g_xh[BB * DD], g_xl[BB * DD];
__device__ __nv_bfloat16 g_wfc0h[EE * CC0 * DD], g_wfc0l[EE * CC0 * DD];
__device__ __nv_bfloat16 g_wfc1h[EE * CC1 * DD], g_wfc1l[EE * CC1 * DD];
__device__ __nv_bfloat16 g_wp0h[EE * PP * CC0], g_wp0l[EE * PP * CC0];
__device__ __nv_bfloat16 g_wp1h[EE * PP * CC1], g_wp1l[EE * PP * CC1];
__device__ __nv_bfloat16 g_h0h[BB * CC0], g_h0l[BB * CC0];
__device__ __nv_bfloat16 g_h1h[BB * CC1], g_h1l[BB * CC1];

struct alignas(8) bh4 { __nv_bfloat16 x, y, z, w; };

// ------------------------- asm helpers (all sm_80+ generic) ---------------
__device__ __forceinline__ uint32_t smem_u32(const void* p) {
    uint32_t a;
    asm("{ .reg .u64 t; cvta.to.shared.u64 t, %1; cvt.u32.u64 %0, t; }"
        : "=r"(a) : "l"(p));
    return a;
}
#define CPA(dst, src) \
    asm volatile("cp.async.cg.shared.global [%0], [%1], 16;" :: "r"(dst), "l"(src) : "memory")
#define CPA_COMMIT() asm volatile("cp.async.commit_group;" ::: "memory")
#define CPA_WAIT(n)  asm volatile("cp.async.wait_group %0;" :: "n"(n) : "memory")
#define LDM4(r, addr) \
    asm volatile("ldmatrix.sync.aligned.m8n8.x4.shared.b16 {%0,%1,%2,%3}, [%4];" \
                 : "=r"((r)[0]), "=r"((r)[1]), "=r"((r)[2]), "=r"((r)[3]) : "r"(addr))

__device__ __forceinline__ void mma_bf16(float* c, const uint32_t* a,
                                         uint32_t b0, uint32_t b1) {
    asm volatile(
        "mma.sync.aligned.m16n8k16.row.col.f32.bf16.bf16.f32 "
        "{%0,%1,%2,%3}, {%4,%5,%6,%7}, {%8,%9}, {%0,%1,%2,%3};"
        : "+f"(c[0]), "+f"(c[1]), "+f"(c[2]), "+f"(c[3])
        : "r"(a[0]), "r"(a[1]), "r"(a[2]), "r"(a[3]), "r"(b0), "r"(b1));
}

// one 64-wide K chunk: NG = N/16 groups; swizzled [row][64] bf16 tiles.
template <int NG>
__device__ __forceinline__ void mma_chunk(uint32_t AH, uint32_t AL,
                                          uint32_t BH, uint32_t BL,
                                          int m0, int lane, float* acc) {
    const int arow = m0 + (lane & 15);
    const uint32_t aoffb = (uint32_t)arow * 128u;
    const uint32_t axr = (uint32_t)((arow & 7) << 4);
    const uint32_t acb0 = (uint32_t)((lane >> 4) << 4);
    const int brl = ((lane >> 4) & 1) * 8 + (lane & 7);
    const uint32_t bcb0 = (uint32_t)(((lane >> 3) & 1) << 4);
    #pragma unroll
    for (int ks = 0; ks < 4; ks++) {
        uint32_t acb = ((uint32_t)(ks * 32) + acb0) ^ axr;
        uint32_t ah[4], al[4];
        LDM4(ah, AH + aoffb + acb);
        LDM4(al, AL + aoffb + acb);
        #pragma unroll
        for (int g = 0; g < NG; g++) {
            int brow = g * 16 + brl;
            uint32_t boff = (uint32_t)brow * 128u
                            + (((uint32_t)(ks * 32) + bcb0) ^ (uint32_t)((brow & 7) << 4));
            uint32_t bh[4], bl[4];
            LDM4(bh, BH + boff);
            LDM4(bl, BL + boff);
            float* c0 = acc + g * 8;
            float* c1 = acc + g * 8 + 4;
            mma_bf16(c0, ah, bh[0], bh[1]);
            mma_bf16(c0, ah, bl[0], bl[1]);
            mma_bf16(c0, al, bh[0], bh[1]);
            mma_bf16(c1, ah, bh[2], bh[3]);
            mma_bf16(c1, ah, bl[2], bl[3]);
            mma_bf16(c1, al, bh[2], bh[3]);
        }
    }
}

// ------------------------- small kernels -------------------------
__global__ void k_init() {
    int t = threadIdx.x;
    if (t < EE) { g_cnt[t] = 0; g_cur[t] = 0; }
}

__global__ void k_cvt(const float* __restrict__ src, int n, int sel) {
    __nv_bfloat16 *dh, *dl;
    switch (sel) {
        case 0: dh = g_xh;   dl = g_xl;   break;
        case 1: dh = g_wfc0h; dl = g_wfc0l; break;
        case 2: dh = g_wfc1h; dl = g_wfc1l; break;
        case 3: dh = g_wp0h; dl = g_wp0l; break;
        default: dh = g_wp1h; dl = g_wp1l; break;
    }
    int i4 = blockIdx.x * 256 + threadIdx.x;
    if (i4 * 4 < n) {
        float4 v = ((const float4*)src)[i4];
        bh4 H, L;
        H.x = __float2bfloat16(v.x); L.x = __float2bfloat16(v.x - __bfloat162float(H.x));
        H.y = __float2bfloat16(v.y); L.y = __float2bfloat16(v.y - __bfloat162float(H.y));
        H.z = __float2bfloat16(v.z); L.z = __float2bfloat16(v.z - __bfloat162float(H.z));
        H.w = __float2bfloat16(v.w); L.w = __float2bfloat16(v.w - __bfloat162float(H.w));
        ((bh4*)dh)[i4] = H;
        ((bh4*)dl)[i4] = L;
    }
}

__global__ void k_scan() {
    if (threadIdx.x == 0) {
        int o = 0;
        for (int e = 0; e < EE; e++) { g_off[e] = o; o += g_cnt[e]; }
        g_off[EE] = o;
    }
}

__global__ void k_scatter() {
    int b = blockIdx.x * 256 + threadIdx.x;
    if (b < BB) {
        int e = g_class[b];
        int pos = g_off[e] + atomicAdd(&g_cur[e], 1);
        g_sidx[pos] = b;
    }
}

// ------------------------- parent FC (exact fp32) -------------------------
__global__ __launch_bounds__(128) void k_parent_fc(
    const float* __restrict__ x, const float* __restrict__ w,
    const float* __restrict__ bias, float* __restrict__ out_pl)
{
    __shared__ __align__(16) float xs[32][68];
    __shared__ __align__(16) float ws[32][20];
    __shared__ float spart[4][64][17];

    const int t = threadIdx.x;
    const int rowg = t & 7;
    const int eg = (t >> 3) & 3;
    const int kg = t >> 5;
    const int brow = blockIdx.x * 64;

    float acc[8][4];
    #pragma unroll
    for (int i = 0; i < 8; i++)
        #pragma unroll
        for (int j = 0; j < 4; j++) acc[i][j] = 0.f;

    for (int kt = 0; kt < DD / 32; kt++) {
        float4 rx[4];
        float4 rw;
        #pragma unroll
        for (int i = 0; i < 4; i++) {
            int s = t + i * 128;
            int row = s >> 3, kq = s & 7;
            rx[i] = *(const float4*)&x[(size_t)(brow + row) * DD + kt * 32 + kq * 4];
        }
        {
            int e2 = t >> 3, kq = t & 7;
            rw = *(const float4*)&w[(size_t)e2 * DD + kt * 32 + kq * 4];
        }
        __syncthreads();
        #pragma unroll
        for (int i = 0; i < 4; i++) {
            int s = t + i * 128;
            int row = s >> 3, kq = s & 7;
            xs[kq * 4 + 0][row] = rx[i].x;
            xs[kq * 4 + 1][row] = rx[i].y;
            xs[kq * 4 + 2][row] = rx[i].z;
            xs[kq * 4 + 3][row] = rx[i].w;
        }
        {
            int e2 = t >> 3, kq = t & 7;
            ws[kq * 4 + 0][e2] = rw.x;
            ws[kq * 4 + 1][e2] = rw.y;
            ws[kq * 4 + 2][e2] = rw.z;
            ws[kq * 4 + 3][e2] = rw.w;
        }
        __syncthreads();
        #pragma unroll
        for (int kk2 = 0; kk2 < 8; kk2++) {
            int kk = kg * 8 + kk2;
            float4 a0 = *(const float4*)&xs[kk][rowg * 4];
            float4 a1 = *(const float4*)&xs[kk][32 + rowg * 4];
            float4 bq = *(const float4*)&ws[kk][eg * 4];
            float av[8] = {a0.x, a0.y, a0.z, a0.w, a1.x, a1.y, a1.z, a1.w};
            float bv[4] = {bq.x, bq.y, bq.z, bq.w};
            #pragma unroll
            for (int i = 0; i < 8; i++)
                #pragma unroll
                for (int j = 0; j < 4; j++) acc[i][j] += av[i] * bv[j];
        }
        __syncthreads();
    }

    #pragma unroll
    for (int i = 0; i < 8; i++) {
        int r = (i < 4) ? (rowg * 4 + i) : (32 + rowg * 4 + (i - 4));
        #pragma unroll
        for (int j = 0; j < 4; j++) spart[kg][r][eg * 4 + j] = acc[i][j];
    }
    __syncthreads();

    if (t < 64) {
        int r = t;
        int b = brow + r;
        float z[16];
        float mu = 0.f;
        #pragma unroll
        for (int e2 = 0; e2 < 16; e2++) {
            float v = spart[0][r][e2] + spart[1][r][e2] + spart[2][r][e2] + spart[3][r][e2]
                      + bias[e2];
            z[e2] = v;
            mu += v;
        }
        mu *= (1.f / 16.f);
        float var = 0.f;
        #pragma unroll
        for (int e2 = 0; e2 < 16; e2++) { float d = z[e2] - mu; var += d * d; }
        var *= (1.f / 16.f);
        float rs = rsqrtf(var + LN_EPS);

        float best = z[0];
        int cls = 0;
        #pragma unroll
        for (int e2 = 1; e2 < 16; e2++)
            if (z[e2] > best) { best = z[e2]; cls = e2; }

        #pragma unroll
        for (int q = 0; q < 4; q++) {
            float4 o = make_float4((z[q * 4 + 0] - mu) * rs, (z[q * 4 + 1] - mu) * rs,
                                   (z[q * 4 + 2] - mu) * rs, (z[q * 4 + 3] - mu) * rs);
            *(float4*)&out_pl[(size_t)b * 16 + q * 4] = o;
        }
        g_class[b] = cls;
        atomicAdd(&g_cnt[cls], 1);
    }
}

// ------------------------- parent proj -------------------------
__global__ __launch_bounds__(256) void k_parent_proj(
    const float* __restrict__ pl, const float* __restrict__ w,
    const float* __restrict__ bias, float* __restrict__ out)
{
    __shared__ __align__(16) float spl[64][20];
    const int t = threadIdx.x;
    const int brow = blockIdx.x * 64;

    {
        int row = t >> 2, q = t & 3;
        float4 g = *(const float4*)&pl[(size_t)(brow + row) * 16 + q * 4];
        spl[row][q * 4 + 0] = g.x;
        spl[row][q * 4 + 1] = g.y;
        spl[row][q * 4 + 2] = g.z;
        spl[row][q * 4 + 3] = g.w;
    }
    __syncthreads();

    for (int pass = 0; pass < 2; pass++) {
        int p0 = pass * 512 + t * 2;
        float w0[16], w1[16];
        #pragma unroll
        for (int q = 0; q < 4; q++) {
            float4 a = *(const float4*)&w[(size_t)p0 * 16 + q * 4];
            w0[q * 4 + 0] = a.x; w0[q * 4 + 1] = a.y; w0[q * 4 + 2] = a.z; w0[q * 4 + 3] = a.w;
            float4 c = *(const float4*)&w[(size_t)(p0 + 1) * 16 + q * 4];
            w1[q * 4 + 0] = c.x; w1[q * 4 + 1] = c.y; w1[q * 4 + 2] = c.z; w1[q * 4 + 3] = c.w;
        }
        float b0 = bias[p0], b1 = bias[p0 + 1];

        for (int r = 0; r < 64; r++) {
            float a0 = b0, a1 = b1;
            #pragma unroll
            for (int q = 0; q < 4; q++) {
                float4 v = *(const float4*)&spl[r][q * 4];
                a0 += v.x * w0[q * 4 + 0] + v.y * w0[q * 4 + 1] + v.z * w0[q * 4 + 2] + v.w * w0[q * 4 + 3];
                a1 += v.x * w1[q * 4 + 0] + v.y * w1[q * 4 + 1] + v.z * w1[q * 4 + 2] + v.w * w1[q * 4 + 3];
            }
            float2 o = make_float2(a0, a1);
            *(float2*)&out[(size_t)(brow + r) * PP + p0] = o;
        }
    }
}

// ===========================================================================
// Child FC + LN via warp HMMA (bf16 split-3). M-tile 128, full BN per warp.
// Buffers: AH 16K | AL 16K | BH BN*128 | BL BN*128, double-buffered.
// ===========================================================================
#define FC_SMEM 131072

template <int BN>
__device__ __forceinline__ void tfc_impl(
    const __nv_bfloat16* __restrict__ xh, const __nv_bfloat16* __restrict__ xl,
    const __nv_bfloat16* __restrict__ wh, const __nv_bfloat16* __restrict__ wl,
    const float* __restrict__ bias, float* __restrict__ out,
    __nv_bfloat16* __restrict__ hh, __nv_bfloat16* __restrict__ hl,
    char* sm, int* sidx)
{
    const int e = blockIdx.y;
    const int start = g_off[e] + blockIdx.x * 128;
    const int end = g_off[e + 1];
    if (start >= end) return;

    const int t = threadIdx.x;
    const int wid = t >> 5, lane = t & 31;
    const int m0 = wid * 16;
    const uint32_t sb = smem_u32(sm);

    constexpr int BH0 = 32768, BL0 = 32768 + BN * 128, BUF = 32768 + 2 * BN * 128;

    if (t < 128) { int gi = start + t; sidx[t] = g_sidx[gi < end ? gi : end - 1]; }
    __syncthreads();

    auto issue = [&](int kt) {
        uint32_t base = sb + (uint32_t)((kt & 1) * BUF);
        #pragma unroll
        for (int i = 0; i < 4; i++) {
            int s = t + i * 256;
            int row = s >> 3, ch = s & 7;
            size_t g = (size_t)sidx[row] * DD + kt * 64 + ch * 8;
            uint32_t off = (uint32_t)(row * 128 + ((ch * 16) ^ ((row & 7) << 4)));
            CPA(base + off, xh + g);
            CPA(base + 16384 + off, xl + g);
        }
        #pragma unroll
        for (int i = 0; i < BN / 32; i++) {
            int s = t + i * 256;
            int row = s >> 3, ch = s & 7;
            size_t g = ((size_t)e * BN + row) * DD + kt * 64 + ch * 8;
            uint32_t off = (uint32_t)(row * 128 + ((ch * 16) ^ ((row & 7) << 4)));
            CPA(base + BH0 + off, wh + g);
            CPA(base + BL0 + off, wl + g);
        }
        CPA_COMMIT();
    };

    float acc[BN / 2];
    #pragma unroll
    for (int i = 0; i < BN / 2; i++) acc[i] = 0.f;

    issue(0);
    const int NKT = DD / 64;
    for (int kt = 0; kt < NKT; kt++) {
        if (kt + 1 < NKT) { issue(kt + 1); CPA_WAIT(1); }
        else              { CPA_WAIT(0); }
        __syncthreads();
        uint32_t base = sb + (uint32_t)((kt & 1) * BUF);
        mma_chunk<BN / 16>(base, base + 16384, base + BH0, base + BL0, m0, lane, acc);
        __syncthreads();
    }

    // epilogue: bias + LN (warp-local, quad butterfly) + store + h hi/lo
    const int r0 = m0 + (lane >> 2), r1 = r0 + 8;
    float s0 = 0.f, s1 = 0.f, q0 = 0.f, q1 = 0.f;
    #pragma unroll
    for (int qd = 0; qd < BN / 8; qd++) {
        int col = qd * 8 + (lane & 3) * 2;
        float bv0 = bias[e * BN + col], bv1 = bias[e * BN + col + 1];
        acc[qd * 4 + 0] += bv0; acc[qd * 4 + 1] += bv1;
        acc[qd * 4 + 2] += bv0; acc[qd * 4 + 3] += bv1;
        s0 += acc[qd * 4 + 0] + acc[qd * 4 + 1];
        q0 += acc[qd * 4 + 0] * acc[qd * 4 + 0] + acc[qd * 4 + 1] * acc[qd * 4 + 1];
        s1 += acc[qd * 4 + 2] + acc[qd * 4 + 3];
        q1 += acc[qd * 4 + 2] * acc[qd * 4 + 2] + acc[qd * 4 + 3] * acc[qd * 4 + 3];
    }
    s0 += __shfl_xor_sync(~0u, s0, 1); s0 += __shfl_xor_sync(~0u, s0, 2);
    q0 += __shfl_xor_sync(~0u, q0, 1); q0 += __shfl_xor_sync(~0u, q0, 2);
    s1 += __shfl_xor_sync(~0u, s1, 1); s1 += __shfl_xor_sync(~0u, s1, 2);
    q1 += __shfl_xor_sync(~0u, q1, 1); q1 += __shfl_xor_sync(~0u, q1, 2);
    float mu0 = s0 * (1.f / BN), mu1 = s1 * (1.f / BN);
    float rs0 = rsqrtf(q0 * (1.f / BN) - mu0 * mu0 + LN_EPS);
    float rs1 = rsqrtf(q1 * (1.f / BN) - mu1 * mu1 + LN_EPS);

    const bool w0 = (start + r0 < end), w1 = (start + r1 < end);
    const int bi0 = sidx[r0], bi1 = sidx[r1];
    #pragma unroll
    for (int qd = 0; qd < BN / 8; qd++) {
        int col = qd * 8 + (lane & 3) * 2;
        if (w0) {
            float o0 = (acc[qd * 4 + 0] - mu0) * rs0;
            float o1 = (acc[qd * 4 + 1] - mu0) * rs0;
            *(float2*)&out[(size_t)bi0 * BN + col] = make_float2(o0, o1);
            __nv_bfloat16 h0 = __float2bfloat16(o0), h1 = __float2bfloat16(o1);
            __nv_bfloat16 l0 = __float2bfloat16(o0 - __bfloat162float(h0));
            __nv_bfloat16 l1 = __float2bfloat16(o1 - __bfloat162float(h1));
            *(uint32_t*)&hh[(size_t)bi0 * BN + col] =
                ((uint32_t)__bfloat16_as_ushort(h1) << 16) | __bfloat16_as_ushort(h0);
            *(uint32_t*)&hl[(size_t)bi0 * BN + col] =
                ((uint32_t)__bfloat16_as_ushort(l1) << 16) | __bfloat16_as_ushort(l0);
        }
        if (w1) {
            float o0 = (acc[qd * 4 + 2] - mu1) * rs1;
            float o1 = (acc[qd * 4 + 3] - mu1) * rs1;
            *(float2*)&out[(size_t)bi1 * BN + col] = make_float2(o0, o1);
            __nv_bfloat16 h0 = __float2bfloat16(o0), h1 = __float2bfloat16(o1);
            __nv_bfloat16 l0 = __float2bfloat16(o0 - __bfloat162float(h0));
            __nv_bfloat16 l1 = __float2bfloat16(o1 - __bfloat162float(h1));
            *(uint32_t*)&hh[(size_t)bi1 * BN + col] =
                ((uint32_t)__bfloat16_as_ushort(h1) << 16) | __bfloat16_as_ushort(h0);
            *(uint32_t*)&hl[(size_t)bi1 * BN + col] =
                ((uint32_t)__bfloat16_as_ushort(l1) << 16) | __bfloat16_as_ushort(l0);
        }
    }
}

__global__ __launch_bounds__(256, 1) void k_tfc(
    const float* __restrict__ bfc0, const float* __restrict__ bfc1,
    float* __restrict__ out)
{
    extern __shared__ char smx[];
    __shared__ int sidx[128];
    if (blockIdx.z == 0)
        tfc_impl<CC0>(g_xh, g_xl, g_wfc0h, g_wfc0l, bfc0, out + OFF_CL0, g_h0h, g_h0l, smx, sidx);
    else
        tfc_impl<CC1>(g_xh, g_xl, g_wfc1h, g_wfc1l, bfc1, out + OFF_CL1, g_h1h, g_h1l, smx, sidx);
}

// ===========================================================================
// Child proj via warp HMMA: M-tile 128 x N-tile 128, K=CK single stage.
// Matrices per kc-half (64 cols): 16KB each. AH | AL | BH | BL.
// ===========================================================================
#define PROJ_SMEM 131072

template <int CK>
__device__ __forceinline__ void tproj_impl(
    const __nv_bfloat16* __restrict__ ah, const __nv_bfloat16* __restrict__ al,
    const __nv_bfloat16* __restrict__ wh, const __nv_bfloat16* __restrict__ wl,
    const float* __restrict__ bias, float* __restrict__ out,
    int pt, char* sm, int* sidx)
{
    const int e = blockIdx.y;
    const int start = g_off[e] + blockIdx.x * 128;
    const int end = g_off[e + 1];
    if (start >= end) return;

    constexpr int NKC = CK / 64;
    const int t = threadIdx.x;
    const int wid = t >> 5, lane = t & 31;
    const int m0 = wid * 16;
    const uint32_t sb = smem_u32(sm);
    constexpr uint32_t MSZ = (uint32_t)NKC * 16384u;

    if (t < 128) { int gi = start + t; sidx[t] = g_sidx[gi < end ? gi : end - 1]; }
    __syncthreads();

    #pragma unroll
    for (int kc = 0; kc < NKC; kc++) {
        #pragma unroll
        for (int i = 0; i < 4; i++) {
            int s = t + i * 256;
            int row = s >> 3, ch = s & 7;
            uint32_t off = (uint32_t)(kc * 16384 + row * 128 + ((ch * 16) ^ ((row & 7) << 4)));
            size_t ga = (size_t)sidx[row] * CK + kc * 64 + ch * 8;
            CPA(sb + off, ah + ga);
            CPA(sb + MSZ + off, al + ga);
            size_t gb = ((size_t)(e * PP + pt * 128 + row)) * CK + kc * 64 + ch * 8;
            CPA(sb + 2 * MSZ + off, wh + gb);
            CPA(sb + 3 * MSZ + off, wl + gb);
        }
    }
    CPA_COMMIT();
    CPA_WAIT(0);
    __syncthreads();

    float acc[64];
    #pragma unroll
    for (int i = 0; i < 64; i++) acc[i] = 0.f;

    #pragma unroll
    for (int kc = 0; kc < NKC; kc++) {
        uint32_t base = sb + (uint32_t)(kc * 16384);
        mma_chunk<8>(base, base + MSZ, base + 2 * MSZ, base + 3 * MSZ, m0, lane, acc);
    }

    const int r0 = m0 + (lane >> 2), r1 = r0 + 8;
    const bool v0 = (start + r0 < end), v1 = (start + r1 < end);
    const int bi0 = sidx[r0], bi1 = sidx[r1];
    #pragma unroll
    for (int qd = 0; qd < 16; qd++) {
        int p = pt * 128 + qd * 8 + (lane & 3) * 2;
        float bv0 = bias[(size_t)e * PP + p], bv1 = bias[(size_t)e * PP + p + 1];
        if (v0)
            *(float2*)&out[(size_t)bi0 * PP + p] =
                make_float2(acc[qd * 4 + 0] + bv0, acc[qd * 4 + 1] + bv1);
        if (v1)
            *(float2*)&out[(size_t)bi1 * PP + p] =
                make_float2(acc[qd * 4 + 2] + bv0, acc[qd * 4 + 3] + bv1);
    }
}

__global__ __launch_bounds__(256, 1) void k_tproj(
    const float* __restrict__ bpr0, const float* __restrict__ bpr1,
    float* __restrict__ out)
{
    extern __shared__ char smx[];
    __shared__ int sidx[128];
    const int level = blockIdx.z >> 3;
    const int pt = blockIdx.z & 7;
    if (level == 0)
        tproj_impl<CC0>(g_h0h, g_h0l, g_wp0h, g_wp0l, bpr0, out + OFF_CP0, pt, smx, sidx);
    else
        tproj_impl<CC1>(g_h1h, g_h1l, g_wp1h, g_wp1l, bpr1, out + OFF_CP1, pt, smx, sidx);
}

// ---------------------------------------------------------------------------

extern "C" void kernel_launch(void* const* d_in, const int* in_sizes, int n_in,
                              void* d_out, int out_size) {
    const float* x       = (const float*)d_in[0];
    const float* pw_fc   = (const float*)d_in[1];
    const float* pb_fc   = (const float*)d_in[2];
    const float* pw_proj = (const float*)d_in[3];
    const float* pb_proj = (const float*)d_in[4];
    const float* cw_fc0  = (const float*)d_in[5];
    const float* cb_fc0  = (const float*)d_in[6];
    const float* cw_pr0  = (const float*)d_in[7];
    const float* cb_pr0  = (const float*)d_in[8];
    const float* cw_fc1  = (const float*)d_in[9];
    const float* cb_fc1  = (const float*)d_in[10];
    const float* cw_pr1  = (const float*)d_in[11];
    const float* cb_pr1  = (const float*)d_in[12];
    float* out = (float*)d_out;

    cudaFuncSetAttribute(k_tfc, cudaFuncAttributeMaxDynamicSharedMemorySize, FC_SMEM);
    cudaFuncSetAttribute(k_tproj, cudaFuncAttributeMaxDynamicSharedMemorySize, PROJ_SMEM);

    k_init<<<1, 32>>>();

    k_cvt<<<(BB * DD / 4 + 255) / 256, 256>>>(x, BB * DD, 0);
    k_cvt<<<(EE * CC0 * DD / 4 + 255) / 256, 256>>>(cw_fc0, EE * CC0 * DD, 1);
    k_cvt<<<(EE * CC1 * DD / 4 + 255) / 256, 256>>>(cw_fc1, EE * CC1 * DD, 2);
    k_cvt<<<(EE * PP * CC0 / 4 + 255) / 256, 256>>>(cw_pr0, EE * PP * CC0, 3);
    k_cvt<<<(EE * PP * CC1 / 4 + 255) / 256, 256>>>(cw_pr1, EE * PP * CC1, 4);

    k_parent_fc<<<BB / 64, 128>>>(x, pw_fc, pb_fc, out + OFF_PL);
    k_scan<<<1, 32>>>();
    k_scatter<<<BB / 256, 256>>>();
    k_parent_proj<<<BB / 64, 256>>>(out + OFF_PL, pw_proj, pb_proj, out + OFF_PP);

    dim3 gfc(BB / 128, EE, 2);
    k_tfc<<<gfc, 256, FC_SMEM>>>(cb_fc0, cb_fc1, out);

    dim3 gpr(BB / 128, EE, 16);
    k_tproj<<<gpr, 256, PROJ_SMEM>>>(cb_pr0, cb_pr1, out);
}

// round 8
// speedup vs baseline: 2.3855x; 1.0003x over previous
#include <cuda_runtime.h>
#include <cuda_bf16.h>
#include <cstdint>

#define BB 8192
#define DD 2048
#define EE 16
#define PP 1024
#define CC0 64
#define CC1 128
#define LN_EPS 1e-5f

#define OFF_PL  0
#define OFF_CL0 (BB*EE)
#define OFF_CL1 (OFF_CL0 + BB*CC0)
#define OFF_PP  (OFF_CL1 + BB*CC1)
#define OFF_CP0 (OFF_PP + BB*PP)
#define OFF_CP1 (OFF_CP0 + BB*PP)

typedef unsigned long long u64t;

// ------------------------- scratch globals -------------------------
__device__ int g_class[BB];
__device__ int g_cnt[EE];
__device__ int g_cur[EE];
__device__ int g_off[EE + 1];
__device__ int g_sidx[BB];

__device__ __nv_bfloat16 g_wfc0h[EE * CC0 * DD], g_wfc0l[EE * CC0 * DD];
__device__ __nv_bfloat16 g_wfc1h[EE * CC1 * DD], g_wfc1l[EE * CC1 * DD];
__device__ __nv_bfloat16 g_wp0h[EE * PP * CC0], g_wp0l[EE * PP * CC0];
__device__ __nv_bfloat16 g_wp1h[EE * PP * CC1], g_wp1l[EE * PP * CC1];
__device__ __nv_bfloat16 g_h0h[BB * CC0], g_h0l[BB * CC0];
__device__ __nv_bfloat16 g_h1h[BB * CC1], g_h1l[BB * CC1];

// split-K partials (fp32)
__device__ float g_pt0[4 * BB * CC0];
__device__ float g_pt1[4 * BB * CC1];

struct alignas(8) bh4 { __nv_bfloat16 x, y, z, w; };

// ------------------------- asm helpers (sm_80+ generic) ---------------
__device__ __forceinline__ uint32_t smem_u32(const void* p) {
    uint32_t a;
    asm("{ .reg .u64 t; cvta.to.shared.u64 t, %1; cvt.u32.u64 %0, t; }"
        : "=r"(a) : "l"(p));
    return a;
}
#define CPA(dst, src) \
    asm volatile("cp.async.cg.shared.global [%0], [%1], 16;" :: "r"(dst), "l"(src) : "memory")
#define CPA_COMMIT() asm volatile("cp.async.commit_group;" ::: "memory")
#define CPA_WAIT(n)  asm volatile("cp.async.wait_group %0;" :: "n"(n) : "memory")
#define LDM4(r, addr) \
    asm volatile("ldmatrix.sync.aligned.m8n8.x4.shared.b16 {%0,%1,%2,%3}, [%4];" \
                 : "=r"((r)[0]), "=r"((r)[1]), "=r"((r)[2]), "=r"((r)[3]) : "r"(addr))

__device__ __forceinline__ void mma_bf16(float* c, const uint32_t* a,
                                         uint32_t b0, uint32_t b1) {
    asm volatile(
        "mma.sync.aligned.m16n8k16.row.col.f32.bf16.bf16.f32 "
        "{%0,%1,%2,%3}, {%4,%5,%6,%7}, {%8,%9}, {%0,%1,%2,%3};"
        : "+f"(c[0]), "+f"(c[1]), "+f"(c[2]), "+f"(c[3])
        : "r"(a[0]), "r"(a[1]), "r"(a[2]), "r"(a[3]), "r"(b0), "r"(b1));
}

// Two 16-row subtiles per warp sharing the same B fragments (halves LDS/FMA).
// NG groups of 16 cols. Swizzled [row][64] bf16 tiles (128B rows).
template <int NG>
__device__ __forceinline__ void mma_chunk2(uint32_t AH, uint32_t AL,
                                           uint32_t BH, uint32_t BL,
                                           int m0, int lane,
                                           float* accA, float* accB) {
    const int arow0 = m0 + (lane & 15);
    const uint32_t aoff0 = (uint32_t)arow0 * 128u;
    const uint32_t aoff1 = aoff0 + 16u * 128u;
    const uint32_t axr = (uint32_t)((arow0 & 7) << 4);  // same for arow0+16
    const uint32_t acb0 = (uint32_t)((lane >> 4) << 4);
    const int brl = ((lane >> 4) & 1) * 8 + (lane & 7);
    const uint32_t bcb0 = (uint32_t)(((lane >> 3) & 1) << 4);
    #pragma unroll
    for (int ks = 0; ks < 4; ks++) {
        uint32_t acb = ((uint32_t)(ks * 32) + acb0) ^ axr;
        uint32_t ah0[4], al0[4], ah1[4], al1[4];
        LDM4(ah0, AH + aoff0 + acb);
        LDM4(al0, AL + aoff0 + acb);
        LDM4(ah1, AH + aoff1 + acb);
        LDM4(al1, AL + aoff1 + acb);
        #pragma unroll
        for (int g = 0; g < NG; g++) {
            int brow = g * 16 + brl;
            uint32_t boff = (uint32_t)brow * 128u
                            + (((uint32_t)(ks * 32) + bcb0) ^ (uint32_t)((brow & 7) << 4));
            uint32_t bh[4], bl[4];
            LDM4(bh, BH + boff);
            LDM4(bl, BL + boff);
            float* c0 = accA + g * 8;
            float* c1 = accA + g * 8 + 4;
            mma_bf16(c0, ah0, bh[0], bh[1]);
            mma_bf16(c0, ah0, bl[0], bl[1]);
            mma_bf16(c0, al0, bh[0], bh[1]);
            mma_bf16(c1, ah0, bh[2], bh[3]);
            mma_bf16(c1, ah0, bl[2], bl[3]);
            mma_bf16(c1, al0, bh[2], bh[3]);
            float* d0 = accB + g * 8;
            float* d1 = accB + g * 8 + 4;
            mma_bf16(d0, ah1, bh[0], bh[1]);
            mma_bf16(d0, ah1, bl[0], bl[1]);
            mma_bf16(d0, al1, bh[0], bh[1]);
            mma_bf16(d1, ah1, bh[2], bh[3]);
            mma_bf16(d1, ah1, bl[2], bl[3]);
            mma_bf16(d1, al1, bh[2], bh[3]);
        }
    }
}

__device__ __forceinline__ void split8(const float* v, uint32_t* H, uint32_t* L) {
    #pragma unroll
    for (int i = 0; i < 4; i++) {
        __nv_bfloat16 h0 = __float2bfloat16(v[2 * i]);
        __nv_bfloat16 h1 = __float2bfloat16(v[2 * i + 1]);
        float l0 = v[2 * i] - __bfloat162float(h0);
        float l1 = v[2 * i + 1] - __bfloat162float(h1);
        H[i] = ((uint32_t)__bfloat16_as_ushort(h1) << 16) | __bfloat16_as_ushort(h0);
        __nv_bfloat16 g0 = __float2bfloat16(l0);
        __nv_bfloat16 g1 = __float2bfloat16(l1);
        L[i] = ((uint32_t)__bfloat16_as_ushort(g1) << 16) | __bfloat16_as_ushort(g0);
    }
}

// ------------------------- small kernels -------------------------
__global__ void k_init() {
    int t = threadIdx.x;
    if (t < EE) { g_cnt[t] = 0; g_cur[t] = 0; }
}

// one launch: all 4 weight arrays -> bf16 hi/lo
__global__ void k_cvtw(const float* __restrict__ s0, const float* __restrict__ s1,
                       const float* __restrict__ s2, const float* __restrict__ s3) {
    const int sel = blockIdx.y;
    const float* src;
    __nv_bfloat16 *dh, *dl;
    int n;
    switch (sel) {
        case 0: src = s0; dh = g_wfc0h; dl = g_wfc0l; n = EE * CC0 * DD; break;
        case 1: src = s1; dh = g_wfc1h; dl = g_wfc1l; n = EE * CC1 * DD; break;
        case 2: src = s2; dh = g_wp0h;  dl = g_wp0l;  n = EE * PP * CC0; break;
        default: src = s3; dh = g_wp1h; dl = g_wp1l;  n = EE * PP * CC1; break;
    }
    int i4 = blockIdx.x * 256 + threadIdx.x;
    if (i4 * 4 < n) {
        float4 v = ((const float4*)src)[i4];
        float vv[4] = {v.x, v.y, v.z, v.w};
        uint32_t H[2], L[2];
        #pragma unroll
        for (int i = 0; i < 2; i++) {
            __nv_bfloat16 h0 = __float2bfloat16(vv[2 * i]);
            __nv_bfloat16 h1 = __float2bfloat16(vv[2 * i + 1]);
            float l0 = vv[2 * i] - __bfloat162float(h0);
            float l1 = vv[2 * i + 1] - __bfloat162float(h1);
            H[i] = ((uint32_t)__bfloat16_as_ushort(h1) << 16) | __bfloat16_as_ushort(h0);
            __nv_bfloat16 g0 = __float2bfloat16(l0);
            __nv_bfloat16 g1 = __float2bfloat16(l1);
            L[i] = ((uint32_t)__bfloat16_as_ushort(g1) << 16) | __bfloat16_as_ushort(g0);
        }
        ((uint2*)dh)[i4] = make_uint2(H[0], H[1]);
        ((uint2*)dl)[i4] = make_uint2(L[0], L[1]);
    }
}

__global__ void k_scan() {
    if (threadIdx.x == 0) {
        int o = 0;
        for (int e = 0; e < EE; e++) { g_off[e] = o; o += g_cnt[e]; }
        g_off[EE] = o;
    }
}

__global__ void k_scatter() {
    int b = blockIdx.x * 256 + threadIdx.x;
    if (b < BB) {
        int e = g_class[b];
        int pos = g_off[e] + atomicAdd(&g_cur[e], 1);
        g_sidx[pos] = b;
    }
}

// ------------------------- parent FC (exact fp32) -------------------------
__global__ __launch_bounds__(128) void k_parent_fc(
    const float* __restrict__ x, const float* __restrict__ w,
    const float* __restrict__ bias, float* __restrict__ out_pl)
{
    __shared__ __align__(16) float xs[32][68];
    __shared__ __align__(16) float ws[32][20];
    __shared__ float spart[4][64][17];

    const int t = threadIdx.x;
    const int rowg = t & 7;
    const int eg = (t >> 3) & 3;
    const int kg = t >> 5;
    const int brow = blockIdx.x * 64;

    float acc[8][4];
    #pragma unroll
    for (int i = 0; i < 8; i++)
        #pragma unroll
        for (int j = 0; j < 4; j++) acc[i][j] = 0.f;

    for (int kt = 0; kt < DD / 32; kt++) {
        float4 rx[4];
        float4 rw;
        #pragma unroll
        for (int i = 0; i < 4; i++) {
            int s = t + i * 128;
            int row = s >> 3, kq = s & 7;
            rx[i] = *(const float4*)&x[(size_t)(brow + row) * DD + kt * 32 + kq * 4];
        }
        {
            int e2 = t >> 3, kq = t & 7;
            rw = *(const float4*)&w[(size_t)e2 * DD + kt * 32 + kq * 4];
        }
        __syncthreads();
        #pragma unroll
        for (int i = 0; i < 4; i++) {
            int s = t + i * 128;
            int row = s >> 3, kq = s & 7;
            xs[kq * 4 + 0][row] = rx[i].x;
            xs[kq * 4 + 1][row] = rx[i].y;
            xs[kq * 4 + 2][row] = rx[i].z;
            xs[kq * 4 + 3][row] = rx[i].w;
        }
        {
            int e2 = t >> 3, kq = t & 7;
            ws[kq * 4 + 0][e2] = rw.x;
            ws[kq * 4 + 1][e2] = rw.y;
            ws[kq * 4 + 2][e2] = rw.z;
            ws[kq * 4 + 3][e2] = rw.w;
        }
        __syncthreads();
        #pragma unroll
        for (int kk2 = 0; kk2 < 8; kk2++) {
            int kk = kg * 8 + kk2;
            float4 a0 = *(const float4*)&xs[kk][rowg * 4];
            float4 a1 = *(const float4*)&xs[kk][32 + rowg * 4];
            float4 bq = *(const float4*)&ws[kk][eg * 4];
            float av[8] = {a0.x, a0.y, a0.z, a0.w, a1.x, a1.y, a1.z, a1.w};
            float bv[4] = {bq.x, bq.y, bq.z, bq.w};
            #pragma unroll
            for (int i = 0; i < 8; i++)
                #pragma unroll
                for (int j = 0; j < 4; j++) acc[i][j] += av[i] * bv[j];
        }
        __syncthreads();
    }

    #pragma unroll
    for (int i = 0; i < 8; i++) {
        int r = (i < 4) ? (rowg * 4 + i) : (32 + rowg * 4 + (i - 4));
        #pragma unroll
        for (int j = 0; j < 4; j++) spart[kg][r][eg * 4 + j] = acc[i][j];
    }
    __syncthreads();

    if (t < 64) {
        int r = t;
        int b = brow + r;
        float z[16];
        float mu = 0.f;
        #pragma unroll
        for (int e2 = 0; e2 < 16; e2++) {
            float v = spart[0][r][e2] + spart[1][r][e2] + spart[2][r][e2] + spart[3][r][e2]
                      + bias[e2];
            z[e2] = v;
            mu += v;
        }
        mu *= (1.f / 16.f);
        float var = 0.f;
        #pragma unroll
        for (int e2 = 0; e2 < 16; e2++) { float d = z[e2] - mu; var += d * d; }
        var *= (1.f / 16.f);
        float rs = rsqrtf(var + LN_EPS);

        float best = z[0];
        int cls = 0;
        #pragma unroll
        for (int e2 = 1; e2 < 16; e2++)
            if (z[e2] > best) { best = z[e2]; cls = e2; }

        #pragma unroll
        for (int q = 0; q < 4; q++) {
            float4 o = make_float4((z[q * 4 + 0] - mu) * rs, (z[q * 4 + 1] - mu) * rs,
                                   (z[q * 4 + 2] - mu) * rs, (z[q * 4 + 3] - mu) * rs);
            *(float4*)&out_pl[(size_t)b * 16 + q * 4] = o;
        }
        g_class[b] = cls;
        atomicAdd(&g_cnt[cls], 1);
    }
}

// ------------------------- parent proj -------------------------
__global__ __launch_bounds__(256) void k_parent_proj(
    const float* __restrict__ pl, const float* __restrict__ w,
    const float* __restrict__ bias, float* __restrict__ out)
{
    __shared__ __align__(16) float spl[64][20];
    const int t = threadIdx.x;
    const int brow = blockIdx.x * 64;

    {
        int row = t >> 2, q = t & 3;
        float4 g = *(const float4*)&pl[(size_t)(brow + row) * 16 + q * 4];
        spl[row][q * 4 + 0] = g.x;
        spl[row][q * 4 + 1] = g.y;
        spl[row][q * 4 + 2] = g.z;
        spl[row][q * 4 + 3] = g.w;
    }
    __syncthreads();

    for (int pass = 0; pass < 2; pass++) {
        int p0 = pass * 512 + t * 2;
        float w0[16], w1[16];
        #pragma unroll
        for (int q = 0; q < 4; q++) {
            float4 a = *(const float4*)&w[(size_t)p0 * 16 + q * 4];
            w0[q * 4 + 0] = a.x; w0[q * 4 + 1] = a.y; w0[q * 4 + 2] = a.z; w0[q * 4 + 3] = a.w;
            float4 c = *(const float4*)&w[(size_t)(p0 + 1) * 16 + q * 4];
            w1[q * 4 + 0] = c.x; w1[q * 4 + 1] = c.y; w1[q * 4 + 2] = c.z; w1[q * 4 + 3] = c.w;
        }
        float b0 = bias[p0], b1 = bias[p0 + 1];

        for (int r = 0; r < 64; r++) {
            float a0 = b0, a1 = b1;
            #pragma unroll
            for (int q = 0; q < 4; q++) {
                float4 v = *(const float4*)&spl[r][q * 4];
                a0 += v.x * w0[q * 4 + 0] + v.y * w0[q * 4 + 1] + v.z * w0[q * 4 + 2] + v.w * w0[q * 4 + 3];
                a1 += v.x * w1[q * 4 + 0] + v.y * w1[q * 4 + 1] + v.z * w1[q * 4 + 2] + v.w * w1[q * 4 + 3];
            }
            float2 o = make_float2(a0, a1);
            *(float2*)&out[(size_t)(brow + r) * PP + p0] = o;
        }
    }
}

// ===========================================================================
// Child FC split-K GEMM (no epilogue): partials to g_pt*. In-kernel x split.
// grid (64, EE, 8): z>>2 = level, z&3 = ksplit (512 k each, 8 chunks of 64).
// smem/buffer: XF(fp32 32K) | AH 16K | AL 16K | BH BN*128 | BL BN*128, x2.
// ===========================================================================
#define FC_SMEM 196608

template <int BN>
__device__ __forceinline__ void tfc_impl(
    const float* __restrict__ x,
    const __nv_bfloat16* __restrict__ wh, const __nv_bfloat16* __restrict__ wl,
    float* __restrict__ part, int ks, char* sm, int* sidx)
{
    const int e = blockIdx.y;
    const int start = g_off[e] + blockIdx.x * 128;
    const int end = g_off[e + 1];
    if (start >= end) return;

    const int t = threadIdx.x;
    const int wid = t >> 5, lane = t & 31;
    const int wr = wid & 3, wc = wid >> 2;
    const uint32_t sb = smem_u32(sm);
    const int kbase = ks * 512;

    constexpr int XF = 0, AH0 = 32768, AL0 = 49152, BH0 = 65536, BL0 = 65536 + BN * 128;
    constexpr int BUF = 65536 + 2 * BN * 128;
    constexpr int NGW = BN / 32;

    if (t < 128) { int gi = start + t; sidx[t] = g_sidx[gi < end ? gi : end - 1]; }
    __syncthreads();

    auto issue = [&](int kt) {
        uint32_t base = sb + (uint32_t)((kt & 1) * BUF);
        // x fp32: 128 rows x 64 fp32 = 2048 16B chunks
        #pragma unroll
        for (int i = 0; i < 8; i++) {
            int d = t + i * 256;
            int row = d >> 4, ch2 = d & 15;
            CPA(base + XF + (uint32_t)(row * 256 + ch2 * 16),
                x + (size_t)sidx[row] * DD + kbase + kt * 64 + ch2 * 4);
        }
        // weights bf16 hi/lo: BN rows x 128B
        #pragma unroll
        for (int i = 0; i < BN / 32; i++) {
            int d = t + i * 256;
            int row = d >> 3, ch = d & 7;
            uint32_t off = (uint32_t)(row * 128 + ((ch * 16) ^ ((row & 7) << 4)));
            size_t g = ((size_t)e * BN + row) * DD + kbase + kt * 64 + ch * 8;
            CPA(base + BH0 + off, wh + g);
            CPA(base + BL0 + off, wl + g);
        }
        CPA_COMMIT();
    };

    auto convert = [&](int kt) {
        char* base = sm + (kt & 1) * BUF;
        #pragma unroll
        for (int i = 0; i < 4; i++) {
            int c = t + i * 256;
            int row = c >> 3, ch8 = c & 7;
            float4 v0 = *(const float4*)(base + XF + row * 256 + ch8 * 32);
            float4 v1 = *(const float4*)(base + XF + row * 256 + ch8 * 32 + 16);
            float vv[8] = {v0.x, v0.y, v0.z, v0.w, v1.x, v1.y, v1.z, v1.w};
            uint32_t H[4], L[4];
            split8(vv, H, L);
            uint32_t off = (uint32_t)(row * 128 + ((ch8 * 16) ^ ((row & 7) << 4)));
            *(uint4*)(base + AH0 + off) = make_uint4(H[0], H[1], H[2], H[3]);
            *(uint4*)(base + AL0 + off) = make_uint4(L[0], L[1], L[2], L[3]);
        }
    };

    float accA[NGW * 8], accB[NGW * 8];
    #pragma unroll
    for (int i = 0; i < NGW * 8; i++) { accA[i] = 0.f; accB[i] = 0.f; }

    issue(0);
    const int NKT = 8;
    for (int kt = 0; kt < NKT; kt++) {
        CPA_WAIT(0);
        __syncthreads();
        convert(kt);
        __syncthreads();
        if (kt + 1 < NKT) issue(kt + 1);
        uint32_t base = sb + (uint32_t)((kt & 1) * BUF);
        mma_chunk2<NGW>(base + AH0, base + AL0,
                        base + BH0 + (uint32_t)(wc * (BN / 2) * 128),
                        base + BL0 + (uint32_t)(wc * (BN / 2) * 128),
                        wr * 32, lane, accA, accB);
    }

    // store fp32 partials (pure GEMM, bias/LN in reduce kernel)
    const int rA0 = wr * 32 + (lane >> 2);
    #pragma unroll
    for (int g = 0; g < NGW; g++) {
        #pragma unroll
        for (int half = 0; half < 2; half++) {
            int col = wc * (BN / 2) + (g * 2 + half) * 8 + (lane & 3) * 2;
            float* pa = accA + g * 8 + half * 4;
            float* pb = accB + g * 8 + half * 4;
            int rows[4] = {rA0, rA0 + 8, rA0 + 16, rA0 + 24};
            float* vals[4] = {pa, pa + 2, pb, pb + 2};
            #pragma unroll
            for (int rv = 0; rv < 4; rv++) {
                int p = start + rows[rv];
                if (p < end)
                    *(float2*)&part[(size_t)ks * BB * BN + (size_t)p * BN + col] =
                        make_float2(vals[rv][0], vals[rv][1]);
            }
        }
    }
}

__global__ __launch_bounds__(256, 1) void k_tfc(const float* __restrict__ x)
{
    extern __shared__ char smx[];
    __shared__ int sidx[128];
    const int level = blockIdx.z >> 2;
    const int ks = blockIdx.z & 3;
    if (level == 0)
        tfc_impl<CC0>(x, g_wfc0h, g_wfc0l, g_pt0, ks, smx, sidx);
    else
        tfc_impl<CC1>(x, g_wfc1h, g_wfc1l, g_pt1, ks, smx, sidx);
}

// ===========================================================================
// FC reduce: sum 4 partials + bias + LN + write cl + h hi/lo. 1 warp per row.
// ===========================================================================
template <int BN>
__device__ __forceinline__ void fcred_impl(
    const float* __restrict__ part, const float* __restrict__ bias,
    float* __restrict__ out, __nv_bfloat16* __restrict__ hh,
    __nv_bfloat16* __restrict__ hl)
{
    const int p = blockIdx.x * 8 + (threadIdx.x >> 5);
    const int lane = threadIdx.x & 31;
    const int b = g_sidx[p];
    const int e = g_class[b];
    constexpr int NC = BN / 32;

    float v[NC];
    float s = 0.f, q = 0.f;
    #pragma unroll
    for (int i = 0; i < NC; i++) {
        int col = lane + i * 32;
        size_t idx = (size_t)p * BN + col;
        float a = part[idx] + part[(size_t)BB * BN + idx]
                + part[2 * (size_t)BB * BN + idx] + part[3 * (size_t)BB * BN + idx]
                + bias[e * BN + col];
        v[i] = a;
        s += a;
        q += a * a;
    }
    #pragma unroll
    for (int o = 16; o; o >>= 1) {
        s += __shfl_xor_sync(~0u, s, o);
        q += __shfl_xor_sync(~0u, q, o);
    }
    float mu = s * (1.f / BN);
    float rs = rsqrtf(q * (1.f / BN) - mu * mu + LN_EPS);
    #pragma unroll
    for (int i = 0; i < NC; i++) {
        int col = lane + i * 32;
        float o = (v[i] - mu) * rs;
        out[(size_t)b * BN + col] = o;
        __nv_bfloat16 h = __float2bfloat16(o);
        __nv_bfloat16 l = __float2bfloat16(o - __bfloat162float(h));
        hh[(size_t)b * BN + col] = h;
        hl[(size_t)b * BN + col] = l;
    }
}

__global__ __launch_bounds__(256) void k_fcred(
    const float* __restrict__ b0, const float* __restrict__ b1,
    float* __restrict__ out)
{
    if (blockIdx.y == 0)
        fcred_impl<CC0>(g_pt0, b0, out + OFF_CL0, g_h0h, g_h0l);
    else
        fcred_impl<CC1>(g_pt1, b1, out + OFF_CL1, g_h1h, g_h1l);
}

// ===========================================================================
// Child proj: M 128 x N 128 per block, K=CK. 4x2 warp grid, shared-B mma.
// ===========================================================================
#define PROJ_SMEM 131072

template <int CK>
__device__ __forceinline__ void tproj_impl(
    const __nv_bfloat16* __restrict__ ah, const __nv_bfloat16* __restrict__ al,
    const __nv_bfloat16* __restrict__ wh, const __nv_bfloat16* __restrict__ wl,
    const float* __restrict__ bias, float* __restrict__ out,
    int pt, char* sm, int* sidx)
{
    const int e = blockIdx.y;
    const int start = g_off[e] + blockIdx.x * 128;
    const int end = g_off[e + 1];
    if (start >= end) return;

    constexpr int NKC = CK / 64;
    const int t = threadIdx.x;
    const int wid = t >> 5, lane = t & 31;
    const int wr = wid & 3, wc = wid >> 2;
    const uint32_t sb = smem_u32(sm);
    constexpr uint32_t MSZ = (uint32_t)NKC * 16384u;

    if (t < 128) { int gi = start + t; sidx[t] = g_sidx[gi < end ? gi : end - 1]; }
    __syncthreads();

    #pragma unroll
    for (int kc = 0; kc < NKC; kc++) {
        #pragma unroll
        for (int i = 0; i < 4; i++) {
            int s = t + i * 256;
            int row = s >> 3, ch = s & 7;
            uint32_t off = (uint32_t)(kc * 16384 + row * 128 + ((ch * 16) ^ ((row & 7) << 4)));
            size_t ga = (size_t)sidx[row] * CK + kc * 64 + ch * 8;
            CPA(sb + off, ah + ga);
            CPA(sb + MSZ + off, al + ga);
            size_t gb = ((size_t)(e * PP + pt * 128 + row)) * CK + kc * 64 + ch * 8;
            CPA(sb + 2 * MSZ + off, wh + gb);
            CPA(sb + 3 * MSZ + off, wl + gb);
        }
    }
    CPA_COMMIT();
    CPA_WAIT(0);
    __syncthreads();

    float accA[32], accB[32];
    #pragma unroll
    for (int i = 0; i < 32; i++) { accA[i] = 0.f; accB[i] = 0.f; }

    #pragma unroll
    for (int kc = 0; kc < NKC; kc++) {
        uint32_t base = sb + (uint32_t)(kc * 16384);
        mma_chunk2<4>(base, base + MSZ,
                      base + 2 * MSZ + (uint32_t)(wc * 64 * 128),
                      base + 3 * MSZ + (uint32_t)(wc * 64 * 128),
                      wr * 32, lane, accA, accB);
    }

    const int rA0 = wr * 32 + (lane >> 2);
    #pragma unroll
    for (int g = 0; g < 4; g++) {
        #pragma unroll
        for (int half = 0; half < 2; half++) {
            int pcol = pt * 128 + wc * 64 + (g * 2 + half) * 8 + (lane & 3) * 2;
            float bv0 = bias[(size_t)e * PP + pcol];
            float bv1 = bias[(size_t)e * PP + pcol + 1];
            float* pa = accA + g * 8 + half * 4;
            float* pb = accB + g * 8 + half * 4;
            int rows[4] = {rA0, rA0 + 8, rA0 + 16, rA0 + 24};
            float* vals[4] = {pa, pa + 2, pb, pb + 2};
            #pragma unroll
            for (int rv = 0; rv < 4; rv++) {
                if (start + rows[rv] < end) {
                    int b = sidx[rows[rv]];
                    *(float2*)&out[(size_t)b * PP + pcol] =
                        make_float2(vals[rv][0] + bv0, vals[rv][1] + bv1);
                }
            }
        }
    }
}

__global__ __launch_bounds__(256, 1) void k_tproj(
    const float* __restrict__ bpr0, const float* __restrict__ bpr1,
    float* __restrict__ out)
{
    extern __shared__ char smx[];
    __shared__ int sidx[128];
    const int level = blockIdx.z >> 3;
    const int pt = blockIdx.z & 7;
    if (level == 0)
        tproj_impl<CC0>(g_h0h, g_h0l, g_wp0h, g_wp0l, bpr0, out + OFF_CP0, pt, smx, sidx);
    else
        tproj_impl<CC1>(g_h1h, g_h1l, g_wp1h, g_wp1l, bpr1, out + OFF_CP1, pt, smx, sidx);
}

// ---------------------------------------------------------------------------

extern "C" void kernel_launch(void* const* d_in, const int* in_sizes, int n_in,
                              void* d_out, int out_size) {
    const float* x       = (const float*)d_in[0];
    const float* pw_fc   = (const float*)d_in[1];
    const float* pb_fc   = (const float*)d_in[2];
    const float* pw_proj = (const float*)d_in[3];
    const float* pb_proj = (const float*)d_in[4];
    const float* cw_fc0  = (const float*)d_in[5];
    const float* cb_fc0  = (const float*)d_in[6];
    const float* cw_pr0  = (const float*)d_in[7];
    const float* cb_pr0  = (const float*)d_in[8];
    const float* cw_fc1  = (const float*)d_in[9];
    const float* cb_fc1  = (const float*)d_in[10];
    const float* cw_pr1  = (const float*)d_in[11];
    const float* cb_pr1  = (const float*)d_in[12];
    float* out = (float*)d_out;

    cudaFuncSetAttribute(k_tfc, cudaFuncAttributeMaxDynamicSharedMemorySize, FC_SMEM);
    cudaFuncSetAttribute(k_tproj, cudaFuncAttributeMaxDynamicSharedMemorySize, PROJ_SMEM);

    k_init<<<1, 32>>>();
    k_cvtw<<<dim3(4096, 4), 256>>>(cw_fc0, cw_fc1, cw_pr0, cw_pr1);

    k_parent_fc<<<BB / 64, 128>>>(x, pw_fc, pb_fc, out + OFF_PL);
    k_scan<<<1, 32>>>();
    k_scatter<<<BB / 256, 256>>>();
    k_parent_proj<<<BB / 64, 256>>>(out + OFF_PL, pw_proj, pb_proj, out + OFF_PP);

    // split-K child fc: 512+ working blocks
    k_tfc<<<dim3(BB / 128, EE, 8), 256, FC_SMEM>>>(x);
    k_fcred<<<dim3(BB / 8, 2), 256>>>(cb_fc0, cb_fc1, out);

    // child proj
    k_tproj<<<dim3(BB / 128, EE, 16), 256, PROJ_SMEM>>>(cb_pr0, cb_pr1, out);
}

// round 9
// speedup vs baseline: 2.4012x; 1.0066x over previous
#include <cuda_runtime.h>
#include <cuda_bf16.h>
#include <cstdint>

#define BB 8192
#define DD 2048
#define EE 16
#define PP 1024
#define CC0 64
#define CC1 128
#define LN_EPS 1e-5f

#define OFF_PL  0
#define OFF_CL0 (BB*EE)
#define OFF_CL1 (OFF_CL0 + BB*CC0)
#define OFF_PP  (OFF_CL1 + BB*CC1)
#define OFF_CP0 (OFF_PP + BB*PP)
#define OFF_CP1 (OFF_CP0 + BB*PP)

typedef unsigned long long u64t;

// ------------------------- scratch globals -------------------------
__device__ int g_class[BB];
__device__ int g_cnt[EE];
__device__ int g_cur[EE];
__device__ int g_off[EE + 1];
__device__ int g_sidx[BB];

__device__ __nv_bfloat16 g_wfc0h[EE * CC0 * DD], g_wfc0l[EE * CC0 * DD];
__device__ __nv_bfloat16 g_wfc1h[EE * CC1 * DD], g_wfc1l[EE * CC1 * DD];
__device__ __nv_bfloat16 g_wp0h[EE * PP * CC0], g_wp0l[EE * PP * CC0];
__device__ __nv_bfloat16 g_wp1h[EE * PP * CC1], g_wp1l[EE * PP * CC1];
__device__ __nv_bfloat16 g_h0h[BB * CC0], g_h0l[BB * CC0];
__device__ __nv_bfloat16 g_h1h[BB * CC1], g_h1l[BB * CC1];

// split-K partials (fp32)
__device__ float g_pt0[4 * BB * CC0];
__device__ float g_pt1[4 * BB * CC1];

struct alignas(8) bh4 { __nv_bfloat16 x, y, z, w; };

// ------------------------- asm helpers (sm_80+ generic) ---------------
__device__ __forceinline__ uint32_t smem_u32(const void* p) {
    uint32_t a;
    asm("{ .reg .u64 t; cvta.to.shared.u64 t, %1; cvt.u32.u64 %0, t; }"
        : "=r"(a) : "l"(p));
    return a;
}
#define CPA(dst, src) \
    asm volatile("cp.async.cg.shared.global [%0], [%1], 16;" :: "r"(dst), "l"(src) : "memory")
#define CPA_COMMIT() asm volatile("cp.async.commit_group;" ::: "memory")
#define CPA_WAIT(n)  asm volatile("cp.async.wait_group %0;" :: "n"(n) : "memory")
#define LDM4(r, addr) \
    asm volatile("ldmatrix.sync.aligned.m8n8.x4.shared.b16 {%0,%1,%2,%3}, [%4];" \
                 : "=r"((r)[0]), "=r"((r)[1]), "=r"((r)[2]), "=r"((r)[3]) : "r"(addr))

__device__ __forceinline__ void mma_bf16(float* c, const uint32_t* a,
                                         uint32_t b0, uint32_t b1) {
    asm volatile(
        "mma.sync.aligned.m16n8k16.row.col.f32.bf16.bf16.f32 "
        "{%0,%1,%2,%3}, {%4,%5,%6,%7}, {%8,%9}, {%0,%1,%2,%3};"
        : "+f"(c[0]), "+f"(c[1]), "+f"(c[2]), "+f"(c[3])
        : "r"(a[0]), "r"(a[1]), "r"(a[2]), "r"(a[3]), "r"(b0), "r"(b1));
}

// Two 16-row subtiles per warp sharing the same B fragments (halves LDS/FMA).
// NG groups of 16 cols. Swizzled [row][64] bf16 tiles (128B rows).
template <int NG>
__device__ __forceinline__ void mma_chunk2(uint32_t AH, uint32_t AL,
                                           uint32_t BH, uint32_t BL,
                                           int m0, int lane,
                                           float* accA, float* accB) {
    const int arow0 = m0 + (lane & 15);
    const uint32_t aoff0 = (uint32_t)arow0 * 128u;
    const uint32_t aoff1 = aoff0 + 16u * 128u;
    const uint32_t axr = (uint32_t)((arow0 & 7) << 4);  // same for arow0+16
    const uint32_t acb0 = (uint32_t)((lane >> 4) << 4);
    const int brl = ((lane >> 4) & 1) * 8 + (lane & 7);
    const uint32_t bcb0 = (uint32_t)(((lane >> 3) & 1) << 4);
    #pragma unroll
    for (int ks = 0; ks < 4; ks++) {
        uint32_t acb = ((uint32_t)(ks * 32) + acb0) ^ axr;
        uint32_t ah0[4], al0[4], ah1[4], al1[4];
        LDM4(ah0, AH + aoff0 + acb);
        LDM4(al0, AL + aoff0 + acb);
        LDM4(ah1, AH + aoff1 + acb);
        LDM4(al1, AL + aoff1 + acb);
        #pragma unroll
        for (int g = 0; g < NG; g++) {
            int brow = g * 16 + brl;
            uint32_t boff = (uint32_t)brow * 128u
                            + (((uint32_t)(ks * 32) + bcb0) ^ (uint32_t)((brow & 7) << 4));
            uint32_t bh[4], bl[4];
            LDM4(bh, BH + boff);
            LDM4(bl, BL + boff);
            float* c0 = accA + g * 8;
            float* c1 = accA + g * 8 + 4;
            mma_bf16(c0, ah0, bh[0], bh[1]);
            mma_bf16(c0, ah0, bl[0], bl[1]);
            mma_bf16(c0, al0, bh[0], bh[1]);
            mma_bf16(c1, ah0, bh[2], bh[3]);
            mma_bf16(c1, ah0, bl[2], bl[3]);
            mma_bf16(c1, al0, bh[2], bh[3]);
            float* d0 = accB + g * 8;
            float* d1 = accB + g * 8 + 4;
            mma_bf16(d0, ah1, bh[0], bh[1]);
            mma_bf16(d0, ah1, bl[0], bl[1]);
            mma_bf16(d0, al1, bh[0], bh[1]);
            mma_bf16(d1, ah1, bh[2], bh[3]);
            mma_bf16(d1, ah1, bl[2], bl[3]);
            mma_bf16(d1, al1, bh[2], bh[3]);
        }
    }
}

__device__ __forceinline__ void split8(const float* v, uint32_t* H, uint32_t* L) {
    #pragma unroll
    for (int i = 0; i < 4; i++) {
        __nv_bfloat16 h0 = __float2bfloat16(v[2 * i]);
        __nv_bfloat16 h1 = __float2bfloat16(v[2 * i + 1]);
        float l0 = v[2 * i] - __bfloat162float(h0);
        float l1 = v[2 * i + 1] - __bfloat162float(h1);
        H[i] = ((uint32_t)__bfloat16_as_ushort(h1) << 16) | __bfloat16_as_ushort(h0);
        __nv_bfloat16 g0 = __float2bfloat16(l0);
        __nv_bfloat16 g1 = __float2bfloat16(l1);
        L[i] = ((uint32_t)__bfloat16_as_ushort(g1) << 16) | __bfloat16_as_ushort(g0);
    }
}

// ------------------------- small kernels -------------------------
__global__ void k_init() {
    int t = threadIdx.x;
    if (t < EE) { g_cnt[t] = 0; g_cur[t] = 0; }
}

// one launch: all 4 weight arrays -> bf16 hi/lo
__global__ void k_cvtw(const float* __restrict__ s0, const float* __restrict__ s1,
                       const float* __restrict__ s2, const float* __restrict__ s3) {
    const int sel = blockIdx.y;
    const float* src;
    __nv_bfloat16 *dh, *dl;
    int n;
    switch (sel) {
        case 0: src = s0; dh = g_wfc0h; dl = g_wfc0l; n = EE * CC0 * DD; break;
        case 1: src = s1; dh = g_wfc1h; dl = g_wfc1l; n = EE * CC1 * DD; break;
        case 2: src = s2; dh = g_wp0h;  dl = g_wp0l;  n = EE * PP * CC0; break;
        default: src = s3; dh = g_wp1h; dl = g_wp1l;  n = EE * PP * CC1; break;
    }
    int i4 = blockIdx.x * 256 + threadIdx.x;
    if (i4 * 4 < n) {
        float4 v = ((const float4*)src)[i4];
        float vv[4] = {v.x, v.y, v.z, v.w};
        uint32_t H[2], L[2];
        #pragma unroll
        for (int i = 0; i < 2; i++) {
            __nv_bfloat16 h0 = __float2bfloat16(vv[2 * i]);
            __nv_bfloat16 h1 = __float2bfloat16(vv[2 * i + 1]);
            float l0 = vv[2 * i] - __bfloat162float(h0);
            float l1 = vv[2 * i + 1] - __bfloat162float(h1);
            H[i] = ((uint32_t)__bfloat16_as_ushort(h1) << 16) | __bfloat16_as_ushort(h0);
            __nv_bfloat16 g0 = __float2bfloat16(l0);
            __nv_bfloat16 g1 = __float2bfloat16(l1);
            L[i] = ((uint32_t)__bfloat16_as_ushort(g1) << 16) | __bfloat16_as_ushort(g0);
        }
        ((uint2*)dh)[i4] = make_uint2(H[0], H[1]);
        ((uint2*)dl)[i4] = make_uint2(L[0], L[1]);
    }
}

__global__ void k_scan() {
    if (threadIdx.x == 0) {
        int o = 0;
        for (int e = 0; e < EE; e++) { g_off[e] = o; o += g_cnt[e]; }
        g_off[EE] = o;
    }
}

__global__ void k_scatter() {
    int b = blockIdx.x * 256 + threadIdx.x;
    if (b < BB) {
        int e = g_class[b];
        int pos = g_off[e] + atomicAdd(&g_cur[e], 1);
        g_sidx[pos] = b;
    }
}

// ------------------------- parent FC (exact fp32) -------------------------
__global__ __launch_bounds__(128) void k_parent_fc(
    const float* __restrict__ x, const float* __restrict__ w,
    const float* __restrict__ bias, float* __restrict__ out_pl)
{
    __shared__ __align__(16) float xs[32][68];
    __shared__ __align__(16) float ws[32][20];
    __shared__ float spart[4][64][17];

    const int t = threadIdx.x;
    const int rowg = t & 7;
    const int eg = (t >> 3) & 3;
    const int kg = t >> 5;
    const int brow = blockIdx.x * 64;

    float acc[8][4];
    #pragma unroll
    for (int i = 0; i < 8; i++)
        #pragma unroll
        for (int j = 0; j < 4; j++) acc[i][j] = 0.f;

    for (int kt = 0; kt < DD / 32; kt++) {
        float4 rx[4];
        float4 rw;
        #pragma unroll
        for (int i = 0; i < 4; i++) {
            int s = t + i * 128;
            int row = s >> 3, kq = s & 7;
            rx[i] = *(const float4*)&x[(size_t)(brow + row) * DD + kt * 32 + kq * 4];
        }
        {
            int e2 = t >> 3, kq = t & 7;
            rw = *(const float4*)&w[(size_t)e2 * DD + kt * 32 + kq * 4];
        }
        __syncthreads();
        #pragma unroll
        for (int i = 0; i < 4; i++) {
            int s = t + i * 128;
            int row = s >> 3, kq = s & 7;
            xs[kq * 4 + 0][row] = rx[i].x;
            xs[kq * 4 + 1][row] = rx[i].y;
            xs[kq * 4 + 2][row] = rx[i].z;
            xs[kq * 4 + 3][row] = rx[i].w;
        }
        {
            int e2 = t >> 3, kq = t & 7;
            ws[kq * 4 + 0][e2] = rw.x;
            ws[kq * 4 + 1][e2] = rw.y;
            ws[kq * 4 + 2][e2] = rw.z;
            ws[kq * 4 + 3][e2] = rw.w;
        }
        __syncthreads();
        #pragma unroll
        for (int kk2 = 0; kk2 < 8; kk2++) {
            int kk = kg * 8 + kk2;
            float4 a0 = *(const float4*)&xs[kk][rowg * 4];
            float4 a1 = *(const float4*)&xs[kk][32 + rowg * 4];
            float4 bq = *(const float4*)&ws[kk][eg * 4];
            float av[8] = {a0.x, a0.y, a0.z, a0.w, a1.x, a1.y, a1.z, a1.w};
            float bv[4] = {bq.x, bq.y, bq.z, bq.w};
            #pragma unroll
            for (int i = 0; i < 8; i++)
                #pragma unroll
                for (int j = 0; j < 4; j++) acc[i][j] += av[i] * bv[j];
        }
        __syncthreads();
    }

    #pragma unroll
    for (int i = 0; i < 8; i++) {
        int r = (i < 4) ? (rowg * 4 + i) : (32 + rowg * 4 + (i - 4));
        #pragma unroll
        for (int j = 0; j < 4; j++) spart[kg][r][eg * 4 + j] = acc[i][j];
    }
    __syncthreads();

    if (t < 64) {
        int r = t;
        int b = brow + r;
        float z[16];
        float mu = 0.f;
        #pragma unroll
        for (int e2 = 0; e2 < 16; e2++) {
            float v = spart[0][r][e2] + spart[1][r][e2] + spart[2][r][e2] + spart[3][r][e2]
                      + bias[e2];
            z[e2] = v;
            mu += v;
        }
        mu *= (1.f / 16.f);
        float var = 0.f;
        #pragma unroll
        for (int e2 = 0; e2 < 16; e2++) { float d = z[e2] - mu; var += d * d; }
        var *= (1.f / 16.f);
        float rs = rsqrtf(var + LN_EPS);

        float best = z[0];
        int cls = 0;
        #pragma unroll
        for (int e2 = 1; e2 < 16; e2++)
            if (z[e2] > best) { best = z[e2]; cls = e2; }

        #pragma unroll
        for (int q = 0; q < 4; q++) {
            float4 o = make_float4((z[q * 4 + 0] - mu) * rs, (z[q * 4 + 1] - mu) * rs,
                                   (z[q * 4 + 2] - mu) * rs, (z[q * 4 + 3] - mu) * rs);
            *(float4*)&out_pl[(size_t)b * 16 + q * 4] = o;
        }
        g_class[b] = cls;
        atomicAdd(&g_cnt[cls], 1);
    }
}

// ------------------------- parent proj -------------------------
__global__ __launch_bounds__(256) void k_parent_proj(
    const float* __restrict__ pl, const float* __restrict__ w,
    const float* __restrict__ bias, float* __restrict__ out)
{
    __shared__ __align__(16) float spl[64][20];
    const int t = threadIdx.x;
    const int brow = blockIdx.x * 64;

    {
        int row = t >> 2, q = t & 3;
        float4 g = *(const float4*)&pl[(size_t)(brow + row) * 16 + q * 4];
        spl[row][q * 4 + 0] = g.x;
        spl[row][q * 4 + 1] = g.y;
        spl[row][q * 4 + 2] = g.z;
        spl[row][q * 4 + 3] = g.w;
    }
    __syncthreads();

    for (int pass = 0; pass < 2; pass++) {
        int p0 = pass * 512 + t * 2;
        float w0[16], w1[16];
        #pragma unroll
        for (int q = 0; q < 4; q++) {
            float4 a = *(const float4*)&w[(size_t)p0 * 16 + q * 4];
            w0[q * 4 + 0] = a.x; w0[q * 4 + 1] = a.y; w0[q * 4 + 2] = a.z; w0[q * 4 + 3] = a.w;
            float4 c = *(const float4*)&w[(size_t)(p0 + 1) * 16 + q * 4];
            w1[q * 4 + 0] = c.x; w1[q * 4 + 1] = c.y; w1[q * 4 + 2] = c.z; w1[q * 4 + 3] = c.w;
        }
        float b0 = bias[p0], b1 = bias[p0 + 1];

        for (int r = 0; r < 64; r++) {
            float a0 = b0, a1 = b1;
            #pragma unroll
            for (int q = 0; q < 4; q++) {
                float4 v = *(const float4*)&spl[r][q * 4];
                a0 += v.x * w0[q * 4 + 0] + v.y * w0[q * 4 + 1] + v.z * w0[q * 4 + 2] + v.w * w0[q * 4 + 3];
                a1 += v.x * w1[q * 4 + 0] + v.y * w1[q * 4 + 1] + v.z * w1[q * 4 + 2] + v.w * w1[q * 4 + 3];
            }
            float2 o = make_float2(a0, a1);
            *(float2*)&out[(size_t)(brow + r) * PP + p0] = o;
        }
    }
}

// ===========================================================================
// Child FC split-K GEMM (no epilogue): partials to g_pt*. In-kernel x split.
// grid (64, EE, 8): z>>2 = level, z&3 = ksplit (512 k each, 8 chunks of 64).
// smem/buffer: XF(fp32 32K) | AH 16K | AL 16K | BH BN*128 | BL BN*128, x2.
// ===========================================================================
#define FC_SMEM 196608

template <int BN>
__device__ __forceinline__ void tfc_impl(
    const float* __restrict__ x,
    const __nv_bfloat16* __restrict__ wh, const __nv_bfloat16* __restrict__ wl,
    float* __restrict__ part, int ks, char* sm, int* sidx)
{
    const int e = blockIdx.y;
    const int start = g_off[e] + blockIdx.x * 128;
    const int end = g_off[e + 1];
    if (start >= end) return;

    const int t = threadIdx.x;
    const int wid = t >> 5, lane = t & 31;
    const int wr = wid & 3, wc = wid >> 2;
    const uint32_t sb = smem_u32(sm);
    const int kbase = ks * 512;

    constexpr int XF = 0, AH0 = 32768, AL0 = 49152, BH0 = 65536, BL0 = 65536 + BN * 128;
    constexpr int BUF = 65536 + 2 * BN * 128;
    constexpr int NGW = BN / 32;

    if (t < 128) { int gi = start + t; sidx[t] = g_sidx[gi < end ? gi : end - 1]; }
    __syncthreads();

    auto issue = [&](int kt) {
        uint32_t base = sb + (uint32_t)((kt & 1) * BUF);
        // x fp32: 128 rows x 64 fp32 = 2048 16B chunks
        #pragma unroll
        for (int i = 0; i < 8; i++) {
            int d = t + i * 256;
            int row = d >> 4, ch2 = d & 15;
            CPA(base + XF + (uint32_t)(row * 256 + ch2 * 16),
                x + (size_t)sidx[row] * DD + kbase + kt * 64 + ch2 * 4);
        }
        // weights bf16 hi/lo: BN rows x 128B
        #pragma unroll
        for (int i = 0; i < BN / 32; i++) {
            int d = t + i * 256;
            int row = d >> 3, ch = d & 7;
            uint32_t off = (uint32_t)(row * 128 + ((ch * 16) ^ ((row & 7) << 4)));
            size_t g = ((size_t)e * BN + row) * DD + kbase + kt * 64 + ch * 8;
            CPA(base + BH0 + off, wh + g);
            CPA(base + BL0 + off, wl + g);
        }
        CPA_COMMIT();
    };

    auto convert = [&](int kt) {
        char* base = sm + (kt & 1) * BUF;
        #pragma unroll
        for (int i = 0; i < 4; i++) {
            int c = t + i * 256;
            int row = c >> 3, ch8 = c & 7;
            float4 v0 = *(const float4*)(base + XF + row * 256 + ch8 * 32);
            float4 v1 = *(const float4*)(base + XF + row * 256 + ch8 * 32 + 16);
            float vv[8] = {v0.x, v0.y, v0.z, v0.w, v1.x, v1.y, v1.z, v1.w};
            uint32_t H[4], L[4];
            split8(vv, H, L);
            uint32_t off = (uint32_t)(row * 128 + ((ch8 * 16) ^ ((row & 7) << 4)));
            *(uint4*)(base + AH0 + off) = make_uint4(H[0], H[1], H[2], H[3]);
            *(uint4*)(base + AL0 + off) = make_uint4(L[0], L[1], L[2], L[3]);
        }
    };

    float accA[NGW * 8], accB[NGW * 8];
    #pragma unroll
    for (int i = 0; i < NGW * 8; i++) { accA[i] = 0.f; accB[i] = 0.f; }

    issue(0);
    const int NKT = 8;
    for (int kt = 0; kt < NKT; kt++) {
        CPA_WAIT(0);
        __syncthreads();
        convert(kt);
        __syncthreads();
        if (kt + 1 < NKT) issue(kt + 1);
        uint32_t base = sb + (uint32_t)((kt & 1) * BUF);
        mma_chunk2<NGW>(base + AH0, base + AL0,
                        base + BH0 + (uint32_t)(wc * (BN / 2) * 128),
                        base + BL0 + (uint32_t)(wc * (BN / 2) * 128),
                        wr * 32, lane, accA, accB);
    }

    // store fp32 partials (pure GEMM, bias/LN in reduce kernel)
    const int rA0 = wr * 32 + (lane >> 2);
    #pragma unroll
    for (int g = 0; g < NGW; g++) {
        #pragma unroll
        for (int half = 0; half < 2; half++) {
            int col = wc * (BN / 2) + (g * 2 + half) * 8 + (lane & 3) * 2;
            float* pa = accA + g * 8 + half * 4;
            float* pb = accB + g * 8 + half * 4;
            int rows[4] = {rA0, rA0 + 8, rA0 + 16, rA0 + 24};
            float* vals[4] = {pa, pa + 2, pb, pb + 2};
            #pragma unroll
            for (int rv = 0; rv < 4; rv++) {
                int p = start + rows[rv];
                if (p < end)
                    *(float2*)&part[(size_t)ks * BB * BN + (size_t)p * BN + col] =
                        make_float2(vals[rv][0], vals[rv][1]);
            }
        }
    }
}

__global__ __launch_bounds__(256, 1) void k_tfc(const float* __restrict__ x)
{
    extern __shared__ char smx[];
    __shared__ int sidx[128];
    const int level = blockIdx.z >> 2;
    const int ks = blockIdx.z & 3;
    if (level == 0)
        tfc_impl<CC0>(x, g_wfc0h, g_wfc0l, g_pt0, ks, smx, sidx);
    else
        tfc_impl<CC1>(x, g_wfc1h, g_wfc1l, g_pt1, ks, smx, sidx);
}

// ===========================================================================
// FC reduce: sum 4 partials + bias + LN + write cl + h hi/lo. 1 warp per row.
// ===========================================================================
template <int BN>
__device__ __forceinline__ void fcred_impl(
    const float* __restrict__ part, const float* __restrict__ bias,
    float* __restrict__ out, __nv_bfloat16* __restrict__ hh,
    __nv_bfloat16* __restrict__ hl)
{
    const int p = blockIdx.x * 8 + (threadIdx.x >> 5);
    const int lane = threadIdx.x & 31;
    const int b = g_sidx[p];
    const int e = g_class[b];
    constexpr int NC = BN / 32;

    float v[NC];
    float s = 0.f, q = 0.f;
    #pragma unroll
    for (int i = 0; i < NC; i++) {
        int col = lane + i * 32;
        size_t idx = (size_t)p * BN + col;
        float a = part[idx] + part[(size_t)BB * BN + idx]
                + part[2 * (size_t)BB * BN + idx] + part[3 * (size_t)BB * BN + idx]
                + bias[e * BN + col];
        v[i] = a;
        s += a;
        q += a * a;
    }
    #pragma unroll
    for (int o = 16; o; o >>= 1) {
        s += __shfl_xor_sync(~0u, s, o);
        q += __shfl_xor_sync(~0u, q, o);
    }
    float mu = s * (1.f / BN);
    float rs = rsqrtf(q * (1.f / BN) - mu * mu + LN_EPS);
    #pragma unroll
    for (int i = 0; i < NC; i++) {
        int col = lane + i * 32;
        float o = (v[i] - mu) * rs;
        out[(size_t)b * BN + col] = o;
        __nv_bfloat16 h = __float2bfloat16(o);
        __nv_bfloat16 l = __float2bfloat16(o - __bfloat162float(h));
        hh[(size_t)b * BN + col] = h;
        hl[(size_t)b * BN + col] = l;
    }
}

__global__ __launch_bounds__(256) void k_fcred(
    const float* __restrict__ b0, const float* __restrict__ b1,
    float* __restrict__ out)
{
    if (blockIdx.y == 0)
        fcred_impl<CC0>(g_pt0, b0, out + OFF_CL0, g_h0h, g_h0l);
    else
        fcred_impl<CC1>(g_pt1, b1, out + OFF_CL1, g_h1h, g_h1l);
}

// ===========================================================================
// Child proj: M 128 x N 128 per block, K=CK. 4x2 warp grid, shared-B mma.
// ===========================================================================
#define PROJ_SMEM 131072

template <int CK>
__device__ __forceinline__ void tproj_impl(
    const __nv_bfloat16* __restrict__ ah, const __nv_bfloat16* __restrict__ al,
    const __nv_bfloat16* __restrict__ wh, const __nv_bfloat16* __restrict__ wl,
    const float* __restrict__ bias, float* __restrict__ out,
    int pt, char* sm, int* sidx)
{
    const int e = blockIdx.y;
    const int start = g_off[e] + blockIdx.x * 128;
    const int end = g_off[e + 1];
    if (start >= end) return;

    constexpr int NKC = CK / 64;
    const int t = threadIdx.x;
    const int wid = t >> 5, lane = t & 31;
    const int wr = wid & 3, wc = wid >> 2;
    const uint32_t sb = smem_u32(sm);
    constexpr uint32_t MSZ = (uint32_t)NKC * 16384u;

    if (t < 128) { int gi = start + t; sidx[t] = g_sidx[gi < end ? gi : end - 1]; }
    __syncthreads();

    #pragma unroll
    for (int kc = 0; kc < NKC; kc++) {
        #pragma unroll
        for (int i = 0; i < 4; i++) {
            int s = t + i * 256;
            int row = s >> 3, ch = s & 7;
            uint32_t off = (uint32_t)(kc * 16384 + row * 128 + ((ch * 16) ^ ((row & 7) << 4)));
            size_t ga = (size_t)sidx[row] * CK + kc * 64 + ch * 8;
            CPA(sb + off, ah + ga);
            CPA(sb + MSZ + off, al + ga);
            size_t gb = ((size_t)(e * PP + pt * 128 + row)) * CK + kc * 64 + ch * 8;
            CPA(sb + 2 * MSZ + off, wh + gb);
            CPA(sb + 3 * MSZ + off, wl + gb);
        }
    }
    CPA_COMMIT();
    CPA_WAIT(0);
    __syncthreads();

    float accA[32], accB[32];
    #pragma unroll
    for (int i = 0; i < 32; i++) { accA[i] = 0.f; accB[i] = 0.f; }

    #pragma unroll
    for (int kc = 0; kc < NKC; kc++) {
        uint32_t base = sb + (uint32_t)(kc * 16384);
        mma_chunk2<4>(base, base + MSZ,
                      base + 2 * MSZ + (uint32_t)(wc * 64 * 128),
                      base + 3 * MSZ + (uint32_t)(wc * 64 * 128),
                      wr * 32, lane, accA, accB);
    }

    const int rA0 = wr * 32 + (lane >> 2);
    #pragma unroll
    for (int g = 0; g < 4; g++) {
        #pragma unroll
        for (int half = 0; half < 2; half++) {
            int pcol = pt * 128 + wc * 64 + (g * 2 + half) * 8 + (lane & 3) * 2;
            float bv0 = bias[(size_t)e * PP + pcol];
            float bv1 = bias[(size_t)e * PP + pcol + 1];
            float* pa = accA + g * 8 + half * 4;
            float* pb = accB + g * 8 + half * 4;
            int rows[4] = {rA0, rA0 + 8, rA0 + 16, rA0 + 24};
            float* vals[4] = {pa, pa + 2, pb, pb + 2};
            #pragma unroll
            for (int rv = 0; rv < 4; rv++) {
                if (start + rows[rv] < end) {
                    int b = sidx[rows[rv]];
                    *(float2*)&out[(size_t)b * PP + pcol] =
                        make_float2(vals[rv][0] + bv0, vals[rv][1] + bv1);
                }
            }
        }
    }
}

__global__ __launch_bounds__(256, 1) void k_tproj(
    const float* __restrict__ bpr0, const float* __restrict__ bpr1,
    float* __restrict__ out)
{
    extern __shared__ char smx[];
    __shared__ int sidx[128];
    const int level = blockIdx.z >> 3;
    const int pt = blockIdx.z & 7;
    if (level == 0)
        tproj_impl<CC0>(g_h0h, g_h0l, g_wp0h, g_wp0l, bpr0, out + OFF_CP0, pt, smx, sidx);
    else
        tproj_impl<CC1>(g_h1h, g_h1l, g_wp1h, g_wp1l, bpr1, out + OFF_CP1, pt, smx, sidx);
}

// ---------------------------------------------------------------------------

extern "C" void kernel_launch(void* const* d_in, const int* in_sizes, int n_in,
                              void* d_out, int out_size) {
    const float* x       = (const float*)d_in[0];
    const float* pw_fc   = (const float*)d_in[1];
    const float* pb_fc   = (const float*)d_in[2];
    const float* pw_proj = (const float*)d_in[3];
    const float* pb_proj = (const float*)d_in[4];
    const float* cw_fc0  = (const float*)d_in[5];
    const float* cb_fc0  = (const float*)d_in[6];
    const float* cw_pr0  = (const float*)d_in[7];
    const float* cb_pr0  = (const float*)d_in[8];
    const float* cw_fc1  = (const float*)d_in[9];
    const float* cb_fc1  = (const float*)d_in[10];
    const float* cw_pr1  = (const float*)d_in[11];
    const float* cb_pr1  = (const float*)d_in[12];
    float* out = (float*)d_out;

    cudaFuncSetAttribute(k_tfc, cudaFuncAttributeMaxDynamicSharedMemorySize, FC_SMEM);
    cudaFuncSetAttribute(k_tproj, cudaFuncAttributeMaxDynamicSharedMemorySize, PROJ_SMEM);

    k_init<<<1, 32>>>();
    k_cvtw<<<dim3(4096, 4), 256>>>(cw_fc0, cw_fc1, cw_pr0, cw_pr1);

    k_parent_fc<<<BB / 64, 128>>>(x, pw_fc, pb_fc, out + OFF_PL);
    k_scan<<<1, 32>>>();
    k_scatter<<<BB / 256, 256>>>();
    k_parent_proj<<<BB / 64, 256>>>(out + OFF_PL, pw_proj, pb_proj, out + OFF_PP);

    // split-K child fc: 512+ working blocks
    k_tfc<<<dim3(BB / 128, EE, 8), 256, FC_SMEM>>>(x);
    k_fcred<<<dim3(BB / 8, 2), 256>>>(cb_fc0, cb_fc1, out);

    // child proj
    k_tproj<<<dim3(BB / 128, EE, 16), 256, PROJ_SMEM>>>(cb_pr0, cb_pr1, out);
}

// round 10
// speedup vs baseline: 2.4876x; 1.0360x over previous
#include <cuda_runtime.h>
#include <cuda_bf16.h>
#include <cstdint>

#define BB 8192
#define DD 2048
#define EE 16
#define PP 1024
#define CC0 64
#define CC1 128
#define LN_EPS 1e-5f

#define OFF_PL  0
#define OFF_CL0 (BB*EE)
#define OFF_CL1 (OFF_CL0 + BB*CC0)
#define OFF_PP  (OFF_CL1 + BB*CC1)
#define OFF_CP0 (OFF_PP + BB*PP)
#define OFF_CP1 (OFF_CP0 + BB*PP)

typedef unsigned long long u64t;

// ------------------------- scratch globals -------------------------
__device__ int g_class[BB];
__device__ int g_cnt[EE];
__device__ int g_cur[EE];
__device__ int g_off[EE + 1];
__device__ int g_sidx[BB];

__device__ __nv_bfloat16 g_xh[BB * DD], g_xl[BB * DD];
__device__ __nv_bfloat16 g_wfc0h[EE * CC0 * DD], g_wfc0l[EE * CC0 * DD];
__device__ __nv_bfloat16 g_wfc1h[EE * CC1 * DD], g_wfc1l[EE * CC1 * DD];
__device__ __nv_bfloat16 g_wp0h[EE * PP * CC0], g_wp0l[EE * PP * CC0];
__device__ __nv_bfloat16 g_wp1h[EE * PP * CC1], g_wp1l[EE * PP * CC1];
__device__ __nv_bfloat16 g_h0h[BB * CC0], g_h0l[BB * CC0];
__device__ __nv_bfloat16 g_h1h[BB * CC1], g_h1l[BB * CC1];

__device__ float g_pt0[4 * BB * CC0];
__device__ float g_pt1[4 * BB * CC1];

// ------------------------- asm helpers (sm_80+ generic) ---------------
__device__ __forceinline__ uint32_t smem_u32(const void* p) {
    uint32_t a;
    asm("{ .reg .u64 t; cvta.to.shared.u64 t, %1; cvt.u32.u64 %0, t; }"
        : "=r"(a) : "l"(p));
    return a;
}
#define CPA(dst, src) \
    asm volatile("cp.async.cg.shared.global [%0], [%1], 16;" :: "r"(dst), "l"(src) : "memory")
#define CPA_COMMIT() asm volatile("cp.async.commit_group;" ::: "memory")
#define CPA_WAIT(n)  asm volatile("cp.async.wait_group %0;" :: "n"(n) : "memory")
#define LDM4(r, addr) \
    asm volatile("ldmatrix.sync.aligned.m8n8.x4.shared.b16 {%0,%1,%2,%3}, [%4];" \
                 : "=r"((r)[0]), "=r"((r)[1]), "=r"((r)[2]), "=r"((r)[3]) : "r"(addr))

__device__ __forceinline__ void mma_bf16(float* c, const uint32_t* a,
                                         uint32_t b0, uint32_t b1) {
    asm volatile(
        "mma.sync.aligned.m16n8k16.row.col.f32.bf16.bf16.f32 "
        "{%0,%1,%2,%3}, {%4,%5,%6,%7}, {%8,%9}, {%0,%1,%2,%3};"
        : "+f"(c[0]), "+f"(c[1]), "+f"(c[2]), "+f"(c[3])
        : "r"(a[0]), "r"(a[1]), "r"(a[2]), "r"(a[3]), "r"(b0), "r"(b1));
}

// Two 16-row subtiles per warp sharing B fragments. NG groups of 16 cols.
// Swizzled [row][64] bf16 tiles (128B rows).
template <int NG>
__device__ __forceinline__ void mma_chunk2(uint32_t AH, uint32_t AL,
                                           uint32_t BH, uint32_t BL,
                                           int m0, int lane,
                                           float* accA, float* accB) {
    const int arow0 = m0 + (lane & 15);
    const uint32_t aoff0 = (uint32_t)arow0 * 128u;
    const uint32_t aoff1 = aoff0 + 16u * 128u;
    const uint32_t axr = (uint32_t)((arow0 & 7) << 4);
    const uint32_t acb0 = (uint32_t)((lane >> 4) << 4);
    const int brl = ((lane >> 4) & 1) * 8 + (lane & 7);
    const uint32_t bcb0 = (uint32_t)(((lane >> 3) & 1) << 4);
    #pragma unroll
    for (int ks = 0; ks < 4; ks++) {
        uint32_t acb = ((uint32_t)(ks * 32) + acb0) ^ axr;
        uint32_t ah0[4], al0[4], ah1[4], al1[4];
        LDM4(ah0, AH + aoff0 + acb);
        LDM4(al0, AL + aoff0 + acb);
        LDM4(ah1, AH + aoff1 + acb);
        LDM4(al1, AL + aoff1 + acb);
        #pragma unroll
        for (int g = 0; g < NG; g++) {
            int brow = g * 16 + brl;
            uint32_t boff = (uint32_t)brow * 128u
                            + (((uint32_t)(ks * 32) + bcb0) ^ (uint32_t)((brow & 7) << 4));
            uint32_t bh[4], bl[4];
            LDM4(bh, BH + boff);
            LDM4(bl, BL + boff);
            float* c0 = accA + g * 8;
            float* c1 = accA + g * 8 + 4;
            mma_bf16(c0, ah0, bh[0], bh[1]);
            mma_bf16(c0, ah0, bl[0], bl[1]);
            mma_bf16(c0, al0, bh[0], bh[1]);
            mma_bf16(c1, ah0, bh[2], bh[3]);
            mma_bf16(c1, ah0, bl[2], bl[3]);
            mma_bf16(c1, al0, bh[2], bh[3]);
            float* d0 = accB + g * 8;
            float* d1 = accB + g * 8 + 4;
            mma_bf16(d0, ah1, bh[0], bh[1]);
            mma_bf16(d0, ah1, bl[0], bl[1]);
            mma_bf16(d0, al1, bh[0], bh[1]);
            mma_bf16(d1, ah1, bh[2], bh[3]);
            mma_bf16(d1, ah1, bl[2], bl[3]);
            mma_bf16(d1, al1, bh[2], bh[3]);
        }
    }
}

// ------------------------- cvt kernels -------------------------
__device__ __forceinline__ void cvt4(const float4 v, uint2& H, uint2& L) {
    float vv[4] = {v.x, v.y, v.z, v.w};
    uint32_t h[2], l[2];
    #pragma unroll
    for (int i = 0; i < 2; i++) {
        __nv_bfloat16 h0 = __float2bfloat16(vv[2 * i]);
        __nv_bfloat16 h1 = __float2bfloat16(vv[2 * i + 1]);
        float l0 = vv[2 * i] - __bfloat162float(h0);
        float l1 = vv[2 * i + 1] - __bfloat162float(h1);
        h[i] = ((uint32_t)__bfloat16_as_ushort(h1) << 16) | __bfloat16_as_ushort(h0);
        __nv_bfloat16 g0 = __float2bfloat16(l0);
        __nv_bfloat16 g1 = __float2bfloat16(l1);
        l[i] = ((uint32_t)__bfloat16_as_ushort(g1) << 16) | __bfloat16_as_ushort(g0);
    }
    H = make_uint2(h[0], h[1]);
    L = make_uint2(l[0], l[1]);
}

// x -> hi/lo ; also init counters (block 0)
__global__ void k_cvtx(const float* __restrict__ src) {
    if (blockIdx.x == 0 && threadIdx.x < EE) {
        g_cnt[threadIdx.x] = 0;
        g_cur[threadIdx.x] = 0;
    }
    int i4 = blockIdx.x * 256 + threadIdx.x;
    if (i4 * 4 < BB * DD) {
        uint2 H, L;
        cvt4(((const float4*)src)[i4], H, L);
        ((uint2*)g_xh)[i4] = H;
        ((uint2*)g_xl)[i4] = L;
    }
}

__global__ void k_cvtw(const float* __restrict__ s0, const float* __restrict__ s1,
                       const float* __restrict__ s2, const float* __restrict__ s3) {
    const int sel = blockIdx.y;
    const float* src;
    __nv_bfloat16 *dh, *dl;
    int n;
    switch (sel) {
        case 0: src = s0; dh = g_wfc0h; dl = g_wfc0l; n = EE * CC0 * DD; break;
        case 1: src = s1; dh = g_wfc1h; dl = g_wfc1l; n = EE * CC1 * DD; break;
        case 2: src = s2; dh = g_wp0h;  dl = g_wp0l;  n = EE * PP * CC0; break;
        default: src = s3; dh = g_wp1h; dl = g_wp1l;  n = EE * PP * CC1; break;
    }
    int i4 = blockIdx.x * 256 + threadIdx.x;
    if (i4 * 4 < n) {
        uint2 H, L;
        cvt4(((const float4*)src)[i4], H, L);
        ((uint2*)dh)[i4] = H;
        ((uint2*)dl)[i4] = L;
    }
}

// scan + scatter in one block
__global__ void k_scansc() {
    if (threadIdx.x == 0) {
        int o = 0;
        for (int e = 0; e < EE; e++) { g_off[e] = o; o += g_cnt[e]; }
        g_off[EE] = o;
    }
    __syncthreads();
    for (int b = threadIdx.x; b < BB; b += 1024) {
        int e = g_class[b];
        int pos = g_off[e] + atomicAdd(&g_cur[e], 1);
        g_sidx[pos] = b;
    }
}

// ------------------------- parent FC (exact fp32) -------------------------
__global__ __launch_bounds__(128) void k_parent_fc(
    const float* __restrict__ x, const float* __restrict__ w,
    const float* __restrict__ bias, float* __restrict__ out_pl)
{
    __shared__ __align__(16) float xs[32][68];
    __shared__ __align__(16) float ws[32][20];
    __shared__ float spart[4][64][17];

    const int t = threadIdx.x;
    const int rowg = t & 7;
    const int eg = (t >> 3) & 3;
    const int kg = t >> 5;
    const int brow = blockIdx.x * 64;

    float acc[8][4];
    #pragma unroll
    for (int i = 0; i < 8; i++)
        #pragma unroll
        for (int j = 0; j < 4; j++) acc[i][j] = 0.f;

    for (int kt = 0; kt < DD / 32; kt++) {
        float4 rx[4];
        float4 rw;
        #pragma unroll
        for (int i = 0; i < 4; i++) {
            int s = t + i * 128;
            int row = s >> 3, kq = s & 7;
            rx[i] = *(const float4*)&x[(size_t)(brow + row) * DD + kt * 32 + kq * 4];
        }
        {
            int e2 = t >> 3, kq = t & 7;
            rw = *(const float4*)&w[(size_t)e2 * DD + kt * 32 + kq * 4];
        }
        __syncthreads();
        #pragma unroll
        for (int i = 0; i < 4; i++) {
            int s = t + i * 128;
            int row = s >> 3, kq = s & 7;
            xs[kq * 4 + 0][row] = rx[i].x;
            xs[kq * 4 + 1][row] = rx[i].y;
            xs[kq * 4 + 2][row] = rx[i].z;
            xs[kq * 4 + 3][row] = rx[i].w;
        }
        {
            int e2 = t >> 3, kq = t & 7;
            ws[kq * 4 + 0][e2] = rw.x;
            ws[kq * 4 + 1][e2] = rw.y;
            ws[kq * 4 + 2][e2] = rw.z;
            ws[kq * 4 + 3][e2] = rw.w;
        }
        __syncthreads();
        #pragma unroll
        for (int kk2 = 0; kk2 < 8; kk2++) {
            int kk = kg * 8 + kk2;
            float4 a0 = *(const float4*)&xs[kk][rowg * 4];
            float4 a1 = *(const float4*)&xs[kk][32 + rowg * 4];
            float4 bq = *(const float4*)&ws[kk][eg * 4];
            float av[8] = {a0.x, a0.y, a0.z, a0.w, a1.x, a1.y, a1.z, a1.w};
            float bv[4] = {bq.x, bq.y, bq.z, bq.w};
            #pragma unroll
            for (int i = 0; i < 8; i++)
                #pragma unroll
                for (int j = 0; j < 4; j++) acc[i][j] += av[i] * bv[j];
        }
        __syncthreads();
    }

    #pragma unroll
    for (int i = 0; i < 8; i++) {
        int r = (i < 4) ? (rowg * 4 + i) : (32 + rowg * 4 + (i - 4));
        #pragma unroll
        for (int j = 0; j < 4; j++) spart[kg][r][eg * 4 + j] = acc[i][j];
    }
    __syncthreads();

    if (t < 64) {
        int r = t;
        int b = brow + r;
        float z[16];
        float mu = 0.f;
        #pragma unroll
        for (int e2 = 0; e2 < 16; e2++) {
            float v = spart[0][r][e2] + spart[1][r][e2] + spart[2][r][e2] + spart[3][r][e2]
                      + bias[e2];
            z[e2] = v;
            mu += v;
        }
        mu *= (1.f / 16.f);
        float var = 0.f;
        #pragma unroll
        for (int e2 = 0; e2 < 16; e2++) { float d = z[e2] - mu; var += d * d; }
        var *= (1.f / 16.f);
        float rs = rsqrtf(var + LN_EPS);

        float best = z[0];
        int cls = 0;
        #pragma unroll
        for (int e2 = 1; e2 < 16; e2++)
            if (z[e2] > best) { best = z[e2]; cls = e2; }

        #pragma unroll
        for (int q = 0; q < 4; q++) {
            float4 o = make_float4((z[q * 4 + 0] - mu) * rs, (z[q * 4 + 1] - mu) * rs,
                                   (z[q * 4 + 2] - mu) * rs, (z[q * 4 + 3] - mu) * rs);
            *(float4*)&out_pl[(size_t)b * 16 + q * 4] = o;
        }
        g_class[b] = cls;
        atomicAdd(&g_cnt[cls], 1);
    }
}

// ------------------------- parent proj -------------------------
__global__ __launch_bounds__(256) void k_parent_proj(
    const float* __restrict__ pl, const float* __restrict__ w,
    const float* __restrict__ bias, float* __restrict__ out)
{
    __shared__ __align__(16) float spl[64][20];
    const int t = threadIdx.x;
    const int brow = blockIdx.x * 64;

    {
        int row = t >> 2, q = t & 3;
        float4 g = *(const float4*)&pl[(size_t)(brow + row) * 16 + q * 4];
        spl[row][q * 4 + 0] = g.x;
        spl[row][q * 4 + 1] = g.y;
        spl[row][q * 4 + 2] = g.z;
        spl[row][q * 4 + 3] = g.w;
    }
    __syncthreads();

    for (int pass = 0; pass < 2; pass++) {
        int p0 = pass * 512 + t * 2;
        float w0[16], w1[16];
        #pragma unroll
        for (int q = 0; q < 4; q++) {
            float4 a = *(const float4*)&w[(size_t)p0 * 16 + q * 4];
            w0[q * 4 + 0] = a.x; w0[q * 4 + 1] = a.y; w0[q * 4 + 2] = a.z; w0[q * 4 + 3] = a.w;
            float4 c = *(const float4*)&w[(size_t)(p0 + 1) * 16 + q * 4];
            w1[q * 4 + 0] = c.x; w1[q * 4 + 1] = c.y; w1[q * 4 + 2] = c.z; w1[q * 4 + 3] = c.w;
        }
        float b0 = bias[p0], b1 = bias[p0 + 1];

        for (int r = 0; r < 64; r++) {
            float a0 = b0, a1 = b1;
            #pragma unroll
            for (int q = 0; q < 4; q++) {
                float4 v = *(const float4*)&spl[r][q * 4];
                a0 += v.x * w0[q * 4 + 0] + v.y * w0[q * 4 + 1] + v.z * w0[q * 4 + 2] + v.w * w0[q * 4 + 3];
                a1 += v.x * w1[q * 4 + 0] + v.y * w1[q * 4 + 1] + v.z * w1[q * 4 + 2] + v.w * w1[q * 4 + 3];
            }
            float2 o = make_float2(a0, a1);
            *(float2*)&out[(size_t)(brow + r) * PP + p0] = o;
        }
    }
}

// ===========================================================================
// Child FC split-K GEMM, pure bf16, double-buffered (single sync pair/chunk).
// grid (64, EE, 4): z = ksplit. Per buffer: AH 16K | AL 16K | BH BN*128 | BL.
// ===========================================================================
template <int BN>
__device__ __forceinline__ void tfc_impl(
    const __nv_bfloat16* __restrict__ xh, const __nv_bfloat16* __restrict__ xl,
    const __nv_bfloat16* __restrict__ wh, const __nv_bfloat16* __restrict__ wl,
    float* __restrict__ part, char* sm, int* sidx)
{
    const int e = blockIdx.y;
    const int start = g_off[e] + blockIdx.x * 128;
    const int end = g_off[e + 1];
    if (start >= end) return;
    const int ks = blockIdx.z;

    const int t = threadIdx.x;
    const int wid = t >> 5, lane = t & 31;
    const int wr = wid & 3, wc = wid >> 2;
    const uint32_t sb = smem_u32(sm);
    const int kbase = ks * 512;

    constexpr int AH0 = 0, AL0 = 16384, BH0 = 32768, BL0 = 32768 + BN * 128;
    constexpr int BUF = 32768 + 2 * BN * 128;
    constexpr int NGW = BN / 32;

    if (t < 128) { int gi = start + t; sidx[t] = g_sidx[gi < end ? gi : end - 1]; }
    __syncthreads();

    auto issue = [&](int kt) {
        uint32_t base = sb + (uint32_t)((kt & 1) * BUF);
        #pragma unroll
        for (int i = 0; i < 4; i++) {
            int d = t + i * 256;
            int row = d >> 3, ch = d & 7;
            uint32_t off = (uint32_t)(row * 128 + ((ch * 16) ^ ((row & 7) << 4)));
            size_t g = (size_t)sidx[row] * DD + kbase + kt * 64 + ch * 8;
            CPA(base + AH0 + off, xh + g);
            CPA(base + AL0 + off, xl + g);
        }
        #pragma unroll
        for (int i = 0; i < BN / 32; i++) {
            int d = t + i * 256;
            int row = d >> 3, ch = d & 7;
            uint32_t off = (uint32_t)(row * 128 + ((ch * 16) ^ ((row & 7) << 4)));
            size_t g = ((size_t)e * BN + row) * DD + kbase + kt * 64 + ch * 8;
            CPA(base + BH0 + off, wh + g);
            CPA(base + BL0 + off, wl + g);
        }
        CPA_COMMIT();
    };

    float accA[NGW * 8], accB[NGW * 8];
    #pragma unroll
    for (int i = 0; i < NGW * 8; i++) { accA[i] = 0.f; accB[i] = 0.f; }

    issue(0);
    const int NKT = 8;
    for (int kt = 0; kt < NKT; kt++) {
        if (kt + 1 < NKT) { issue(kt + 1); CPA_WAIT(1); }
        else              { CPA_WAIT(0); }
        __syncthreads();
        uint32_t base = sb + (uint32_t)((kt & 1) * BUF);
        mma_chunk2<NGW>(base + AH0, base + AL0,
                        base + BH0 + (uint32_t)(wc * (BN / 2) * 128),
                        base + BL0 + (uint32_t)(wc * (BN / 2) * 128),
                        wr * 32, lane, accA, accB);
        __syncthreads();
    }

    const int rA0 = wr * 32 + (lane >> 2);
    #pragma unroll
    for (int g = 0; g < NGW; g++) {
        #pragma unroll
        for (int half = 0; half < 2; half++) {
            int col = wc * (BN / 2) + (g * 2 + half) * 8 + (lane & 3) * 2;
            float* pa = accA + g * 8 + half * 4;
            float* pb = accB + g * 8 + half * 4;
            int rows[4] = {rA0, rA0 + 8, rA0 + 16, rA0 + 24};
            float* vals[4] = {pa, pa + 2, pb, pb + 2};
            #pragma unroll
            for (int rv = 0; rv < 4; rv++) {
                int p = start + rows[rv];
                if (p < end)
                    *(float2*)&part[(size_t)ks * BB * BN + (size_t)p * BN + col] =
                        make_float2(vals[rv][0], vals[rv][1]);
            }
        }
    }
}

#define FC_SMEM0 98304
#define FC_SMEM1 131072

__global__ __launch_bounds__(256, 1) void k_tfc0() {
    extern __shared__ char smx[];
    __shared__ int sidx[128];
    tfc_impl<CC0>(g_xh, g_xl, g_wfc0h, g_wfc0l, g_pt0, smx, sidx);
}
__global__ __launch_bounds__(256, 1) void k_tfc1() {
    extern __shared__ char smx[];
    __shared__ int sidx[128];
    tfc_impl<CC1>(g_xh, g_xl, g_wfc1h, g_wfc1l, g_pt1, smx, sidx);
}

// ===========================================================================
// FC reduce: sum 4 partials + bias + LN + write cl + h hi/lo. 1 warp per row.
// ===========================================================================
template <int BN>
__device__ __forceinline__ void fcred_impl(
    const float* __restrict__ part, const float* __restrict__ bias,
    float* __restrict__ out, __nv_bfloat16* __restrict__ hh,
    __nv_bfloat16* __restrict__ hl)
{
    const int p = blockIdx.x * 8 + (threadIdx.x >> 5);
    const int lane = threadIdx.x & 31;
    const int b = g_sidx[p];
    const int e = g_class[b];
    constexpr int NC = BN / 32;

    float v[NC];
    float s = 0.f, q = 0.f;
    #pragma unroll
    for (int i = 0; i < NC; i++) {
        int col = lane + i * 32;
        size_t idx = (size_t)p * BN + col;
        float a = part[idx] + part[(size_t)BB * BN + idx]
                + part[2 * (size_t)BB * BN + idx] + part[3 * (size_t)BB * BN + idx]
                + bias[e * BN + col];
        v[i] = a;
        s += a;
        q += a * a;
    }
    #pragma unroll
    for (int o = 16; o; o >>= 1) {
        s += __shfl_xor_sync(~0u, s, o);
        q += __shfl_xor_sync(~0u, q, o);
    }
    float mu = s * (1.f / BN);
    float rs = rsqrtf(q * (1.f / BN) - mu * mu + LN_EPS);
    #pragma unroll
    for (int i = 0; i < NC; i++) {
        int col = lane + i * 32;
        float o = (v[i] - mu) * rs;
        out[(size_t)b * BN + col] = o;
        __nv_bfloat16 h = __float2bfloat16(o);
        __nv_bfloat16 l = __float2bfloat16(o - __bfloat162float(h));
        hh[(size_t)b * BN + col] = h;
        hl[(size_t)b * BN + col] = l;
    }
}

__global__ __launch_bounds__(256) void k_fcred(
    const float* __restrict__ b0, const float* __restrict__ b1,
    float* __restrict__ out)
{
    if (blockIdx.y == 0)
        fcred_impl<CC0>(g_pt0, b0, out + OFF_CL0, g_h0h, g_h0l);
    else
        fcred_impl<CC1>(g_pt1, b1, out + OFF_CL1, g_h1h, g_h1l);
}

// ===========================================================================
// Child proj: A resident, loop 4 p-tiles with double-buffered B.
// grid (64, EE, 4): z = level*2 + half. smem: A (hi|lo) | B0 (hi|lo) | B1.
// ===========================================================================
template <int CK>
__device__ __forceinline__ void tproj_impl(
    const __nv_bfloat16* __restrict__ ah, const __nv_bfloat16* __restrict__ al,
    const __nv_bfloat16* __restrict__ wh, const __nv_bfloat16* __restrict__ wl,
    const float* __restrict__ bias, float* __restrict__ out,
    int half4, char* sm, int* sidx)
{
    const int e = blockIdx.y;
    const int start = g_off[e] + blockIdx.x * 128;
    const int end = g_off[e + 1];
    if (start >= end) return;

    constexpr int NKC = CK / 64;
    const int t = threadIdx.x;
    const int wid = t >> 5, lane = t & 31;
    const int wr = wid & 3, wc = wid >> 2;
    const uint32_t sb = smem_u32(sm);
    constexpr uint32_t MSZ = (uint32_t)NKC * 16384u;  // one matrix (hi or lo)
    constexpr uint32_t ABLK = 2 * MSZ;                // A hi+lo
    constexpr uint32_t BBLK = 2 * MSZ;                // B hi+lo per buffer
    const int pt0 = half4 * 4;

    if (t < 128) { int gi = start + t; sidx[t] = g_sidx[gi < end ? gi : end - 1]; }
    __syncthreads();

    // A loads (no commit yet — grouped with first B)
    #pragma unroll
    for (int kc = 0; kc < NKC; kc++) {
        #pragma unroll
        for (int i = 0; i < 4; i++) {
            int s = t + i * 256;
            int row = s >> 3, ch = s & 7;
            uint32_t off = (uint32_t)(kc * 16384 + row * 128 + ((ch * 16) ^ ((row & 7) << 4)));
            size_t ga = (size_t)sidx[row] * CK + kc * 64 + ch * 8;
            CPA(sb + off, ah + ga);
            CPA(sb + MSZ + off, al + ga);
        }
    }

    auto issueB = [&](int pi) {  // pi in [0,4)
        uint32_t base = sb + ABLK + (uint32_t)((pi & 1) * BBLK);
        int pt = pt0 + pi;
        #pragma unroll
        for (int kc = 0; kc < NKC; kc++) {
            #pragma unroll
            for (int i = 0; i < 4; i++) {
                int s = t + i * 256;
                int row = s >> 3, ch = s & 7;
                uint32_t off = (uint32_t)(kc * 16384 + row * 128
                                          + ((ch * 16) ^ ((row & 7) << 4)));
                size_t gb = ((size_t)(e * PP + pt * 128 + row)) * CK + kc * 64 + ch * 8;
                CPA(base + off, wh + gb);
                CPA(base + MSZ + off, wl + gb);
            }
        }
        CPA_COMMIT();
    };

    issueB(0);  // commits A + B0 together

    const int rA0 = wr * 32 + (lane >> 2);
    for (int pi = 0; pi < 4; pi++) {
        if (pi + 1 < 4) { issueB(pi + 1); CPA_WAIT(1); }
        else            { CPA_WAIT(0); }
        __syncthreads();

        float accA[32], accB[32];
        #pragma unroll
        for (int i = 0; i < 32; i++) { accA[i] = 0.f; accB[i] = 0.f; }

        uint32_t bbase = sb + ABLK + (uint32_t)((pi & 1) * BBLK);
        #pragma unroll
        for (int kc = 0; kc < NKC; kc++) {
            uint32_t ab = sb + (uint32_t)(kc * 16384);
            uint32_t bb = bbase + (uint32_t)(kc * 16384);
            mma_chunk2<4>(ab, ab + MSZ,
                          bb + (uint32_t)(wc * 64 * 128),
                          bb + MSZ + (uint32_t)(wc * 64 * 128),
                          wr * 32, lane, accA, accB);
        }

        int pt = pt0 + pi;
        #pragma unroll
        for (int g = 0; g < 4; g++) {
            #pragma unroll
            for (int hf = 0; hf < 2; hf++) {
                int pcol = pt * 128 + wc * 64 + (g * 2 + hf) * 8 + (lane & 3) * 2;
                float bv0 = bias[(size_t)e * PP + pcol];
                float bv1 = bias[(size_t)e * PP + pcol + 1];
                float* pa = accA + g * 8 + hf * 4;
                float* pb = accB + g * 8 + hf * 4;
                int rows[4] = {rA0, rA0 + 8, rA0 + 16, rA0 + 24};
                float* vals[4] = {pa, pa + 2, pb, pb + 2};
                #pragma unroll
                for (int rv = 0; rv < 4; rv++) {
                    if (start + rows[rv] < end) {
                        int b = sidx[rows[rv]];
                        *(float2*)&out[(size_t)b * PP + pcol] =
                            make_float2(vals[rv][0] + bv0, vals[rv][1] + bv1);
                    }
                }
            }
        }
        __syncthreads();
    }
}

#define PROJ_SMEM 196608

__global__ __launch_bounds__(256, 1) void k_tproj(
    const float* __restrict__ bpr0, const float* __restrict__ bpr1,
    float* __restrict__ out)
{
    extern __shared__ char smx[];
    __shared__ int sidx[128];
    const int level = blockIdx.z >> 1;
    const int half4 = blockIdx.z & 1;
    if (level == 0)
        tproj_impl<CC0>(g_h0h, g_h0l, g_wp0h, g_wp0l, bpr0, out + OFF_CP0, half4, smx, sidx);
    else
        tproj_impl<CC1>(g_h1h, g_h1l, g_wp1h, g_wp1l, bpr1, out + OFF_CP1, half4, smx, sidx);
}

// ---------------------------------------------------------------------------

extern "C" void kernel_launch(void* const* d_in, const int* in_sizes, int n_in,
                              void* d_out, int out_size) {
    const float* x       = (const float*)d_in[0];
    const float* pw_fc   = (const float*)d_in[1];
    const float* pb_fc   = (const float*)d_in[2];
    const float* pw_proj = (const float*)d_in[3];
    const float* pb_proj = (const float*)d_in[4];
    const float* cw_fc0  = (const float*)d_in[5];
    const float* cb_fc0  = (const float*)d_in[6];
    const float* cw_pr0  = (const float*)d_in[7];
    const float* cb_pr0  = (const float*)d_in[8];
    const float* cw_fc1  = (const float*)d_in[9];
    const float* cb_fc1  = (const float*)d_in[10];
    const float* cw_pr1  = (const float*)d_in[11];
    const float* cb_pr1  = (const float*)d_in[12];
    float* out = (float*)d_out;

    cudaFuncSetAttribute(k_tfc0, cudaFuncAttributeMaxDynamicSharedMemorySize, FC_SMEM0);
    cudaFuncSetAttribute(k_tfc1, cudaFuncAttributeMaxDynamicSharedMemorySize, FC_SMEM1);
    cudaFuncSetAttribute(k_tproj, cudaFuncAttributeMaxDynamicSharedMemorySize, PROJ_SMEM);

    // 1
    k_cvtx<<<BB * DD / 4 / 256, 256>>>(x);
    // 2
    k_cvtw<<<dim3(4096, 4), 256>>>(cw_fc0, cw_fc1, cw_pr0, cw_pr1);
    // 3
    k_parent_fc<<<BB / 64, 128>>>(x, pw_fc, pb_fc, out + OFF_PL);
    // 4
    k_scansc<<<1, 1024>>>();
    // 5
    k_parent_proj<<<BB / 64, 256>>>(out + OFF_PL, pw_proj, pb_proj, out + OFF_PP);
    // 6  <-- ncu -s 5 profiles this one: the big child fc GEMM
    k_tfc1<<<dim3(BB / 128, EE, 4), 256, FC_SMEM1>>>();
    // 7
    k_tfc0<<<dim3(BB / 128, EE, 4), 256, FC_SMEM0>>>();
    // 8
    k_fcred<<<dim3(BB / 8, 2), 256>>>(cb_fc0, cb_fc1, out);
    // 9
    k_tproj<<<dim3(BB / 128, EE, 4), 256, PROJ_SMEM>>>(cb_pr0, cb_pr1, out);
}

// round 11
// speedup vs baseline: 2.6540x; 1.0669x over previous
#include <cuda_runtime.h>
#include <cuda_bf16.h>
#include <cstdint>

#define BB 8192
#define DD 2048
#define EE 16
#define PP 1024
#define CC0 64
#define CC1 128
#define LN_EPS 1e-5f

#define OFF_PL  0
#define OFF_CL0 (BB*EE)
#define OFF_CL1 (OFF_CL0 + BB*CC0)
#define OFF_PP  (OFF_CL1 + BB*CC1)
#define OFF_CP0 (OFF_PP + BB*PP)
#define OFF_CP1 (OFF_CP0 + BB*PP)

typedef unsigned long long u64t;

// ------------------------- scratch globals -------------------------
__device__ int g_class[BB];
__device__ int g_off[EE + 1];
__device__ int g_sidx[BB];

__device__ __nv_bfloat16 g_xh[BB * DD], g_xl[BB * DD];
__device__ __nv_bfloat16 g_wfc0h[EE * CC0 * DD], g_wfc0l[EE * CC0 * DD];
__device__ __nv_bfloat16 g_wfc1h[EE * CC1 * DD], g_wfc1l[EE * CC1 * DD];
__device__ __nv_bfloat16 g_wp0h[EE * PP * CC0], g_wp0l[EE * PP * CC0];
__device__ __nv_bfloat16 g_wp1h[EE * PP * CC1], g_wp1l[EE * PP * CC1];
__device__ __nv_bfloat16 g_h0h[BB * CC0], g_h0l[BB * CC0];
__device__ __nv_bfloat16 g_h1h[BB * CC1], g_h1l[BB * CC1];

__device__ float g_pt0[4 * BB * CC0];
__device__ float g_pt1[4 * BB * CC1];

// ------------------------- asm helpers (sm_80+ generic) ---------------
__device__ __forceinline__ uint32_t smem_u32(const void* p) {
    uint32_t a;
    asm("{ .reg .u64 t; cvta.to.shared.u64 t, %1; cvt.u32.u64 %0, t; }"
        : "=r"(a) : "l"(p));
    return a;
}
#define CPA(dst, src) \
    asm volatile("cp.async.cg.shared.global [%0], [%1], 16;" :: "r"(dst), "l"(src) : "memory")
#define CPA_COMMIT() asm volatile("cp.async.commit_group;" ::: "memory")
#define CPA_WAIT(n)  asm volatile("cp.async.wait_group %0;" :: "n"(n) : "memory")
#define LDM4(r, addr) \
    asm volatile("ldmatrix.sync.aligned.m8n8.x4.shared.b16 {%0,%1,%2,%3}, [%4];" \
                 : "=r"((r)[0]), "=r"((r)[1]), "=r"((r)[2]), "=r"((r)[3]) : "r"(addr))

__device__ __forceinline__ void mma_bf16(float* c, const uint32_t* a,
                                         uint32_t b0, uint32_t b1) {
    asm volatile(
        "mma.sync.aligned.m16n8k16.row.col.f32.bf16.bf16.f32 "
        "{%0,%1,%2,%3}, {%4,%5,%6,%7}, {%8,%9}, {%0,%1,%2,%3};"
        : "+f"(c[0]), "+f"(c[1]), "+f"(c[2]), "+f"(c[3])
        : "r"(a[0]), "r"(a[1]), "r"(a[2]), "r"(a[3]), "r"(b0), "r"(b1));
}

// Two 16-row subtiles per warp sharing B fragments. NG groups of 16 cols.
template <int NG>
__device__ __forceinline__ void mma_chunk2(uint32_t AH, uint32_t AL,
                                           uint32_t BH, uint32_t BL,
                                           int m0, int lane,
                                           float* accA, float* accB) {
    const int arow0 = m0 + (lane & 15);
    const uint32_t aoff0 = (uint32_t)arow0 * 128u;
    const uint32_t aoff1 = aoff0 + 16u * 128u;
    const uint32_t axr = (uint32_t)((arow0 & 7) << 4);
    const uint32_t acb0 = (uint32_t)((lane >> 4) << 4);
    const int brl = ((lane >> 4) & 1) * 8 + (lane & 7);
    const uint32_t bcb0 = (uint32_t)(((lane >> 3) & 1) << 4);
    #pragma unroll
    for (int ks = 0; ks < 4; ks++) {
        uint32_t acb = ((uint32_t)(ks * 32) + acb0) ^ axr;
        uint32_t ah0[4], al0[4], ah1[4], al1[4];
        LDM4(ah0, AH + aoff0 + acb);
        LDM4(al0, AL + aoff0 + acb);
        LDM4(ah1, AH + aoff1 + acb);
        LDM4(al1, AL + aoff1 + acb);
        #pragma unroll
        for (int g = 0; g < NG; g++) {
            int brow = g * 16 + brl;
            uint32_t boff = (uint32_t)brow * 128u
                            + (((uint32_t)(ks * 32) + bcb0) ^ (uint32_t)((brow & 7) << 4));
            uint32_t bh[4], bl[4];
            LDM4(bh, BH + boff);
            LDM4(bl, BL + boff);
            float* c0 = accA + g * 8;
            float* c1 = accA + g * 8 + 4;
            mma_bf16(c0, ah0, bh[0], bh[1]);
            mma_bf16(c0, ah0, bl[0], bl[1]);
            mma_bf16(c0, al0, bh[0], bh[1]);
            mma_bf16(c1, ah0, bh[2], bh[3]);
            mma_bf16(c1, ah0, bl[2], bl[3]);
            mma_bf16(c1, al0, bh[2], bh[3]);
            float* d0 = accB + g * 8;
            float* d1 = accB + g * 8 + 4;
            mma_bf16(d0, ah1, bh[0], bh[1]);
            mma_bf16(d0, ah1, bl[0], bl[1]);
            mma_bf16(d0, al1, bh[0], bh[1]);
            mma_bf16(d1, ah1, bh[2], bh[3]);
            mma_bf16(d1, ah1, bl[2], bl[3]);
            mma_bf16(d1, al1, bh[2], bh[3]);
        }
    }
}

// ------------------------- cvt kernels -------------------------
__device__ __forceinline__ void cvt4(const float4 v, uint2& H, uint2& L) {
    float vv[4] = {v.x, v.y, v.z, v.w};
    uint32_t h[2], l[2];
    #pragma unroll
    for (int i = 0; i < 2; i++) {
        __nv_bfloat16 h0 = __float2bfloat16(vv[2 * i]);
        __nv_bfloat16 h1 = __float2bfloat16(vv[2 * i + 1]);
        float l0 = vv[2 * i] - __bfloat162float(h0);
        float l1 = vv[2 * i + 1] - __bfloat162float(h1);
        h[i] = ((uint32_t)__bfloat16_as_ushort(h1) << 16) | __bfloat16_as_ushort(h0);
        __nv_bfloat16 g0 = __float2bfloat16(l0);
        __nv_bfloat16 g1 = __float2bfloat16(l1);
        l[i] = ((uint32_t)__bfloat16_as_ushort(g1) << 16) | __bfloat16_as_ushort(g0);
    }
    H = make_uint2(h[0], h[1]);
    L = make_uint2(l[0], l[1]);
}

__global__ void k_cvtx(const float* __restrict__ src) {
    int i4 = blockIdx.x * 256 + threadIdx.x;
    if (i4 * 4 < BB * DD) {
        uint2 H, L;
        cvt4(((const float4*)src)[i4], H, L);
        ((uint2*)g_xh)[i4] = H;
        ((uint2*)g_xl)[i4] = L;
    }
}

// mode 0: fc weights (y=0 -> wfc0, y=1 -> wfc1); mode 1: proj weights
__global__ void k_cvtw(const float* __restrict__ sa, const float* __restrict__ sb,
                       int mode) {
    const int sel = blockIdx.y;
    const float* src;
    __nv_bfloat16 *dh, *dl;
    int n;
    if (mode == 0) {
        if (sel == 0) { src = sa; dh = g_wfc0h; dl = g_wfc0l; n = EE * CC0 * DD; }
        else          { src = sb; dh = g_wfc1h; dl = g_wfc1l; n = EE * CC1 * DD; }
    } else {
        if (sel == 0) { src = sa; dh = g_wp0h; dl = g_wp0l; n = EE * PP * CC0; }
        else          { src = sb; dh = g_wp1h; dl = g_wp1l; n = EE * PP * CC1; }
    }
    int i4 = blockIdx.x * 256 + threadIdx.x;
    if (i4 * 4 < n) {
        uint2 H, L;
        cvt4(((const float4*)src)[i4], H, L);
        ((uint2*)dh)[i4] = H;
        ((uint2*)dl)[i4] = L;
    }
}

// histogram + scan + scatter in one block (smem atomics)
__global__ void k_scansc() {
    __shared__ int hist[EE];
    __shared__ int off[EE];
    __shared__ int cur[EE];
    const int t = threadIdx.x;
    if (t < EE) hist[t] = 0;
    __syncthreads();
    for (int b = t; b < BB; b += 1024) atomicAdd(&hist[g_class[b]], 1);
    __syncthreads();
    if (t == 0) {
        int o = 0;
        for (int e = 0; e < EE; e++) { off[e] = o; g_off[e] = o; o += hist[e]; }
        g_off[EE] = o;
    }
    if (t < EE) cur[t] = 0;
    __syncthreads();
    for (int b = t; b < BB; b += 1024) {
        int e = g_class[b];
        int pos = off[e] + atomicAdd(&cur[e], 1);
        g_sidx[pos] = b;
    }
}

// ------------------------- parent FC (exact fp32) -------------------------
__global__ __launch_bounds__(128) void k_parent_fc(
    const float* __restrict__ x, const float* __restrict__ w,
    const float* __restrict__ bias, float* __restrict__ out_pl)
{
    __shared__ __align__(16) float xs[32][68];
    __shared__ __align__(16) float ws[32][20];
    __shared__ float spart[4][64][17];

    const int t = threadIdx.x;
    const int rowg = t & 7;
    const int eg = (t >> 3) & 3;
    const int kg = t >> 5;
    const int brow = blockIdx.x * 64;

    float acc[8][4];
    #pragma unroll
    for (int i = 0; i < 8; i++)
        #pragma unroll
        for (int j = 0; j < 4; j++) acc[i][j] = 0.f;

    for (int kt = 0; kt < DD / 32; kt++) {
        float4 rx[4];
        float4 rw;
        #pragma unroll
        for (int i = 0; i < 4; i++) {
            int s = t + i * 128;
            int row = s >> 3, kq = s & 7;
            rx[i] = *(const float4*)&x[(size_t)(brow + row) * DD + kt * 32 + kq * 4];
        }
        {
            int e2 = t >> 3, kq = t & 7;
            rw = *(const float4*)&w[(size_t)e2 * DD + kt * 32 + kq * 4];
        }
        __syncthreads();
        #pragma unroll
        for (int i = 0; i < 4; i++) {
            int s = t + i * 128;
            int row = s >> 3, kq = s & 7;
            xs[kq * 4 + 0][row] = rx[i].x;
            xs[kq * 4 + 1][row] = rx[i].y;
            xs[kq * 4 + 2][row] = rx[i].z;
            xs[kq * 4 + 3][row] = rx[i].w;
        }
        {
            int e2 = t >> 3, kq = t & 7;
            ws[kq * 4 + 0][e2] = rw.x;
            ws[kq * 4 + 1][e2] = rw.y;
            ws[kq * 4 + 2][e2] = rw.z;
            ws[kq * 4 + 3][e2] = rw.w;
        }
        __syncthreads();
        #pragma unroll
        for (int kk2 = 0; kk2 < 8; kk2++) {
            int kk = kg * 8 + kk2;
            float4 a0 = *(const float4*)&xs[kk][rowg * 4];
            float4 a1 = *(const float4*)&xs[kk][32 + rowg * 4];
            float4 bq = *(const float4*)&ws[kk][eg * 4];
            float av[8] = {a0.x, a0.y, a0.z, a0.w, a1.x, a1.y, a1.z, a1.w};
            float bv[4] = {bq.x, bq.y, bq.z, bq.w};
            #pragma unroll
            for (int i = 0; i < 8; i++)
                #pragma unroll
                for (int j = 0; j < 4; j++) acc[i][j] += av[i] * bv[j];
        }
        __syncthreads();
    }

    #pragma unroll
    for (int i = 0; i < 8; i++) {
        int r = (i < 4) ? (rowg * 4 + i) : (32 + rowg * 4 + (i - 4));
        #pragma unroll
        for (int j = 0; j < 4; j++) spart[kg][r][eg * 4 + j] = acc[i][j];
    }
    __syncthreads();

    if (t < 64) {
        int r = t;
        int b = brow + r;
        float z[16];
        float mu = 0.f;
        #pragma unroll
        for (int e2 = 0; e2 < 16; e2++) {
            float v = spart[0][r][e2] + spart[1][r][e2] + spart[2][r][e2] + spart[3][r][e2]
                      + bias[e2];
            z[e2] = v;
            mu += v;
        }
        mu *= (1.f / 16.f);
        float var = 0.f;
        #pragma unroll
        for (int e2 = 0; e2 < 16; e2++) { float d = z[e2] - mu; var += d * d; }
        var *= (1.f / 16.f);
        float rs = rsqrtf(var + LN_EPS);

        float best = z[0];
        int cls = 0;
        #pragma unroll
        for (int e2 = 1; e2 < 16; e2++)
            if (z[e2] > best) { best = z[e2]; cls = e2; }

        #pragma unroll
        for (int q = 0; q < 4; q++) {
            float4 o = make_float4((z[q * 4 + 0] - mu) * rs, (z[q * 4 + 1] - mu) * rs,
                                   (z[q * 4 + 2] - mu) * rs, (z[q * 4 + 3] - mu) * rs);
            *(float4*)&out_pl[(size_t)b * 16 + q * 4] = o;
        }
        g_class[b] = cls;
    }
}

// ------------------------- parent proj -------------------------
__global__ __launch_bounds__(256) void k_parent_proj(
    const float* __restrict__ pl, const float* __restrict__ w,
    const float* __restrict__ bias, float* __restrict__ out)
{
    __shared__ __align__(16) float spl[64][20];
    const int t = threadIdx.x;
    const int brow = blockIdx.x * 64;

    {
        int row = t >> 2, q = t & 3;
        float4 g = *(const float4*)&pl[(size_t)(brow + row) * 16 + q * 4];
        spl[row][q * 4 + 0] = g.x;
        spl[row][q * 4 + 1] = g.y;
        spl[row][q * 4 + 2] = g.z;
        spl[row][q * 4 + 3] = g.w;
    }
    __syncthreads();

    for (int pass = 0; pass < 2; pass++) {
        int p0 = pass * 512 + t * 2;
        float w0[16], w1[16];
        #pragma unroll
        for (int q = 0; q < 4; q++) {
            float4 a = *(const float4*)&w[(size_t)p0 * 16 + q * 4];
            w0[q * 4 + 0] = a.x; w0[q * 4 + 1] = a.y; w0[q * 4 + 2] = a.z; w0[q * 4 + 3] = a.w;
            float4 c = *(const float4*)&w[(size_t)(p0 + 1) * 16 + q * 4];
            w1[q * 4 + 0] = c.x; w1[q * 4 + 1] = c.y; w1[q * 4 + 2] = c.z; w1[q * 4 + 3] = c.w;
        }
        float b0 = bias[p0], b1 = bias[p0 + 1];

        for (int r = 0; r < 64; r++) {
            float a0 = b0, a1 = b1;
            #pragma unroll
            for (int q = 0; q < 4; q++) {
                float4 v = *(const float4*)&spl[r][q * 4];
                a0 += v.x * w0[q * 4 + 0] + v.y * w0[q * 4 + 1] + v.z * w0[q * 4 + 2] + v.w * w0[q * 4 + 3];
                a1 += v.x * w1[q * 4 + 0] + v.y * w1[q * 4 + 1] + v.z * w1[q * 4 + 2] + v.w * w1[q * 4 + 3];
            }
            float2 o = make_float2(a0, a1);
            *(float2*)&out[(size_t)(brow + r) * PP + p0] = o;
        }
    }
}

// ===========================================================================
// Child FC split-K GEMM, pure bf16, double-buffered. ks passed in.
// ===========================================================================
template <int BN>
__device__ __forceinline__ void tfc_impl(
    const __nv_bfloat16* __restrict__ xh, const __nv_bfloat16* __restrict__ xl,
    const __nv_bfloat16* __restrict__ wh, const __nv_bfloat16* __restrict__ wl,
    float* __restrict__ part, int ks, char* sm, int* sidx)
{
    const int e = blockIdx.y;
    const int start = g_off[e] + blockIdx.x * 128;
    const int end = g_off[e + 1];
    if (start >= end) return;

    const int t = threadIdx.x;
    const int wid = t >> 5, lane = t & 31;
    const int wr = wid & 3, wc = wid >> 2;
    const uint32_t sb = smem_u32(sm);
    const int kbase = ks * 512;

    constexpr int AH0 = 0, AL0 = 16384, BH0 = 32768, BL0 = 32768 + BN * 128;
    constexpr int BUF = 32768 + 2 * BN * 128;
    constexpr int NGW = BN / 32;

    if (t < 128) { int gi = start + t; sidx[t] = g_sidx[gi < end ? gi : end - 1]; }
    __syncthreads();

    auto issue = [&](int kt) {
        uint32_t base = sb + (uint32_t)((kt & 1) * BUF);
        #pragma unroll
        for (int i = 0; i < 4; i++) {
            int d = t + i * 256;
            int row = d >> 3, ch = d & 7;
            uint32_t off = (uint32_t)(row * 128 + ((ch * 16) ^ ((row & 7) << 4)));
            size_t g = (size_t)sidx[row] * DD + kbase + kt * 64 + ch * 8;
            CPA(base + AH0 + off, xh + g);
            CPA(base + AL0 + off, xl + g);
        }
        #pragma unroll
        for (int i = 0; i < BN / 32; i++) {
            int d = t + i * 256;
            int row = d >> 3, ch = d & 7;
            uint32_t off = (uint32_t)(row * 128 + ((ch * 16) ^ ((row & 7) << 4)));
            size_t g = ((size_t)e * BN + row) * DD + kbase + kt * 64 + ch * 8;
            CPA(base + BH0 + off, wh + g);
            CPA(base + BL0 + off, wl + g);
        }
        CPA_COMMIT();
    };

    float accA[NGW * 8], accB[NGW * 8];
    #pragma unroll
    for (int i = 0; i < NGW * 8; i++) { accA[i] = 0.f; accB[i] = 0.f; }

    issue(0);
    const int NKT = 8;
    for (int kt = 0; kt < NKT; kt++) {
        if (kt + 1 < NKT) { issue(kt + 1); CPA_WAIT(1); }
        else              { CPA_WAIT(0); }
        __syncthreads();
        uint32_t base = sb + (uint32_t)((kt & 1) * BUF);
        mma_chunk2<NGW>(base + AH0, base + AL0,
                        base + BH0 + (uint32_t)(wc * (BN / 2) * 128),
                        base + BL0 + (uint32_t)(wc * (BN / 2) * 128),
                        wr * 32, lane, accA, accB);
        __syncthreads();
    }

    const int rA0 = wr * 32 + (lane >> 2);
    #pragma unroll
    for (int g = 0; g < NGW; g++) {
        #pragma unroll
        for (int half = 0; half < 2; half++) {
            int col = wc * (BN / 2) + (g * 2 + half) * 8 + (lane & 3) * 2;
            float* pa = accA + g * 8 + half * 4;
            float* pb = accB + g * 8 + half * 4;
            int rows[4] = {rA0, rA0 + 8, rA0 + 16, rA0 + 24};
            float* vals[4] = {pa, pa + 2, pb, pb + 2};
            #pragma unroll
            for (int rv = 0; rv < 4; rv++) {
                int p = start + rows[rv];
                if (p < end)
                    *(float2*)&part[(size_t)ks * BB * BN + (size_t)p * BN + col] =
                        make_float2(vals[rv][0], vals[rv][1]);
            }
        }
    }
}

#define FC_SMEM 131072

__global__ __launch_bounds__(256, 1) void k_tfc() {
    extern __shared__ char smx[];
    __shared__ int sidx[128];
    if (blockIdx.z < 4)
        tfc_impl<CC1>(g_xh, g_xl, g_wfc1h, g_wfc1l, g_pt1, blockIdx.z, smx, sidx);
    else
        tfc_impl<CC0>(g_xh, g_xl, g_wfc0h, g_wfc0l, g_pt0, blockIdx.z - 4, smx, sidx);
}

// ===========================================================================
// FC reduce: sum 4 partials + bias + LN + write cl + h hi/lo. 1 warp per row.
// ===========================================================================
template <int BN>
__device__ __forceinline__ void fcred_impl(
    const float* __restrict__ part, const float* __restrict__ bias,
    float* __restrict__ out, __nv_bfloat16* __restrict__ hh,
    __nv_bfloat16* __restrict__ hl)
{
    const int p = blockIdx.x * 8 + (threadIdx.x >> 5);
    const int lane = threadIdx.x & 31;
    const int b = g_sidx[p];
    const int e = g_class[b];
    constexpr int NC = BN / 32;

    float v[NC];
    float s = 0.f, q = 0.f;
    #pragma unroll
    for (int i = 0; i < NC; i++) {
        int col = lane + i * 32;
        size_t idx = (size_t)p * BN + col;
        float a = part[idx] + part[(size_t)BB * BN + idx]
                + part[2 * (size_t)BB * BN + idx] + part[3 * (size_t)BB * BN + idx]
                + bias[e * BN + col];
        v[i] = a;
        s += a;
        q += a * a;
    }
    #pragma unroll
    for (int o = 16; o; o >>= 1) {
        s += __shfl_xor_sync(~0u, s, o);
        q += __shfl_xor_sync(~0u, q, o);
    }
    float mu = s * (1.f / BN);
    float rs = rsqrtf(q * (1.f / BN) - mu * mu + LN_EPS);
    #pragma unroll
    for (int i = 0; i < NC; i++) {
        int col = lane + i * 32;
        float o = (v[i] - mu) * rs;
        out[(size_t)b * BN + col] = o;
        __nv_bfloat16 h = __float2bfloat16(o);
        __nv_bfloat16 l = __float2bfloat16(o - __bfloat162float(h));
        hh[(size_t)b * BN + col] = h;
        hl[(size_t)b * BN + col] = l;
    }
}

__global__ __launch_bounds__(256) void k_fcred(
    const float* __restrict__ b0, const float* __restrict__ b1,
    float* __restrict__ out)
{
    if (blockIdx.y == 0)
        fcred_impl<CC0>(g_pt0, b0, out + OFF_CL0, g_h0h, g_h0l);
    else
        fcred_impl<CC1>(g_pt1, b1, out + OFF_CL1, g_h1h, g_h1l);
}

// ===========================================================================
// Child proj: A resident, loop 4 p-tiles with double-buffered B.
// ===========================================================================
template <int CK>
__device__ __forceinline__ void tproj_impl(
    const __nv_bfloat16* __restrict__ ah, const __nv_bfloat16* __restrict__ al,
    const __nv_bfloat16* __restrict__ wh, const __nv_bfloat16* __restrict__ wl,
    const float* __restrict__ bias, float* __restrict__ out,
    int half4, char* sm, int* sidx)
{
    const int e = blockIdx.y;
    const int start = g_off[e] + blockIdx.x * 128;
    const int end = g_off[e + 1];
    if (start >= end) return;

    constexpr int NKC = CK / 64;
    const int t = threadIdx.x;
    const int wid = t >> 5, lane = t & 31;
    const int wr = wid & 3, wc = wid >> 2;
    const uint32_t sb = smem_u32(sm);
    constexpr uint32_t MSZ = (uint32_t)NKC * 16384u;
    constexpr uint32_t ABLK = 2 * MSZ;
    constexpr uint32_t BBLK = 2 * MSZ;
    const int pt0 = half4 * 4;

    if (t < 128) { int gi = start + t; sidx[t] = g_sidx[gi < end ? gi : end - 1]; }
    __syncthreads();

    #pragma unroll
    for (int kc = 0; kc < NKC; kc++) {
        #pragma unroll
        for (int i = 0; i < 4; i++) {
            int s = t + i * 256;
            int row = s >> 3, ch = s & 7;
            uint32_t off = (uint32_t)(kc * 16384 + row * 128 + ((ch * 16) ^ ((row & 7) << 4)));
            size_t ga = (size_t)sidx[row] * CK + kc * 64 + ch * 8;
            CPA(sb + off, ah + ga);
            CPA(sb + MSZ + off, al + ga);
        }
    }

    auto issueB = [&](int pi) {
        uint32_t base = sb + ABLK + (uint32_t)((pi & 1) * BBLK);
        int pt = pt0 + pi;
        #pragma unroll
        for (int kc = 0; kc < NKC; kc++) {
            #pragma unroll
            for (int i = 0; i < 4; i++) {
                int s = t + i * 256;
                int row = s >> 3, ch = s & 7;
                uint32_t off = (uint32_t)(kc * 16384 + row * 128
                                          + ((ch * 16) ^ ((row & 7) << 4)));
                size_t gb = ((size_t)(e * PP + pt * 128 + row)) * CK + kc * 64 + ch * 8;
                CPA(base + off, wh + gb);
                CPA(base + MSZ + off, wl + gb);
            }
        }
        CPA_COMMIT();
    };

    issueB(0);

    const int rA0 = wr * 32 + (lane >> 2);
    for (int pi = 0; pi < 4; pi++) {
        if (pi + 1 < 4) { issueB(pi + 1); CPA_WAIT(1); }
        else            { CPA_WAIT(0); }
        __syncthreads();

        float accA[32], accB[32];
        #pragma unroll
        for (int i = 0; i < 32; i++) { accA[i] = 0.f; accB[i] = 0.f; }

        uint32_t bbase = sb + ABLK + (uint32_t)((pi & 1) * BBLK);
        #pragma unroll
        for (int kc = 0; kc < NKC; kc++) {
            uint32_t ab = sb + (uint32_t)(kc * 16384);
            uint32_t bb = bbase + (uint32_t)(kc * 16384);
            mma_chunk2<4>(ab, ab + MSZ,
                          bb + (uint32_t)(wc * 64 * 128),
                          bb + MSZ + (uint32_t)(wc * 64 * 128),
                          wr * 32, lane, accA, accB);
        }

        int pt = pt0 + pi;
        #pragma unroll
        for (int g = 0; g < 4; g++) {
            #pragma unroll
            for (int hf = 0; hf < 2; hf++) {
                int pcol = pt * 128 + wc * 64 + (g * 2 + hf) * 8 + (lane & 3) * 2;
                float bv0 = bias[(size_t)e * PP + pcol];
                float bv1 = bias[(size_t)e * PP + pcol + 1];
                float* pa = accA + g * 8 + hf * 4;
                float* pb = accB + g * 8 + hf * 4;
                int rows[4] = {rA0, rA0 + 8, rA0 + 16, rA0 + 24};
                float* vals[4] = {pa, pa + 2, pb, pb + 2};
                #pragma unroll
                for (int rv = 0; rv < 4; rv++) {
                    if (start + rows[rv] < end) {
                        int b = sidx[rows[rv]];
                        *(float2*)&out[(size_t)b * PP + pcol] =
                            make_float2(vals[rv][0] + bv0, vals[rv][1] + bv1);
                    }
                }
            }
        }
        __syncthreads();
    }
}

#define PROJ_SMEM 196608

__global__ __launch_bounds__(256, 1) void k_tproj(
    const float* __restrict__ bpr0, const float* __restrict__ bpr1,
    float* __restrict__ out)
{
    extern __shared__ char smx[];
    __shared__ int sidx[128];
    const int level = blockIdx.z >> 1;
    const int half4 = blockIdx.z & 1;
    if (level == 0)
        tproj_impl<CC0>(g_h0h, g_h0l, g_wp0h, g_wp0l, bpr0, out + OFF_CP0, half4, smx, sidx);
    else
        tproj_impl<CC1>(g_h1h, g_h1l, g_wp1h, g_wp1l, bpr1, out + OFF_CP1, half4, smx, sidx);
}

// ---------------------------------------------------------------------------

extern "C" void kernel_launch(void* const* d_in, const int* in_sizes, int n_in,
                              void* d_out, int out_size) {
    const float* x       = (const float*)d_in[0];
    const float* pw_fc   = (const float*)d_in[1];
    const float* pb_fc   = (const float*)d_in[2];
    const float* pw_proj = (const float*)d_in[3];
    const float* pb_proj = (const float*)d_in[4];
    const float* cw_fc0  = (const float*)d_in[5];
    const float* cb_fc0  = (const float*)d_in[6];
    const float* cw_pr0  = (const float*)d_in[7];
    const float* cb_pr0  = (const float*)d_in[8];
    const float* cw_fc1  = (const float*)d_in[9];
    const float* cb_fc1  = (const float*)d_in[10];
    const float* cw_pr1  = (const float*)d_in[11];
    const float* cb_pr1  = (const float*)d_in[12];
    float* out = (float*)d_out;

    // one-time infra (created on the uncaptured correctness call; no device mem)
    static cudaStream_t sA = nullptr;
    static cudaEvent_t e0, evS, evC, evP;
    if (!sA) {
        cudaStreamCreate(&sA);
        cudaEventCreateWithFlags(&e0, cudaEventDisableTiming);
        cudaEventCreateWithFlags(&evS, cudaEventDisableTiming);
        cudaEventCreateWithFlags(&evC, cudaEventDisableTiming);
        cudaEventCreateWithFlags(&evP, cudaEventDisableTiming);
        cudaFuncSetAttribute(k_tfc, cudaFuncAttributeMaxDynamicSharedMemorySize, FC_SMEM);
        cudaFuncSetAttribute(k_tproj, cudaFuncAttributeMaxDynamicSharedMemorySize, PROJ_SMEM);
    }

    // fork
    cudaEventRecord(e0, 0);
    cudaStreamWaitEvent(sA, e0, 0);

    // branch 0 (default stream): parent fc -> bucket
    k_parent_fc<<<BB / 64, 128>>>(x, pw_fc, pb_fc, out + OFF_PL);
    k_scansc<<<1, 1024>>>();
    cudaEventRecord(evS, 0);

    // branch A: converts, then (after scansc? no — after parent_fc via evS) pproj
    k_cvtx<<<BB * DD / 4 / 256, 256, 0, sA>>>(x);
    k_cvtw<<<dim3(4096, 2), 256, 0, sA>>>(cw_fc0, cw_fc1, 0);
    cudaEventRecord(evC, sA);
    cudaStreamWaitEvent(sA, evS, 0);
    k_parent_proj<<<BB / 64, 256, 0, sA>>>(out + OFF_PL, pw_proj, pb_proj, out + OFF_PP);
    k_cvtw<<<dim3(2048, 2), 256, 0, sA>>>(cw_pr0, cw_pr1, 1);
    cudaEventRecord(evP, sA);

    // branch 0 continues: children (needs scansc + x/fc-weight cvts)
    cudaStreamWaitEvent(0, evC, 0);
    k_tfc<<<dim3(BB / 128, EE, 8), 256, FC_SMEM>>>();
    k_fcred<<<dim3(BB / 8, 2), 256>>>(cb_fc0, cb_fc1, out);
    cudaStreamWaitEvent(0, evP, 0);  // join: pproj + proj-weight cvt done
    k_tproj<<<dim3(BB / 128, EE, 4), 256, PROJ_SMEM>>>(cb_pr0, cb_pr1, out);
}

// round 12
// speedup vs baseline: 2.6875x; 1.0126x over previous
#include <cuda_runtime.h>
#include <cuda_bf16.h>
#include <cstdint>

#define BB 8192
#define DD 2048
#define EE 16
#define PP 1024
#define CC0 64
#define CC1 128
#define LN_EPS 1e-5f

#define OFF_PL  0
#define OFF_CL0 (BB*EE)
#define OFF_CL1 (OFF_CL0 + BB*CC0)
#define OFF_PP  (OFF_CL1 + BB*CC1)
#define OFF_CP0 (OFF_PP + BB*PP)
#define OFF_CP1 (OFF_CP0 + BB*PP)

typedef unsigned long long u64t;

// ------------------------- scratch globals -------------------------
__device__ int g_class[BB];
__device__ int g_off[EE + 1];
__device__ int g_sidx[BB];

__device__ __nv_bfloat16 g_xh[BB * DD], g_xl[BB * DD];
__device__ __nv_bfloat16 g_wfc0h[EE * CC0 * DD], g_wfc0l[EE * CC0 * DD];
__device__ __nv_bfloat16 g_wfc1h[EE * CC1 * DD], g_wfc1l[EE * CC1 * DD];
__device__ __nv_bfloat16 g_wp0h[EE * PP * CC0], g_wp0l[EE * PP * CC0];
__device__ __nv_bfloat16 g_wp1h[EE * PP * CC1], g_wp1l[EE * PP * CC1];
__device__ __nv_bfloat16 g_h0h[BB * CC0], g_h0l[BB * CC0];
__device__ __nv_bfloat16 g_h1h[BB * CC1], g_h1l[BB * CC1];

__device__ float g_pt0[4 * BB * CC0];
__device__ float g_pt1[4 * BB * CC1];

// ------------------------- asm helpers (sm_80+ generic) ---------------
__device__ __forceinline__ uint32_t smem_u32(const void* p) {
    uint32_t a;
    asm("{ .reg .u64 t; cvta.to.shared.u64 t, %1; cvt.u32.u64 %0, t; }"
        : "=r"(a) : "l"(p));
    return a;
}
#define CPA(dst, src) \
    asm volatile("cp.async.cg.shared.global [%0], [%1], 16;" :: "r"(dst), "l"(src) : "memory")
#define CPA_COMMIT() asm volatile("cp.async.commit_group;" ::: "memory")
#define CPA_WAIT(n)  asm volatile("cp.async.wait_group %0;" :: "n"(n) : "memory")
#define LDM4(r, addr) \
    asm volatile("ldmatrix.sync.aligned.m8n8.x4.shared.b16 {%0,%1,%2,%3}, [%4];" \
                 : "=r"((r)[0]), "=r"((r)[1]), "=r"((r)[2]), "=r"((r)[3]) : "r"(addr))

__device__ __forceinline__ void mma_bf16(float* c, const uint32_t* a,
                                         uint32_t b0, uint32_t b1) {
    asm volatile(
        "mma.sync.aligned.m16n8k16.row.col.f32.bf16.bf16.f32 "
        "{%0,%1,%2,%3}, {%4,%5,%6,%7}, {%8,%9}, {%0,%1,%2,%3};"
        : "+f"(c[0]), "+f"(c[1]), "+f"(c[2]), "+f"(c[3])
        : "r"(a[0]), "r"(a[1]), "r"(a[2]), "r"(a[3]), "r"(b0), "r"(b1));
}

// Two 16-row subtiles per warp sharing B fragments. NG groups of 16 cols.
template <int NG>
__device__ __forceinline__ void mma_chunk2(uint32_t AH, uint32_t AL,
                                           uint32_t BH, uint32_t BL,
                                           int m0, int lane,
                                           float* accA, float* accB) {
    const int arow0 = m0 + (lane & 15);
    const uint32_t aoff0 = (uint32_t)arow0 * 128u;
    const uint32_t aoff1 = aoff0 + 16u * 128u;
    const uint32_t axr = (uint32_t)((arow0 & 7) << 4);
    const uint32_t acb0 = (uint32_t)((lane >> 4) << 4);
    const int brl = ((lane >> 4) & 1) * 8 + (lane & 7);
    const uint32_t bcb0 = (uint32_t)(((lane >> 3) & 1) << 4);
    #pragma unroll
    for (int ks = 0; ks < 4; ks++) {
        uint32_t acb = ((uint32_t)(ks * 32) + acb0) ^ axr;
        uint32_t ah0[4], al0[4], ah1[4], al1[4];
        LDM4(ah0, AH + aoff0 + acb);
        LDM4(al0, AL + aoff0 + acb);
        LDM4(ah1, AH + aoff1 + acb);
        LDM4(al1, AL + aoff1 + acb);
        #pragma unroll
        for (int g = 0; g < NG; g++) {
            int brow = g * 16 + brl;
            uint32_t boff = (uint32_t)brow * 128u
                            + (((uint32_t)(ks * 32) + bcb0) ^ (uint32_t)((brow & 7) << 4));
            uint32_t bh[4], bl[4];
            LDM4(bh, BH + boff);
            LDM4(bl, BL + boff);
            float* c0 = accA + g * 8;
            float* c1 = accA + g * 8 + 4;
            mma_bf16(c0, ah0, bh[0], bh[1]);
            mma_bf16(c0, ah0, bl[0], bl[1]);
            mma_bf16(c0, al0, bh[0], bh[1]);
            mma_bf16(c1, ah0, bh[2], bh[3]);
            mma_bf16(c1, ah0, bl[2], bl[3]);
            mma_bf16(c1, al0, bh[2], bh[3]);
            float* d0 = accB + g * 8;
            float* d1 = accB + g * 8 + 4;
            mma_bf16(d0, ah1, bh[0], bh[1]);
            mma_bf16(d0, ah1, bl[0], bl[1]);
            mma_bf16(d0, al1, bh[0], bh[1]);
            mma_bf16(d1, ah1, bh[2], bh[3]);
            mma_bf16(d1, ah1, bl[2], bl[3]);
            mma_bf16(d1, al1, bh[2], bh[3]);
        }
    }
}

// ------------------------- cvt kernels -------------------------
__device__ __forceinline__ void cvt4(const float4 v, uint2& H, uint2& L) {
    float vv[4] = {v.x, v.y, v.z, v.w};
    uint32_t h[2], l[2];
    #pragma unroll
    for (int i = 0; i < 2; i++) {
        __nv_bfloat16 h0 = __float2bfloat16(vv[2 * i]);
        __nv_bfloat16 h1 = __float2bfloat16(vv[2 * i + 1]);
        float l0 = vv[2 * i] - __bfloat162float(h0);
        float l1 = vv[2 * i + 1] - __bfloat162float(h1);
        h[i] = ((uint32_t)__bfloat16_as_ushort(h1) << 16) | __bfloat16_as_ushort(h0);
        __nv_bfloat16 g0 = __float2bfloat16(l0);
        __nv_bfloat16 g1 = __float2bfloat16(l1);
        l[i] = ((uint32_t)__bfloat16_as_ushort(g1) << 16) | __bfloat16_as_ushort(g0);
    }
    H = make_uint2(h[0], h[1]);
    L = make_uint2(l[0], l[1]);
}

__global__ void k_cvtx(const float* __restrict__ src) {
    int i4 = blockIdx.x * 256 + threadIdx.x;
    if (i4 * 4 < BB * DD) {
        uint2 H, L;
        cvt4(((const float4*)src)[i4], H, L);
        ((uint2*)g_xh)[i4] = H;
        ((uint2*)g_xl)[i4] = L;
    }
}

// mode 0: fc weights (y=0 -> wfc0, y=1 -> wfc1); mode 1: proj weights
__global__ void k_cvtw(const float* __restrict__ sa, const float* __restrict__ sb,
                       int mode) {
    const int sel = blockIdx.y;
    const float* src;
    __nv_bfloat16 *dh, *dl;
    int n;
    if (mode == 0) {
        if (sel == 0) { src = sa; dh = g_wfc0h; dl = g_wfc0l; n = EE * CC0 * DD; }
        else          { src = sb; dh = g_wfc1h; dl = g_wfc1l; n = EE * CC1 * DD; }
    } else {
        if (sel == 0) { src = sa; dh = g_wp0h; dl = g_wp0l; n = EE * PP * CC0; }
        else          { src = sb; dh = g_wp1h; dl = g_wp1l; n = EE * PP * CC1; }
    }
    int i4 = blockIdx.x * 256 + threadIdx.x;
    if (i4 * 4 < n) {
        uint2 H, L;
        cvt4(((const float4*)src)[i4], H, L);
        ((uint2*)dh)[i4] = H;
        ((uint2*)dl)[i4] = L;
    }
}

// histogram + scan + scatter in one block (smem atomics)
__global__ void k_scansc() {
    __shared__ int hist[EE];
    __shared__ int off[EE];
    __shared__ int cur[EE];
    const int t = threadIdx.x;
    if (t < EE) hist[t] = 0;
    __syncthreads();
    for (int b = t; b < BB; b += 1024) atomicAdd(&hist[g_class[b]], 1);
    __syncthreads();
    if (t == 0) {
        int o = 0;
        for (int e = 0; e < EE; e++) { off[e] = o; g_off[e] = o; o += hist[e]; }
        g_off[EE] = o;
    }
    if (t < EE) cur[t] = 0;
    __syncthreads();
    for (int b = t; b < BB; b += 1024) {
        int e = g_class[b];
        int pos = off[e] + atomicAdd(&cur[e], 1);
        g_sidx[pos] = b;
    }
}

// ------------------------- parent FC (exact fp32) -------------------------
__global__ __launch_bounds__(128) void k_parent_fc(
    const float* __restrict__ x, const float* __restrict__ w,
    const float* __restrict__ bias, float* __restrict__ out_pl)
{
    __shared__ __align__(16) float xs[32][68];
    __shared__ __align__(16) float ws[32][20];
    __shared__ float spart[4][64][17];

    const int t = threadIdx.x;
    const int rowg = t & 7;
    const int eg = (t >> 3) & 3;
    const int kg = t >> 5;
    const int brow = blockIdx.x * 64;

    float acc[8][4];
    #pragma unroll
    for (int i = 0; i < 8; i++)
        #pragma unroll
        for (int j = 0; j < 4; j++) acc[i][j] = 0.f;

    for (int kt = 0; kt < DD / 32; kt++) {
        float4 rx[4];
        float4 rw;
        #pragma unroll
        for (int i = 0; i < 4; i++) {
            int s = t + i * 128;
            int row = s >> 3, kq = s & 7;
            rx[i] = *(const float4*)&x[(size_t)(brow + row) * DD + kt * 32 + kq * 4];
        }
        {
            int e2 = t >> 3, kq = t & 7;
            rw = *(const float4*)&w[(size_t)e2 * DD + kt * 32 + kq * 4];
        }
        __syncthreads();
        #pragma unroll
        for (int i = 0; i < 4; i++) {
            int s = t + i * 128;
            int row = s >> 3, kq = s & 7;
            xs[kq * 4 + 0][row] = rx[i].x;
            xs[kq * 4 + 1][row] = rx[i].y;
            xs[kq * 4 + 2][row] = rx[i].z;
            xs[kq * 4 + 3][row] = rx[i].w;
        }
        {
            int e2 = t >> 3, kq = t & 7;
            ws[kq * 4 + 0][e2] = rw.x;
            ws[kq * 4 + 1][e2] = rw.y;
            ws[kq * 4 + 2][e2] = rw.z;
            ws[kq * 4 + 3][e2] = rw.w;
        }
        __syncthreads();
        #pragma unroll
        for (int kk2 = 0; kk2 < 8; kk2++) {
            int kk = kg * 8 + kk2;
            float4 a0 = *(const float4*)&xs[kk][rowg * 4];
            float4 a1 = *(const float4*)&xs[kk][32 + rowg * 4];
            float4 bq = *(const float4*)&ws[kk][eg * 4];
            float av[8] = {a0.x, a0.y, a0.z, a0.w, a1.x, a1.y, a1.z, a1.w};
            float bv[4] = {bq.x, bq.y, bq.z, bq.w};
            #pragma unroll
            for (int i = 0; i < 8; i++)
                #pragma unroll
                for (int j = 0; j < 4; j++) acc[i][j] += av[i] * bv[j];
        }
        __syncthreads();
    }

    #pragma unroll
    for (int i = 0; i < 8; i++) {
        int r = (i < 4) ? (rowg * 4 + i) : (32 + rowg * 4 + (i - 4));
        #pragma unroll
        for (int j = 0; j < 4; j++) spart[kg][r][eg * 4 + j] = acc[i][j];
    }
    __syncthreads();

    if (t < 64) {
        int r = t;
        int b = brow + r;
        float z[16];
        float mu = 0.f;
        #pragma unroll
        for (int e2 = 0; e2 < 16; e2++) {
            float v = spart[0][r][e2] + spart[1][r][e2] + spart[2][r][e2] + spart[3][r][e2]
                      + bias[e2];
            z[e2] = v;
            mu += v;
        }
        mu *= (1.f / 16.f);
        float var = 0.f;
        #pragma unroll
        for (int e2 = 0; e2 < 16; e2++) { float d = z[e2] - mu; var += d * d; }
        var *= (1.f / 16.f);
        float rs = rsqrtf(var + LN_EPS);

        float best = z[0];
        int cls = 0;
        #pragma unroll
        for (int e2 = 1; e2 < 16; e2++)
            if (z[e2] > best) { best = z[e2]; cls = e2; }

        #pragma unroll
        for (int q = 0; q < 4; q++) {
            float4 o = make_float4((z[q * 4 + 0] - mu) * rs, (z[q * 4 + 1] - mu) * rs,
                                   (z[q * 4 + 2] - mu) * rs, (z[q * 4 + 3] - mu) * rs);
            *(float4*)&out_pl[(size_t)b * 16 + q * 4] = o;
        }
        g_class[b] = cls;
    }
}

// ------------------------- parent proj -------------------------
__global__ __launch_bounds__(256) void k_parent_proj(
    const float* __restrict__ pl, const float* __restrict__ w,
    const float* __restrict__ bias, float* __restrict__ out)
{
    __shared__ __align__(16) float spl[64][20];
    const int t = threadIdx.x;
    const int brow = blockIdx.x * 64;

    {
        int row = t >> 2, q = t & 3;
        float4 g = *(const float4*)&pl[(size_t)(brow + row) * 16 + q * 4];
        spl[row][q * 4 + 0] = g.x;
        spl[row][q * 4 + 1] = g.y;
        spl[row][q * 4 + 2] = g.z;
        spl[row][q * 4 + 3] = g.w;
    }
    __syncthreads();

    for (int pass = 0; pass < 2; pass++) {
        int p0 = pass * 512 + t * 2;
        float w0[16], w1[16];
        #pragma unroll
        for (int q = 0; q < 4; q++) {
            float4 a = *(const float4*)&w[(size_t)p0 * 16 + q * 4];
            w0[q * 4 + 0] = a.x; w0[q * 4 + 1] = a.y; w0[q * 4 + 2] = a.z; w0[q * 4 + 3] = a.w;
            float4 c = *(const float4*)&w[(size_t)(p0 + 1) * 16 + q * 4];
            w1[q * 4 + 0] = c.x; w1[q * 4 + 1] = c.y; w1[q * 4 + 2] = c.z; w1[q * 4 + 3] = c.w;
        }
        float b0 = bias[p0], b1 = bias[p0 + 1];

        for (int r = 0; r < 64; r++) {
            float a0 = b0, a1 = b1;
            #pragma unroll
            for (int q = 0; q < 4; q++) {
                float4 v = *(const float4*)&spl[r][q * 4];
                a0 += v.x * w0[q * 4 + 0] + v.y * w0[q * 4 + 1] + v.z * w0[q * 4 + 2] + v.w * w0[q * 4 + 3];
                a1 += v.x * w1[q * 4 + 0] + v.y * w1[q * 4 + 1] + v.z * w1[q * 4 + 2] + v.w * w1[q * 4 + 3];
            }
            float2 o = make_float2(a0, a1);
            *(float2*)&out[(size_t)(brow + r) * PP + p0] = o;
        }
    }
}

// ===========================================================================
// Child FC split-K GEMM, pure bf16, double-buffered. ks passed in.
// ===========================================================================
template <int BN>
__device__ __forceinline__ void tfc_impl(
    const __nv_bfloat16* __restrict__ xh, const __nv_bfloat16* __restrict__ xl,
    const __nv_bfloat16* __restrict__ wh, const __nv_bfloat16* __restrict__ wl,
    float* __restrict__ part, int ks, char* sm, int* sidx)
{
    const int e = blockIdx.y;
    const int start = g_off[e] + blockIdx.x * 128;
    const int end = g_off[e + 1];
    if (start >= end) return;

    const int t = threadIdx.x;
    const int wid = t >> 5, lane = t & 31;
    const int wr = wid & 3, wc = wid >> 2;
    const uint32_t sb = smem_u32(sm);
    const int kbase = ks * 512;

    constexpr int AH0 = 0, AL0 = 16384, BH0 = 32768, BL0 = 32768 + BN * 128;
    constexpr int BUF = 32768 + 2 * BN * 128;
    constexpr int NGW = BN / 32;

    if (t < 128) { int gi = start + t; sidx[t] = g_sidx[gi < end ? gi : end - 1]; }
    __syncthreads();

    auto issue = [&](int kt) {
        uint32_t base = sb + (uint32_t)((kt & 1) * BUF);
        #pragma unroll
        for (int i = 0; i < 4; i++) {
            int d = t + i * 256;
            int row = d >> 3, ch = d & 7;
            uint32_t off = (uint32_t)(row * 128 + ((ch * 16) ^ ((row & 7) << 4)));
            size_t g = (size_t)sidx[row] * DD + kbase + kt * 64 + ch * 8;
            CPA(base + AH0 + off, xh + g);
            CPA(base + AL0 + off, xl + g);
        }
        #pragma unroll
        for (int i = 0; i < BN / 32; i++) {
            int d = t + i * 256;
            int row = d >> 3, ch = d & 7;
            uint32_t off = (uint32_t)(row * 128 + ((ch * 16) ^ ((row & 7) << 4)));
            size_t g = ((size_t)e * BN + row) * DD + kbase + kt * 64 + ch * 8;
            CPA(base + BH0 + off, wh + g);
            CPA(base + BL0 + off, wl + g);
        }
        CPA_COMMIT();
    };

    float accA[NGW * 8], accB[NGW * 8];
    #pragma unroll
    for (int i = 0; i < NGW * 8; i++) { accA[i] = 0.f; accB[i] = 0.f; }

    issue(0);
    const int NKT = 8;
    for (int kt = 0; kt < NKT; kt++) {
        if (kt + 1 < NKT) { issue(kt + 1); CPA_WAIT(1); }
        else              { CPA_WAIT(0); }
        __syncthreads();
        uint32_t base = sb + (uint32_t)((kt & 1) * BUF);
        mma_chunk2<NGW>(base + AH0, base + AL0,
                        base + BH0 + (uint32_t)(wc * (BN / 2) * 128),
                        base + BL0 + (uint32_t)(wc * (BN / 2) * 128),
                        wr * 32, lane, accA, accB);
        __syncthreads();
    }

    const int rA0 = wr * 32 + (lane >> 2);
    #pragma unroll
    for (int g = 0; g < NGW; g++) {
        #pragma unroll
        for (int half = 0; half < 2; half++) {
            int col = wc * (BN / 2) + (g * 2 + half) * 8 + (lane & 3) * 2;
            float* pa = accA + g * 8 + half * 4;
            float* pb = accB + g * 8 + half * 4;
            int rows[4] = {rA0, rA0 + 8, rA0 + 16, rA0 + 24};
            float* vals[4] = {pa, pa + 2, pb, pb + 2};
            #pragma unroll
            for (int rv = 0; rv < 4; rv++) {
                int p = start + rows[rv];
                if (p < end)
                    *(float2*)&part[(size_t)ks * BB * BN + (size_t)p * BN + col] =
                        make_float2(vals[rv][0], vals[rv][1]);
            }
        }
    }
}

#define FC_SMEM 131072

__global__ __launch_bounds__(256, 1) void k_tfc() {
    extern __shared__ char smx[];
    __shared__ int sidx[128];
    if (blockIdx.z < 4)
        tfc_impl<CC1>(g_xh, g_xl, g_wfc1h, g_wfc1l, g_pt1, blockIdx.z, smx, sidx);
    else
        tfc_impl<CC0>(g_xh, g_xl, g_wfc0h, g_wfc0l, g_pt0, blockIdx.z - 4, smx, sidx);
}

// ===========================================================================
// FC reduce: sum 4 partials + bias + LN + write cl + h hi/lo. 1 warp per row.
// ===========================================================================
template <int BN>
__device__ __forceinline__ void fcred_impl(
    const float* __restrict__ part, const float* __restrict__ bias,
    float* __restrict__ out, __nv_bfloat16* __restrict__ hh,
    __nv_bfloat16* __restrict__ hl)
{
    const int p = blockIdx.x * 8 + (threadIdx.x >> 5);
    const int lane = threadIdx.x & 31;
    const int b = g_sidx[p];
    const int e = g_class[b];
    constexpr int NC = BN / 32;

    float v[NC];
    float s = 0.f, q = 0.f;
    #pragma unroll
    for (int i = 0; i < NC; i++) {
        int col = lane + i * 32;
        size_t idx = (size_t)p * BN + col;
        float a = part[idx] + part[(size_t)BB * BN + idx]
                + part[2 * (size_t)BB * BN + idx] + part[3 * (size_t)BB * BN + idx]
                + bias[e * BN + col];
        v[i] = a;
        s += a;
        q += a * a;
    }
    #pragma unroll
    for (int o = 16; o; o >>= 1) {
        s += __shfl_xor_sync(~0u, s, o);
        q += __shfl_xor_sync(~0u, q, o);
    }
    float mu = s * (1.f / BN);
    float rs = rsqrtf(q * (1.f / BN) - mu * mu + LN_EPS);
    #pragma unroll
    for (int i = 0; i < NC; i++) {
        int col = lane + i * 32;
        float o = (v[i] - mu) * rs;
        out[(size_t)b * BN + col] = o;
        __nv_bfloat16 h = __float2bfloat16(o);
        __nv_bfloat16 l = __float2bfloat16(o - __bfloat162float(h));
        hh[(size_t)b * BN + col] = h;
        hl[(size_t)b * BN + col] = l;
    }
}

__global__ __launch_bounds__(256) void k_fcred(
    const float* __restrict__ b0, const float* __restrict__ b1,
    float* __restrict__ out)
{
    if (blockIdx.y == 0)
        fcred_impl<CC0>(g_pt0, b0, out + OFF_CL0, g_h0h, g_h0l);
    else
        fcred_impl<CC1>(g_pt1, b1, out + OFF_CL1, g_h1h, g_h1l);
}

// ===========================================================================
// Child proj: A resident, loop 4 p-tiles with double-buffered B.
// ===========================================================================
template <int CK>
__device__ __forceinline__ void tproj_impl(
    const __nv_bfloat16* __restrict__ ah, const __nv_bfloat16* __restrict__ al,
    const __nv_bfloat16* __restrict__ wh, const __nv_bfloat16* __restrict__ wl,
    const float* __restrict__ bias, float* __restrict__ out,
    int half4, char* sm, int* sidx)
{
    const int e = blockIdx.y;
    const int start = g_off[e] + blockIdx.x * 128;
    const int end = g_off[e + 1];
    if (start >= end) return;

    constexpr int NKC = CK / 64;
    const int t = threadIdx.x;
    const int wid = t >> 5, lane = t & 31;
    const int wr = wid & 3, wc = wid >> 2;
    const uint32_t sb = smem_u32(sm);
    constexpr uint32_t MSZ = (uint32_t)NKC * 16384u;
    constexpr uint32_t ABLK = 2 * MSZ;
    constexpr uint32_t BBLK = 2 * MSZ;
    const int pt0 = half4 * 4;

    if (t < 128) { int gi = start + t; sidx[t] = g_sidx[gi < end ? gi : end - 1]; }
    __syncthreads();

    #pragma unroll
    for (int kc = 0; kc < NKC; kc++) {
        #pragma unroll
        for (int i = 0; i < 4; i++) {
            int s = t + i * 256;
            int row = s >> 3, ch = s & 7;
            uint32_t off = (uint32_t)(kc * 16384 + row * 128 + ((ch * 16) ^ ((row & 7) << 4)));
            size_t ga = (size_t)sidx[row] * CK + kc * 64 + ch * 8;
            CPA(sb + off, ah + ga);
            CPA(sb + MSZ + off, al + ga);
        }
    }

    auto issueB = [&](int pi) {
        uint32_t base = sb + ABLK + (uint32_t)((pi & 1) * BBLK);
        int pt = pt0 + pi;
        #pragma unroll
        for (int kc = 0; kc < NKC; kc++) {
            #pragma unroll
            for (int i = 0; i < 4; i++) {
                int s = t + i * 256;
                int row = s >> 3, ch = s & 7;
                uint32_t off = (uint32_t)(kc * 16384 + row * 128
                                          + ((ch * 16) ^ ((row & 7) << 4)));
                size_t gb = ((size_t)(e * PP + pt * 128 + row)) * CK + kc * 64 + ch * 8;
                CPA(base + off, wh + gb);
                CPA(base + MSZ + off, wl + gb);
            }
        }
        CPA_COMMIT();
    };

    issueB(0);

    const int rA0 = wr * 32 + (lane >> 2);
    for (int pi = 0; pi < 4; pi++) {
        if (pi + 1 < 4) { issueB(pi + 1); CPA_WAIT(1); }
        else            { CPA_WAIT(0); }
        __syncthreads();

        float accA[32], accB[32];
        #pragma unroll
        for (int i = 0; i < 32; i++) { accA[i] = 0.f; accB[i] = 0.f; }

        uint32_t bbase = sb + ABLK + (uint32_t)((pi & 1) * BBLK);
        #pragma unroll
        for (int kc = 0; kc < NKC; kc++) {
            uint32_t ab = sb + (uint32_t)(kc * 16384);
            uint32_t bb = bbase + (uint32_t)(kc * 16384);
            mma_chunk2<4>(ab, ab + MSZ,
                          bb + (uint32_t)(wc * 64 * 128),
                          bb + MSZ + (uint32_t)(wc * 64 * 128),
                          wr * 32, lane, accA, accB);
        }

        int pt = pt0 + pi;
        #pragma unroll
        for (int g = 0; g < 4; g++) {
            #pragma unroll
            for (int hf = 0; hf < 2; hf++) {
                int pcol = pt * 128 + wc * 64 + (g * 2 + hf) * 8 + (lane & 3) * 2;
                float bv0 = bias[(size_t)e * PP + pcol];
                float bv1 = bias[(size_t)e * PP + pcol + 1];
                float* pa = accA + g * 8 + hf * 4;
                float* pb = accB + g * 8 + hf * 4;
                int rows[4] = {rA0, rA0 + 8, rA0 + 16, rA0 + 24};
                float* vals[4] = {pa, pa + 2, pb, pb + 2};
                #pragma unroll
                for (int rv = 0; rv < 4; rv++) {
                    if (start + rows[rv] < end) {
                        int b = sidx[rows[rv]];
                        *(float2*)&out[(size_t)b * PP + pcol] =
                            make_float2(vals[rv][0] + bv0, vals[rv][1] + bv1);
                    }
                }
            }
        }
        __syncthreads();
    }
}

#define PROJ_SMEM 196608

__global__ __launch_bounds__(256, 1) void k_tproj(
    const float* __restrict__ bpr0, const float* __restrict__ bpr1,
    float* __restrict__ out)
{
    extern __shared__ char smx[];
    __shared__ int sidx[128];
    const int level = blockIdx.z >> 1;
    const int half4 = blockIdx.z & 1;
    if (level == 0)
        tproj_impl<CC0>(g_h0h, g_h0l, g_wp0h, g_wp0l, bpr0, out + OFF_CP0, half4, smx, sidx);
    else
        tproj_impl<CC1>(g_h1h, g_h1l, g_wp1h, g_wp1l, bpr1, out + OFF_CP1, half4, smx, sidx);
}

// ---------------------------------------------------------------------------

extern "C" void kernel_launch(void* const* d_in, const int* in_sizes, int n_in,
                              void* d_out, int out_size) {
    const float* x       = (const float*)d_in[0];
    const float* pw_fc   = (const float*)d_in[1];
    const float* pb_fc   = (const float*)d_in[2];
    const float* pw_proj = (const float*)d_in[3];
    const float* pb_proj = (const float*)d_in[4];
    const float* cw_fc0  = (const float*)d_in[5];
    const float* cb_fc0  = (const float*)d_in[6];
    const float* cw_pr0  = (const float*)d_in[7];
    const float* cb_pr0  = (const float*)d_in[8];
    const float* cw_fc1  = (const float*)d_in[9];
    const float* cb_fc1  = (const float*)d_in[10];
    const float* cw_pr1  = (const float*)d_in[11];
    const float* cb_pr1  = (const float*)d_in[12];
    float* out = (float*)d_out;

    // one-time infra (created on the uncaptured correctness call; no device mem)
    static cudaStream_t sA = nullptr;
    static cudaEvent_t e0, evS, evC, evP;
    if (!sA) {
        cudaStreamCreate(&sA);
        cudaEventCreateWithFlags(&e0, cudaEventDisableTiming);
        cudaEventCreateWithFlags(&evS, cudaEventDisableTiming);
        cudaEventCreateWithFlags(&evC, cudaEventDisableTiming);
        cudaEventCreateWithFlags(&evP, cudaEventDisableTiming);
        cudaFuncSetAttribute(k_tfc, cudaFuncAttributeMaxDynamicSharedMemorySize, FC_SMEM);
        cudaFuncSetAttribute(k_tproj, cudaFuncAttributeMaxDynamicSharedMemorySize, PROJ_SMEM);
    }

    // fork
    cudaEventRecord(e0, 0);
    cudaStreamWaitEvent(sA, e0, 0);

    // branch 0 (default stream): parent fc -> bucket
    k_parent_fc<<<BB / 64, 128>>>(x, pw_fc, pb_fc, out + OFF_PL);
    k_scansc<<<1, 1024>>>();
    cudaEventRecord(evS, 0);

    // branch A: converts, then (after scansc? no — after parent_fc via evS) pproj
    k_cvtx<<<BB * DD / 4 / 256, 256, 0, sA>>>(x);
    k_cvtw<<<dim3(4096, 2), 256, 0, sA>>>(cw_fc0, cw_fc1, 0);
    cudaEventRecord(evC, sA);
    cudaStreamWaitEvent(sA, evS, 0);
    k_parent_proj<<<BB / 64, 256, 0, sA>>>(out + OFF_PL, pw_proj, pb_proj, out + OFF_PP);
    k_cvtw<<<dim3(2048, 2), 256, 0, sA>>>(cw_pr0, cw_pr1, 1);
    cudaEventRecord(evP, sA);

    // branch 0 continues: children (needs scansc + x/fc-weight cvts)
    cudaStreamWaitEvent(0, evC, 0);
    k_tfc<<<dim3(BB / 128, EE, 8), 256, FC_SMEM>>>();
    k_fcred<<<dim3(BB / 8, 2), 256>>>(cb_fc0, cb_fc1, out);
    cudaStreamWaitEvent(0, evP, 0);  // join: pproj + proj-weight cvt done
    k_tproj<<<dim3(BB / 128, EE, 4), 256, PROJ_SMEM>>>(cb_pr0, cb_pr1, out);
}

// round 13
// speedup vs baseline: 3.0350x; 1.1293x over previous
#include <cuda_runtime.h>
#include <cuda_bf16.h>
#include <cstdint>

#define BB 8192
#define DD 2048
#define EE 16
#define PP 1024
#define CC0 64
#define CC1 128
#define LN_EPS 1e-5f

#define OFF_PL  0
#define OFF_CL0 (BB*EE)
#define OFF_CL1 (OFF_CL0 + BB*CC0)
#define OFF_PP  (OFF_CL1 + BB*CC1)
#define OFF_CP0 (OFF_PP + BB*PP)
#define OFF_CP1 (OFF_CP0 + BB*PP)

typedef unsigned long long u64t;

// ------------------------- scratch globals -------------------------
__device__ int g_class[BB];
__device__ int g_off[EE + 1];
__device__ int g_sidx[BB];
__device__ int g_tiles[96];   // (e<<16)|tile, 128-row tiles
__device__ int g_ntiles;

__device__ __nv_bfloat16 g_xh[BB * DD], g_xl[BB * DD];
__device__ __nv_bfloat16 g_wfc0h[EE * CC0 * DD], g_wfc0l[EE * CC0 * DD];
__device__ __nv_bfloat16 g_wfc1h[EE * CC1 * DD], g_wfc1l[EE * CC1 * DD];
__device__ __nv_bfloat16 g_wp0h[EE * PP * CC0], g_wp0l[EE * PP * CC0];
__device__ __nv_bfloat16 g_wp1h[EE * PP * CC1], g_wp1l[EE * PP * CC1];
__device__ __nv_bfloat16 g_h0h[BB * CC0], g_h0l[BB * CC0];
__device__ __nv_bfloat16 g_h1h[BB * CC1], g_h1l[BB * CC1];

__device__ float g_pt0[4 * BB * CC0];
__device__ float g_pt1[4 * BB * CC1];

// ------------------------- asm helpers (sm_80+ generic) ---------------
__device__ __forceinline__ uint32_t smem_u32(const void* p) {
    uint32_t a;
    asm("{ .reg .u64 t; cvta.to.shared.u64 t, %1; cvt.u32.u64 %0, t; }"
        : "=r"(a) : "l"(p));
    return a;
}
#define CPA(dst, src) \
    asm volatile("cp.async.cg.shared.global [%0], [%1], 16;" :: "r"(dst), "l"(src) : "memory")
#define CPA_COMMIT() asm volatile("cp.async.commit_group;" ::: "memory")
#define CPA_WAIT(n)  asm volatile("cp.async.wait_group %0;" :: "n"(n) : "memory")
#define LDM4(r, addr) \
    asm volatile("ldmatrix.sync.aligned.m8n8.x4.shared.b16 {%0,%1,%2,%3}, [%4];" \
                 : "=r"((r)[0]), "=r"((r)[1]), "=r"((r)[2]), "=r"((r)[3]) : "r"(addr))

__device__ __forceinline__ void mma_bf16(float* c, const uint32_t* a,
                                         uint32_t b0, uint32_t b1) {
    asm volatile(
        "mma.sync.aligned.m16n8k16.row.col.f32.bf16.bf16.f32 "
        "{%0,%1,%2,%3}, {%4,%5,%6,%7}, {%8,%9}, {%0,%1,%2,%3};"
        : "+f"(c[0]), "+f"(c[1]), "+f"(c[2]), "+f"(c[3])
        : "r"(a[0]), "r"(a[1]), "r"(a[2]), "r"(a[3]), "r"(b0), "r"(b1));
}

// Two 16-row subtiles per warp sharing B fragments. NG groups of 16 cols.
template <int NG>
__device__ __forceinline__ void mma_chunk2(uint32_t AH, uint32_t AL,
                                           uint32_t BH, uint32_t BL,
                                           int m0, int lane,
                                           float* accA, float* accB) {
    const int arow0 = m0 + (lane & 15);
    const uint32_t aoff0 = (uint32_t)arow0 * 128u;
    const uint32_t aoff1 = aoff0 + 16u * 128u;
    const uint32_t axr = (uint32_t)((arow0 & 7) << 4);
    const uint32_t acb0 = (uint32_t)((lane >> 4) << 4);
    const int brl = ((lane >> 4) & 1) * 8 + (lane & 7);
    const uint32_t bcb0 = (uint32_t)(((lane >> 3) & 1) << 4);
    #pragma unroll
    for (int ks = 0; ks < 4; ks++) {
        uint32_t acb = ((uint32_t)(ks * 32) + acb0) ^ axr;
        uint32_t ah0[4], al0[4], ah1[4], al1[4];
        LDM4(ah0, AH + aoff0 + acb);
        LDM4(al0, AL + aoff0 + acb);
        LDM4(ah1, AH + aoff1 + acb);
        LDM4(al1, AL + aoff1 + acb);
        #pragma unroll
        for (int g = 0; g < NG; g++) {
            int brow = g * 16 + brl;
            uint32_t boff = (uint32_t)brow * 128u
                            + (((uint32_t)(ks * 32) + bcb0) ^ (uint32_t)((brow & 7) << 4));
            uint32_t bh[4], bl[4];
            LDM4(bh, BH + boff);
            LDM4(bl, BL + boff);
            float* c0 = accA + g * 8;
            float* c1 = accA + g * 8 + 4;
            mma_bf16(c0, ah0, bh[0], bh[1]);
            mma_bf16(c0, ah0, bl[0], bl[1]);
            mma_bf16(c0, al0, bh[0], bh[1]);
            mma_bf16(c1, ah0, bh[2], bh[3]);
            mma_bf16(c1, ah0, bl[2], bl[3]);
            mma_bf16(c1, al0, bh[2], bh[3]);
            float* d0 = accB + g * 8;
            float* d1 = accB + g * 8 + 4;
            mma_bf16(d0, ah1, bh[0], bh[1]);
            mma_bf16(d0, ah1, bl[0], bl[1]);
            mma_bf16(d0, al1, bh[0], bh[1]);
            mma_bf16(d1, ah1, bh[2], bh[3]);
            mma_bf16(d1, ah1, bl[2], bl[3]);
            mma_bf16(d1, al1, bh[2], bh[3]);
        }
    }
}

// ------------------------- cvt kernels -------------------------
__device__ __forceinline__ void cvt4(const float4 v, uint2& H, uint2& L) {
    float vv[4] = {v.x, v.y, v.z, v.w};
    uint32_t h[2], l[2];
    #pragma unroll
    for (int i = 0; i < 2; i++) {
        __nv_bfloat16 h0 = __float2bfloat16(vv[2 * i]);
        __nv_bfloat16 h1 = __float2bfloat16(vv[2 * i + 1]);
        float l0 = vv[2 * i] - __bfloat162float(h0);
        float l1 = vv[2 * i + 1] - __bfloat162float(h1);
        h[i] = ((uint32_t)__bfloat16_as_ushort(h1) << 16) | __bfloat16_as_ushort(h0);
        __nv_bfloat16 g0 = __float2bfloat16(l0);
        __nv_bfloat16 g1 = __float2bfloat16(l1);
        l[i] = ((uint32_t)__bfloat16_as_ushort(g1) << 16) | __bfloat16_as_ushort(g0);
    }
    H = make_uint2(h[0], h[1]);
    L = make_uint2(l[0], l[1]);
}

__global__ void k_cvtx(const float* __restrict__ src) {
    int i4 = blockIdx.x * 256 + threadIdx.x;
    if (i4 * 4 < BB * DD) {
        uint2 H, L;
        cvt4(((const float4*)src)[i4], H, L);
        ((uint2*)g_xh)[i4] = H;
        ((uint2*)g_xl)[i4] = L;
    }
}

__global__ void k_cvtw(const float* __restrict__ sa, const float* __restrict__ sb,
                       int mode) {
    const int sel = blockIdx.y;
    const float* src;
    __nv_bfloat16 *dh, *dl;
    int n;
    if (mode == 0) {
        if (sel == 0) { src = sa; dh = g_wfc0h; dl = g_wfc0l; n = EE * CC0 * DD; }
        else          { src = sb; dh = g_wfc1h; dl = g_wfc1l; n = EE * CC1 * DD; }
    } else {
        if (sel == 0) { src = sa; dh = g_wp0h; dl = g_wp0l; n = EE * PP * CC0; }
        else          { src = sb; dh = g_wp1h; dl = g_wp1l; n = EE * PP * CC1; }
    }
    int i4 = blockIdx.x * 256 + threadIdx.x;
    if (i4 * 4 < n) {
        uint2 H, L;
        cvt4(((const float4*)src)[i4], H, L);
        ((uint2*)dh)[i4] = H;
        ((uint2*)dl)[i4] = L;
    }
}

// histogram + scan + scatter + tile list, one block
__global__ void k_scansc() {
    __shared__ int hist[EE];
    __shared__ int off[EE];
    __shared__ int cur[EE];
    const int t = threadIdx.x;
    if (t < EE) hist[t] = 0;
    __syncthreads();
    for (int b = t; b < BB; b += 1024) atomicAdd(&hist[g_class[b]], 1);
    __syncthreads();
    if (t == 0) {
        int o = 0, nt = 0;
        for (int e = 0; e < EE; e++) {
            off[e] = o;
            g_off[e] = o;
            int m = (hist[e] + 127) >> 7;
            for (int i = 0; i < m; i++) g_tiles[nt++] = (e << 16) | i;
            o += hist[e];
        }
        g_off[EE] = o;
        g_ntiles = nt;
    }
    if (t < EE) cur[t] = 0;
    __syncthreads();
    for (int b = t; b < BB; b += 1024) {
        int e = g_class[b];
        int pos = off[e] + atomicAdd(&cur[e], 1);
        g_sidx[pos] = b;
    }
}

// ------------------------- parent FC (exact fp32), BM=32 ------------------
__global__ __launch_bounds__(128) void k_parent_fc(
    const float* __restrict__ x, const float* __restrict__ w,
    const float* __restrict__ bias, float* __restrict__ out_pl)
{
    __shared__ __align__(16) float xs[32][36];
    __shared__ __align__(16) float ws[32][20];
    __shared__ float spart[4][32][17];

    const int t = threadIdx.x;
    const int rowg = t & 7;
    const int eg = (t >> 3) & 3;
    const int kg = t >> 5;
    const int brow = blockIdx.x * 32;

    float acc[4][4];
    #pragma unroll
    for (int i = 0; i < 4; i++)
        #pragma unroll
        for (int j = 0; j < 4; j++) acc[i][j] = 0.f;

    for (int kt = 0; kt < DD / 32; kt++) {
        float4 rx[2];
        float4 rw;
        #pragma unroll
        for (int i = 0; i < 2; i++) {
            int s = t + i * 128;
            int row = s >> 3, kq = s & 7;
            rx[i] = *(const float4*)&x[(size_t)(brow + row) * DD + kt * 32 + kq * 4];
        }
        {
            int e2 = t >> 3, kq = t & 7;
            rw = *(const float4*)&w[(size_t)e2 * DD + kt * 32 + kq * 4];
        }
        __syncthreads();
        #pragma unroll
        for (int i = 0; i < 2; i++) {
            int s = t + i * 128;
            int row = s >> 3, kq = s & 7;
            xs[kq * 4 + 0][row] = rx[i].x;
            xs[kq * 4 + 1][row] = rx[i].y;
            xs[kq * 4 + 2][row] = rx[i].z;
            xs[kq * 4 + 3][row] = rx[i].w;
        }
        {
            int e2 = t >> 3, kq = t & 7;
            ws[kq * 4 + 0][e2] = rw.x;
            ws[kq * 4 + 1][e2] = rw.y;
            ws[kq * 4 + 2][e2] = rw.z;
            ws[kq * 4 + 3][e2] = rw.w;
        }
        __syncthreads();
        #pragma unroll
        for (int kk2 = 0; kk2 < 8; kk2++) {
            int kk = kg * 8 + kk2;
            float4 a0 = *(const float4*)&xs[kk][rowg * 4];
            float4 bq = *(const float4*)&ws[kk][eg * 4];
            float av[4] = {a0.x, a0.y, a0.z, a0.w};
            float bv[4] = {bq.x, bq.y, bq.z, bq.w};
            #pragma unroll
            for (int i = 0; i < 4; i++)
                #pragma unroll
                for (int j = 0; j < 4; j++) acc[i][j] += av[i] * bv[j];
        }
        __syncthreads();
    }

    #pragma unroll
    for (int i = 0; i < 4; i++) {
        int r = rowg * 4 + i;
        #pragma unroll
        for (int j = 0; j < 4; j++) spart[kg][r][eg * 4 + j] = acc[i][j];
    }
    __syncthreads();

    if (t < 32) {
        int r = t;
        int b = brow + r;
        float z[16];
        float mu = 0.f;
        #pragma unroll
        for (int e2 = 0; e2 < 16; e2++) {
            float v = spart[0][r][e2] + spart[1][r][e2] + spart[2][r][e2] + spart[3][r][e2]
                      + bias[e2];
            z[e2] = v;
            mu += v;
        }
        mu *= (1.f / 16.f);
        float var = 0.f;
        #pragma unroll
        for (int e2 = 0; e2 < 16; e2++) { float d = z[e2] - mu; var += d * d; }
        var *= (1.f / 16.f);
        float rs = rsqrtf(var + LN_EPS);

        float best = z[0];
        int cls = 0;
        #pragma unroll
        for (int e2 = 1; e2 < 16; e2++)
            if (z[e2] > best) { best = z[e2]; cls = e2; }

        #pragma unroll
        for (int q = 0; q < 4; q++) {
            float4 o = make_float4((z[q * 4 + 0] - mu) * rs, (z[q * 4 + 1] - mu) * rs,
                                   (z[q * 4 + 2] - mu) * rs, (z[q * 4 + 3] - mu) * rs);
            *(float4*)&out_pl[(size_t)b * 16 + q * 4] = o;
        }
        g_class[b] = cls;
    }
}

// ------------------------- parent proj -------------------------
__global__ __launch_bounds__(256) void k_parent_proj(
    const float* __restrict__ pl, const float* __restrict__ w,
    const float* __restrict__ bias, float* __restrict__ out)
{
    __shared__ __align__(16) float spl[64][20];
    const int t = threadIdx.x;
    const int brow = blockIdx.x * 64;

    {
        int row = t >> 2, q = t & 3;
        float4 g = *(const float4*)&pl[(size_t)(brow + row) * 16 + q * 4];
        spl[row][q * 4 + 0] = g.x;
        spl[row][q * 4 + 1] = g.y;
        spl[row][q * 4 + 2] = g.z;
        spl[row][q * 4 + 3] = g.w;
    }
    __syncthreads();

    for (int pass = 0; pass < 2; pass++) {
        int p0 = pass * 512 + t * 2;
        float w0[16], w1[16];
        #pragma unroll
        for (int q = 0; q < 4; q++) {
            float4 a = *(const float4*)&w[(size_t)p0 * 16 + q * 4];
            w0[q * 4 + 0] = a.x; w0[q * 4 + 1] = a.y; w0[q * 4 + 2] = a.z; w0[q * 4 + 3] = a.w;
            float4 c = *(const float4*)&w[(size_t)(p0 + 1) * 16 + q * 4];
            w1[q * 4 + 0] = c.x; w1[q * 4 + 1] = c.y; w1[q * 4 + 2] = c.z; w1[q * 4 + 3] = c.w;
        }
        float b0 = bias[p0], b1 = bias[p0 + 1];

        for (int r = 0; r < 64; r++) {
            float a0 = b0, a1 = b1;
            #pragma unroll
            for (int q = 0; q < 4; q++) {
                float4 v = *(const float4*)&spl[r][q * 4];
                a0 += v.x * w0[q * 4 + 0] + v.y * w0[q * 4 + 1] + v.z * w0[q * 4 + 2] + v.w * w0[q * 4 + 3];
                a1 += v.x * w1[q * 4 + 0] + v.y * w1[q * 4 + 1] + v.z * w1[q * 4 + 2] + v.w * w1[q * 4 + 3];
            }
            float2 o = make_float2(a0, a1);
            *(float2*)&out[(size_t)(brow + r) * PP + p0] = o;
        }
    }
}

// ===========================================================================
// Child FC split-K GEMM, compact tile list. grid (80, 1, 8).
// ===========================================================================
template <int BN>
__device__ __forceinline__ void tfc_impl(
    const __nv_bfloat16* __restrict__ xh, const __nv_bfloat16* __restrict__ xl,
    const __nv_bfloat16* __restrict__ wh, const __nv_bfloat16* __restrict__ wl,
    float* __restrict__ part, int ks, char* sm, int* sidx)
{
    if (blockIdx.x >= (unsigned)g_ntiles) return;
    const int pk = g_tiles[blockIdx.x];
    const int e = pk >> 16;
    const int start = g_off[e] + (pk & 0xffff) * 128;
    const int end = g_off[e + 1];

    const int t = threadIdx.x;
    const int wid = t >> 5, lane = t & 31;
    const int wr = wid & 3, wc = wid >> 2;
    const uint32_t sb = smem_u32(sm);
    const int kbase = ks * 512;

    constexpr int AH0 = 0, AL0 = 16384, BH0 = 32768, BL0 = 32768 + BN * 128;
    constexpr int BUF = 32768 + 2 * BN * 128;
    constexpr int NGW = BN / 32;

    if (t < 128) { int gi = start + t; sidx[t] = g_sidx[gi < end ? gi : end - 1]; }
    __syncthreads();

    auto issue = [&](int kt) {
        uint32_t base = sb + (uint32_t)((kt & 1) * BUF);
        #pragma unroll
        for (int i = 0; i < 4; i++) {
            int d = t + i * 256;
            int row = d >> 3, ch = d & 7;
            uint32_t off = (uint32_t)(row * 128 + ((ch * 16) ^ ((row & 7) << 4)));
            size_t g = (size_t)sidx[row] * DD + kbase + kt * 64 + ch * 8;
            CPA(base + AH0 + off, xh + g);
            CPA(base + AL0 + off, xl + g);
        }
        #pragma unroll
        for (int i = 0; i < BN / 32; i++) {
            int d = t + i * 256;
            int row = d >> 3, ch = d & 7;
            uint32_t off = (uint32_t)(row * 128 + ((ch * 16) ^ ((row & 7) << 4)));
            size_t g = ((size_t)e * BN + row) * DD + kbase + kt * 64 + ch * 8;
            CPA(base + BH0 + off, wh + g);
            CPA(base + BL0 + off, wl + g);
        }
        CPA_COMMIT();
    };

    float accA[NGW * 8], accB[NGW * 8];
    #pragma unroll
    for (int i = 0; i < NGW * 8; i++) { accA[i] = 0.f; accB[i] = 0.f; }

    issue(0);
    const int NKT = 8;
    for (int kt = 0; kt < NKT; kt++) {
        if (kt + 1 < NKT) { issue(kt + 1); CPA_WAIT(1); }
        else              { CPA_WAIT(0); }
        __syncthreads();
        uint32_t base = sb + (uint32_t)((kt & 1) * BUF);
        mma_chunk2<NGW>(base + AH0, base + AL0,
                        base + BH0 + (uint32_t)(wc * (BN / 2) * 128),
                        base + BL0 + (uint32_t)(wc * (BN / 2) * 128),
                        wr * 32, lane, accA, accB);
        __syncthreads();
    }

    const int rA0 = wr * 32 + (lane >> 2);
    #pragma unroll
    for (int g = 0; g < NGW; g++) {
        #pragma unroll
        for (int half = 0; half < 2; half++) {
            int col = wc * (BN / 2) + (g * 2 + half) * 8 + (lane & 3) * 2;
            float* pa = accA + g * 8 + half * 4;
            float* pb = accB + g * 8 + half * 4;
            int rows[4] = {rA0, rA0 + 8, rA0 + 16, rA0 + 24};
            float* vals[4] = {pa, pa + 2, pb, pb + 2};
            #pragma unroll
            for (int rv = 0; rv < 4; rv++) {
                int p = start + rows[rv];
                if (p < end)
                    *(float2*)&part[(size_t)ks * BB * BN + (size_t)p * BN + col] =
                        make_float2(vals[rv][0], vals[rv][1]);
            }
        }
    }
}

#define FC_SMEM 131072

__global__ __launch_bounds__(256, 1) void k_tfc() {
    extern __shared__ char smx[];
    __shared__ int sidx[128];
    if (blockIdx.z < 4)
        tfc_impl<CC1>(g_xh, g_xl, g_wfc1h, g_wfc1l, g_pt1, blockIdx.z, smx, sidx);
    else
        tfc_impl<CC0>(g_xh, g_xl, g_wfc0h, g_wfc0l, g_pt0, blockIdx.z - 4, smx, sidx);
}

// ===========================================================================
// FC reduce: sum 4 partials + bias + LN + write cl + h hi/lo. 1 warp per row.
// ===========================================================================
template <int BN>
__device__ __forceinline__ void fcred_impl(
    const float* __restrict__ part, const float* __restrict__ bias,
    float* __restrict__ out, __nv_bfloat16* __restrict__ hh,
    __nv_bfloat16* __restrict__ hl)
{
    const int p = blockIdx.x * 8 + (threadIdx.x >> 5);
    const int lane = threadIdx.x & 31;
    const int b = g_sidx[p];
    const int e = g_class[b];
    constexpr int NC = BN / 32;

    float v[NC];
    float s = 0.f, q = 0.f;
    #pragma unroll
    for (int i = 0; i < NC; i++) {
        int col = lane + i * 32;
        size_t idx = (size_t)p * BN + col;
        float a = part[idx] + part[(size_t)BB * BN + idx]
                + part[2 * (size_t)BB * BN + idx] + part[3 * (size_t)BB * BN + idx]
                + bias[e * BN + col];
        v[i] = a;
        s += a;
        q += a * a;
    }
    #pragma unroll
    for (int o = 16; o; o >>= 1) {
        s += __shfl_xor_sync(~0u, s, o);
        q += __shfl_xor_sync(~0u, q, o);
    }
    float mu = s * (1.f / BN);
    float rs = rsqrtf(q * (1.f / BN) - mu * mu + LN_EPS);
    #pragma unroll
    for (int i = 0; i < NC; i++) {
        int col = lane + i * 32;
        float o = (v[i] - mu) * rs;
        out[(size_t)b * BN + col] = o;
        __nv_bfloat16 h = __float2bfloat16(o);
        __nv_bfloat16 l = __float2bfloat16(o - __bfloat162float(h));
        hh[(size_t)b * BN + col] = h;
        hl[(size_t)b * BN + col] = l;
    }
}

__global__ __launch_bounds__(256) void k_fcred(
    const float* __restrict__ b0, const float* __restrict__ b1,
    float* __restrict__ out)
{
    if (blockIdx.y == 0)
        fcred_impl<CC0>(g_pt0, b0, out + OFF_CL0, g_h0h, g_h0l);
    else
        fcred_impl<CC1>(g_pt1, b1, out + OFF_CL1, g_h1h, g_h1l);
}

// ===========================================================================
// Child proj: compact tiles, A resident, 4 p-tiles double-buffered B.
// grid (80, 1, 4): z = level*2 + half.
// ===========================================================================
template <int CK>
__device__ __forceinline__ void tproj_impl(
    const __nv_bfloat16* __restrict__ ah, const __nv_bfloat16* __restrict__ al,
    const __nv_bfloat16* __restrict__ wh, const __nv_bfloat16* __restrict__ wl,
    const float* __restrict__ bias, float* __restrict__ out,
    int half4, char* sm, int* sidx)
{
    if (blockIdx.x >= (unsigned)g_ntiles) return;
    const int pk = g_tiles[blockIdx.x];
    const int e = pk >> 16;
    const int start = g_off[e] + (pk & 0xffff) * 128;
    const int end = g_off[e + 1];

    constexpr int NKC = CK / 64;
    const int t = threadIdx.x;
    const int wid = t >> 5, lane = t & 31;
    const int wr = wid & 3, wc = wid >> 2;
    const uint32_t sb = smem_u32(sm);
    constexpr uint32_t MSZ = (uint32_t)NKC * 16384u;
    constexpr uint32_t ABLK = 2 * MSZ;
    constexpr uint32_t BBLK = 2 * MSZ;
    const int pt0 = half4 * 4;

    if (t < 128) { int gi = start + t; sidx[t] = g_sidx[gi < end ? gi : end - 1]; }
    __syncthreads();

    #pragma unroll
    for (int kc = 0; kc < NKC; kc++) {
        #pragma unroll
        for (int i = 0; i < 4; i++) {
            int s = t + i * 256;
            int row = s >> 3, ch = s & 7;
            uint32_t off = (uint32_t)(kc * 16384 + row * 128 + ((ch * 16) ^ ((row & 7) << 4)));
            size_t ga = (size_t)sidx[row] * CK + kc * 64 + ch * 8;
            CPA(sb + off, ah + ga);
            CPA(sb + MSZ + off, al + ga);
        }
    }

    auto issueB = [&](int pi) {
        uint32_t base = sb + ABLK + (uint32_t)((pi & 1) * BBLK);
        int pt = pt0 + pi;
        #pragma unroll
        for (int kc = 0; kc < NKC; kc++) {
            #pragma unroll
            for (int i = 0; i < 4; i++) {
                int s = t + i * 256;
                int row = s >> 3, ch = s & 7;
                uint32_t off = (uint32_t)(kc * 16384 + row * 128
                                          + ((ch * 16) ^ ((row & 7) << 4)));
                size_t gb = ((size_t)(e * PP + pt * 128 + row)) * CK + kc * 64 + ch * 8;
                CPA(base + off, wh + gb);
                CPA(base + MSZ + off, wl + gb);
            }
        }
        CPA_COMMIT();
    };

    issueB(0);

    const int rA0 = wr * 32 + (lane >> 2);
    for (int pi = 0; pi < 4; pi++) {
        if (pi + 1 < 4) { issueB(pi + 1); CPA_WAIT(1); }
        else            { CPA_WAIT(0); }
        __syncthreads();

        float accA[32], accB[32];
        #pragma unroll
        for (int i = 0; i < 32; i++) { accA[i] = 0.f; accB[i] = 0.f; }

        uint32_t bbase = sb + ABLK + (uint32_t)((pi & 1) * BBLK);
        #pragma unroll
        for (int kc = 0; kc < NKC; kc++) {
            uint32_t ab = sb + (uint32_t)(kc * 16384);
            uint32_t bb = bbase + (uint32_t)(kc * 16384);
            mma_chunk2<4>(ab, ab + MSZ,
                          bb + (uint32_t)(wc * 64 * 128),
                          bb + MSZ + (uint32_t)(wc * 64 * 128),
                          wr * 32, lane, accA, accB);
        }

        int pt = pt0 + pi;
        #pragma unroll
        for (int g = 0; g < 4; g++) {
            #pragma unroll
            for (int hf = 0; hf < 2; hf++) {
                int pcol = pt * 128 + wc * 64 + (g * 2 + hf) * 8 + (lane & 3) * 2;
                float bv0 = bias[(size_t)e * PP + pcol];
                float bv1 = bias[(size_t)e * PP + pcol + 1];
                float* pa = accA + g * 8 + hf * 4;
                float* pb = accB + g * 8 + hf * 4;
                int rows[4] = {rA0, rA0 + 8, rA0 + 16, rA0 + 24};
                float* vals[4] = {pa, pa + 2, pb, pb + 2};
                #pragma unroll
                for (int rv = 0; rv < 4; rv++) {
                    if (start + rows[rv] < end) {
                        int b = sidx[rows[rv]];
                        *(float2*)&out[(size_t)b * PP + pcol] =
                            make_float2(vals[rv][0] + bv0, vals[rv][1] + bv1);
                    }
                }
            }
        }
        __syncthreads();
    }
}

#define PROJ_SMEM 196608

__global__ __launch_bounds__(256, 1) void k_tproj(
    const float* __restrict__ bpr0, const float* __restrict__ bpr1,
    float* __restrict__ out)
{
    extern __shared__ char smx[];
    __shared__ int sidx[128];
    const int level = blockIdx.z >> 1;
    const int half4 = blockIdx.z & 1;
    if (level == 0)
        tproj_impl<CC0>(g_h0h, g_h0l, g_wp0h, g_wp0l, bpr0, out + OFF_CP0, half4, smx, sidx);
    else
        tproj_impl<CC1>(g_h1h, g_h1l, g_wp1h, g_wp1l, bpr1, out + OFF_CP1, half4, smx, sidx);
}

// ---------------------------------------------------------------------------

extern "C" void kernel_launch(void* const* d_in, const int* in_sizes, int n_in,
                              void* d_out, int out_size) {
    const float* x       = (const float*)d_in[0];
    const float* pw_fc   = (const float*)d_in[1];
    const float* pb_fc   = (const float*)d_in[2];
    const float* pw_proj = (const float*)d_in[3];
    const float* pb_proj = (const float*)d_in[4];
    const float* cw_fc0  = (const float*)d_in[5];
    const float* cb_fc0  = (const float*)d_in[6];
    const float* cw_pr0  = (const float*)d_in[7];
    const float* cb_pr0  = (const float*)d_in[8];
    const float* cw_fc1  = (const float*)d_in[9];
    const float* cb_fc1  = (const float*)d_in[10];
    const float* cw_pr1  = (const float*)d_in[11];
    const float* cb_pr1  = (const float*)d_in[12];
    float* out = (float*)d_out;

    static cudaStream_t sA = nullptr;
    static cudaEvent_t e0, evS, evC, evP;
    if (!sA) {
        cudaStreamCreate(&sA);
        cudaEventCreateWithFlags(&e0, cudaEventDisableTiming);
        cudaEventCreateWithFlags(&evS, cudaEventDisableTiming);
        cudaEventCreateWithFlags(&evC, cudaEventDisableTiming);
        cudaEventCreateWithFlags(&evP, cudaEventDisableTiming);
        cudaFuncSetAttribute(k_tfc, cudaFuncAttributeMaxDynamicSharedMemorySize, FC_SMEM);
        cudaFuncSetAttribute(k_tproj, cudaFuncAttributeMaxDynamicSharedMemorySize, PROJ_SMEM);
    }

    cudaEventRecord(e0, 0);
    cudaStreamWaitEvent(sA, e0, 0);

    // launch 1-2 (stream 0): parent fc -> bucket/tiles
    k_parent_fc<<<BB / 32, 128>>>(x, pw_fc, pb_fc, out + OFF_PL);
    k_scansc<<<1, 1024>>>();
    cudaEventRecord(evS, 0);

    // launches 3-5 (stream A)
    k_cvtx<<<BB * DD / 4 / 256, 256, 0, sA>>>(x);
    k_cvtw<<<dim3(4096, 2), 256, 0, sA>>>(cw_fc0, cw_fc1, 0);
    cudaEventRecord(evC, sA);
    cudaStreamWaitEvent(sA, evS, 0);
    k_parent_proj<<<BB / 64, 256, 0, sA>>>(out + OFF_PL, pw_proj, pb_proj, out + OFF_PP);

    // launch 6 (stream 0): the big child fc GEMM — ncu -s 5 profiles this
    cudaStreamWaitEvent(0, evC, 0);
    k_tfc<<<dim3(80, 1, 8), 256, FC_SMEM>>>();

    // launch 7 (stream A)
    k_cvtw<<<dim3(2048, 2), 256, 0, sA>>>(cw_pr0, cw_pr1, 1);
    cudaEventRecord(evP, sA);

    // launches 8-9 (stream 0)
    k_fcred<<<dim3(BB / 8, 2), 256>>>(cb_fc0, cb_fc1, out);
    cudaStreamWaitEvent(0, evP, 0);
    k_tproj<<<dim3(80, 1, 4), 256, PROJ_SMEM>>>(cb_pr0, cb_pr1, out);
}

// round 14
// speedup vs baseline: 3.2898x; 1.0840x over previous
#include <cuda_runtime.h>
#include <cuda_bf16.h>
#include <cuda_fp16.h>
#include <cstdint>

#define BB 8192
#define DD 2048
#define EE 16
#define PP 1024
#define CC0 64
#define CC1 128
#define LN_EPS 1e-5f

#define OFF_PL  0
#define OFF_CL0 (BB*EE)
#define OFF_CL1 (OFF_CL0 + BB*CC0)
#define OFF_PP  (OFF_CL1 + BB*CC1)
#define OFF_CP0 (OFF_PP + BB*PP)
#define OFF_CP1 (OFF_CP0 + BB*PP)

typedef unsigned long long u64t;

// ------------------------- scratch globals -------------------------
__device__ int g_class[BB];
__device__ int g_off[EE + 1];
__device__ int g_sidx[BB];
__device__ int g_tiles[96];
__device__ int g_ntiles;

__device__ __nv_bfloat16 g_xh[BB * DD], g_xl[BB * DD];
__device__ __nv_bfloat16 g_wfc0h[EE * CC0 * DD], g_wfc0l[EE * CC0 * DD];
__device__ __nv_bfloat16 g_wfc1h[EE * CC1 * DD], g_wfc1l[EE * CC1 * DD];
// proj path: plain fp16 (terminal outputs tolerate ~4e-4)
__device__ __half g_wp0f[EE * PP * CC0], g_wp1f[EE * PP * CC1];
__device__ __half g_h0f[BB * CC0], g_h1f[BB * CC1];

__device__ float g_pt0[4 * BB * CC0];
__device__ float g_pt1[4 * BB * CC1];

// ------------------------- asm helpers (sm_80+ generic) ---------------
__device__ __forceinline__ uint32_t smem_u32(const void* p) {
    uint32_t a;
    asm("{ .reg .u64 t; cvta.to.shared.u64 t, %1; cvt.u32.u64 %0, t; }"
        : "=r"(a) : "l"(p));
    return a;
}
#define CPA(dst, src) \
    asm volatile("cp.async.cg.shared.global [%0], [%1], 16;" :: "r"(dst), "l"(src) : "memory")
#define CPA_COMMIT() asm volatile("cp.async.commit_group;" ::: "memory")
#define CPA_WAIT(n)  asm volatile("cp.async.wait_group %0;" :: "n"(n) : "memory")
#define LDM4(r, addr) \
    asm volatile("ldmatrix.sync.aligned.m8n8.x4.shared.b16 {%0,%1,%2,%3}, [%4];" \
                 : "=r"((r)[0]), "=r"((r)[1]), "=r"((r)[2]), "=r"((r)[3]) : "r"(addr))

__device__ __forceinline__ void mma_bf16(float* c, const uint32_t* a,
                                         uint32_t b0, uint32_t b1) {
    asm volatile(
        "mma.sync.aligned.m16n8k16.row.col.f32.bf16.bf16.f32 "
        "{%0,%1,%2,%3}, {%4,%5,%6,%7}, {%8,%9}, {%0,%1,%2,%3};"
        : "+f"(c[0]), "+f"(c[1]), "+f"(c[2]), "+f"(c[3])
        : "r"(a[0]), "r"(a[1]), "r"(a[2]), "r"(a[3]), "r"(b0), "r"(b1));
}
__device__ __forceinline__ void mma_f16(float* c, const uint32_t* a,
                                        uint32_t b0, uint32_t b1) {
    asm volatile(
        "mma.sync.aligned.m16n8k16.row.col.f32.f16.f16.f32 "
        "{%0,%1,%2,%3}, {%4,%5,%6,%7}, {%8,%9}, {%0,%1,%2,%3};"
        : "+f"(c[0]), "+f"(c[1]), "+f"(c[2]), "+f"(c[3])
        : "r"(a[0]), "r"(a[1]), "r"(a[2]), "r"(a[3]), "r"(b0), "r"(b1));
}

// bf16 split-3, two 16-row subtiles sharing B fragments. NG groups of 16 cols.
template <int NG>
__device__ __forceinline__ void mma_chunk2(uint32_t AH, uint32_t AL,
                                           uint32_t BH, uint32_t BL,
                                           int m0, int lane,
                                           float* accA, float* accB) {
    const int arow0 = m0 + (lane & 15);
    const uint32_t aoff0 = (uint32_t)arow0 * 128u;
    const uint32_t aoff1 = aoff0 + 16u * 128u;
    const uint32_t axr = (uint32_t)((arow0 & 7) << 4);
    const uint32_t acb0 = (uint32_t)((lane >> 4) << 4);
    const int brl = ((lane >> 4) & 1) * 8 + (lane & 7);
    const uint32_t bcb0 = (uint32_t)(((lane >> 3) & 1) << 4);
    #pragma unroll
    for (int ks = 0; ks < 4; ks++) {
        uint32_t acb = ((uint32_t)(ks * 32) + acb0) ^ axr;
        uint32_t ah0[4], al0[4], ah1[4], al1[4];
        LDM4(ah0, AH + aoff0 + acb);
        LDM4(al0, AL + aoff0 + acb);
        LDM4(ah1, AH + aoff1 + acb);
        LDM4(al1, AL + aoff1 + acb);
        #pragma unroll
        for (int g = 0; g < NG; g++) {
            int brow = g * 16 + brl;
            uint32_t boff = (uint32_t)brow * 128u
                            + (((uint32_t)(ks * 32) + bcb0) ^ (uint32_t)((brow & 7) << 4));
            uint32_t bh[4], bl[4];
            LDM4(bh, BH + boff);
            LDM4(bl, BL + boff);
            float* c0 = accA + g * 8;
            float* c1 = accA + g * 8 + 4;
            mma_bf16(c0, ah0, bh[0], bh[1]);
            mma_bf16(c0, ah0, bl[0], bl[1]);
            mma_bf16(c0, al0, bh[0], bh[1]);
            mma_bf16(c1, ah0, bh[2], bh[3]);
            mma_bf16(c1, ah0, bl[2], bl[3]);
            mma_bf16(c1, al0, bh[2], bh[3]);
            float* d0 = accB + g * 8;
            float* d1 = accB + g * 8 + 4;
            mma_bf16(d0, ah1, bh[0], bh[1]);
            mma_bf16(d0, ah1, bl[0], bl[1]);
            mma_bf16(d0, al1, bh[0], bh[1]);
            mma_bf16(d1, ah1, bh[2], bh[3]);
            mma_bf16(d1, ah1, bl[2], bl[3]);
            mma_bf16(d1, al1, bh[2], bh[3]);
        }
    }
}

// plain fp16, two 16-row subtiles sharing B fragments. NG groups of 16 cols.
template <int NG>
__device__ __forceinline__ void mma_chunk2f(uint32_t A, uint32_t B,
                                            int m0, int lane,
                                            float* accA, float* accB) {
    const int arow0 = m0 + (lane & 15);
    const uint32_t aoff0 = (uint32_t)arow0 * 128u;
    const uint32_t aoff1 = aoff0 + 16u * 128u;
    const uint32_t axr = (uint32_t)((arow0 & 7) << 4);
    const uint32_t acb0 = (uint32_t)((lane >> 4) << 4);
    const int brl = ((lane >> 4) & 1) * 8 + (lane & 7);
    const uint32_t bcb0 = (uint32_t)(((lane >> 3) & 1) << 4);
    #pragma unroll
    for (int ks = 0; ks < 4; ks++) {
        uint32_t acb = ((uint32_t)(ks * 32) + acb0) ^ axr;
        uint32_t a0[4], a1[4];
        LDM4(a0, A + aoff0 + acb);
        LDM4(a1, A + aoff1 + acb);
        #pragma unroll
        for (int g = 0; g < NG; g++) {
            int brow = g * 16 + brl;
            uint32_t boff = (uint32_t)brow * 128u
                            + (((uint32_t)(ks * 32) + bcb0) ^ (uint32_t)((brow & 7) << 4));
            uint32_t b[4];
            LDM4(b, B + boff);
            mma_f16(accA + g * 8,     a0, b[0], b[1]);
            mma_f16(accA + g * 8 + 4, a0, b[2], b[3]);
            mma_f16(accB + g * 8,     a1, b[0], b[1]);
            mma_f16(accB + g * 8 + 4, a1, b[2], b[3]);
        }
    }
}

// ------------------------- cvt kernels -------------------------
__device__ __forceinline__ void cvt4(const float4 v, uint2& H, uint2& L) {
    float vv[4] = {v.x, v.y, v.z, v.w};
    uint32_t h[2], l[2];
    #pragma unroll
    for (int i = 0; i < 2; i++) {
        __nv_bfloat16 h0 = __float2bfloat16(vv[2 * i]);
        __nv_bfloat16 h1 = __float2bfloat16(vv[2 * i + 1]);
        float l0 = vv[2 * i] - __bfloat162float(h0);
        float l1 = vv[2 * i + 1] - __bfloat162float(h1);
        h[i] = ((uint32_t)__bfloat16_as_ushort(h1) << 16) | __bfloat16_as_ushort(h0);
        __nv_bfloat16 g0 = __float2bfloat16(l0);
        __nv_bfloat16 g1 = __float2bfloat16(l1);
        l[i] = ((uint32_t)__bfloat16_as_ushort(g1) << 16) | __bfloat16_as_ushort(g0);
    }
    H = make_uint2(h[0], h[1]);
    L = make_uint2(l[0], l[1]);
}

__global__ void k_cvtx(const float* __restrict__ src) {
    int i4 = blockIdx.x * 256 + threadIdx.x;
    if (i4 * 4 < BB * DD) {
        uint2 H, L;
        cvt4(((const float4*)src)[i4], H, L);
        ((uint2*)g_xh)[i4] = H;
        ((uint2*)g_xl)[i4] = L;
    }
}

// fc weights -> bf16 hi/lo
__global__ void k_cvtwfc(const float* __restrict__ sa, const float* __restrict__ sb) {
    const int sel = blockIdx.y;
    const float* src = sel ? sb : sa;
    __nv_bfloat16* dh = sel ? g_wfc1h : g_wfc0h;
    __nv_bfloat16* dl = sel ? g_wfc1l : g_wfc0l;
    const int n = sel ? EE * CC1 * DD : EE * CC0 * DD;
    int i4 = blockIdx.x * 256 + threadIdx.x;
    if (i4 * 4 < n) {
        uint2 H, L;
        cvt4(((const float4*)src)[i4], H, L);
        ((uint2*)dh)[i4] = H;
        ((uint2*)dl)[i4] = L;
    }
}

// proj weights -> plain fp16
__global__ void k_cvtwpr(const float* __restrict__ sa, const float* __restrict__ sb) {
    const int sel = blockIdx.y;
    const float* src = sel ? sb : sa;
    __half* df = sel ? g_wp1f : g_wp0f;
    const int n = sel ? EE * PP * CC1 : EE * PP * CC0;
    int i4 = blockIdx.x * 256 + threadIdx.x;
    if (i4 * 4 < n) {
        float4 v = ((const float4*)src)[i4];
        __half2 p0 = __floats2half2_rn(v.x, v.y);
        __half2 p1 = __floats2half2_rn(v.z, v.w);
        ((__half2*)df)[i4 * 2 + 0] = p0;
        ((__half2*)df)[i4 * 2 + 1] = p1;
    }
}

// histogram + scan + scatter + tile list, one block
__global__ void k_scansc() {
    __shared__ int hist[EE];
    __shared__ int off[EE];
    __shared__ int cur[EE];
    const int t = threadIdx.x;
    if (t < EE) hist[t] = 0;
    __syncthreads();
    for (int b = t; b < BB; b += 1024) atomicAdd(&hist[g_class[b]], 1);
    __syncthreads();
    if (t == 0) {
        int o = 0, nt = 0;
        for (int e = 0; e < EE; e++) {
            off[e] = o;
            g_off[e] = o;
            int m = (hist[e] + 127) >> 7;
            for (int i = 0; i < m; i++) g_tiles[nt++] = (e << 16) | i;
            o += hist[e];
        }
        g_off[EE] = o;
        g_ntiles = nt;
    }
    if (t < EE) cur[t] = 0;
    __syncthreads();
    for (int b = t; b < BB; b += 1024) {
        int e = g_class[b];
        int pos = off[e] + atomicAdd(&cur[e], 1);
        g_sidx[pos] = b;
    }
}

// ------------------------- parent FC (exact fp32), BM=32 ------------------
__global__ __launch_bounds__(128) void k_parent_fc(
    const float* __restrict__ x, const float* __restrict__ w,
    const float* __restrict__ bias, float* __restrict__ out_pl)
{
    __shared__ __align__(16) float xs[32][36];
    __shared__ __align__(16) float ws[32][20];
    __shared__ float spart[4][32][17];

    const int t = threadIdx.x;
    const int rowg = t & 7;
    const int eg = (t >> 3) & 3;
    const int kg = t >> 5;
    const int brow = blockIdx.x * 32;

    float acc[4][4];
    #pragma unroll
    for (int i = 0; i < 4; i++)
        #pragma unroll
        for (int j = 0; j < 4; j++) acc[i][j] = 0.f;

    for (int kt = 0; kt < DD / 32; kt++) {
        float4 rx[2];
        float4 rw;
        #pragma unroll
        for (int i = 0; i < 2; i++) {
            int s = t + i * 128;
            int row = s >> 3, kq = s & 7;
            rx[i] = *(const float4*)&x[(size_t)(brow + row) * DD + kt * 32 + kq * 4];
        }
        {
            int e2 = t >> 3, kq = t & 7;
            rw = *(const float4*)&w[(size_t)e2 * DD + kt * 32 + kq * 4];
        }
        __syncthreads();
        #pragma unroll
        for (int i = 0; i < 2; i++) {
            int s = t + i * 128;
            int row = s >> 3, kq = s & 7;
            xs[kq * 4 + 0][row] = rx[i].x;
            xs[kq * 4 + 1][row] = rx[i].y;
            xs[kq * 4 + 2][row] = rx[i].z;
            xs[kq * 4 + 3][row] = rx[i].w;
        }
        {
            int e2 = t >> 3, kq = t & 7;
            ws[kq * 4 + 0][e2] = rw.x;
            ws[kq * 4 + 1][e2] = rw.y;
            ws[kq * 4 + 2][e2] = rw.z;
            ws[kq * 4 + 3][e2] = rw.w;
        }
        __syncthreads();
        #pragma unroll
        for (int kk2 = 0; kk2 < 8; kk2++) {
            int kk = kg * 8 + kk2;
            float4 a0 = *(const float4*)&xs[kk][rowg * 4];
            float4 bq = *(const float4*)&ws[kk][eg * 4];
            float av[4] = {a0.x, a0.y, a0.z, a0.w};
            float bv[4] = {bq.x, bq.y, bq.z, bq.w};
            #pragma unroll
            for (int i = 0; i < 4; i++)
                #pragma unroll
                for (int j = 0; j < 4; j++) acc[i][j] += av[i] * bv[j];
        }
        __syncthreads();
    }

    #pragma unroll
    for (int i = 0; i < 4; i++) {
        int r = rowg * 4 + i;
        #pragma unroll
        for (int j = 0; j < 4; j++) spart[kg][r][eg * 4 + j] = acc[i][j];
    }
    __syncthreads();

    if (t < 32) {
        int r = t;
        int b = brow + r;
        float z[16];
        float mu = 0.f;
        #pragma unroll
        for (int e2 = 0; e2 < 16; e2++) {
            float v = spart[0][r][e2] + spart[1][r][e2] + spart[2][r][e2] + spart[3][r][e2]
                      + bias[e2];
            z[e2] = v;
            mu += v;
        }
        mu *= (1.f / 16.f);
        float var = 0.f;
        #pragma unroll
        for (int e2 = 0; e2 < 16; e2++) { float d = z[e2] - mu; var += d * d; }
        var *= (1.f / 16.f);
        float rs = rsqrtf(var + LN_EPS);

        float best = z[0];
        int cls = 0;
        #pragma unroll
        for (int e2 = 1; e2 < 16; e2++)
            if (z[e2] > best) { best = z[e2]; cls = e2; }

        #pragma unroll
        for (int q = 0; q < 4; q++) {
            float4 o = make_float4((z[q * 4 + 0] - mu) * rs, (z[q * 4 + 1] - mu) * rs,
                                   (z[q * 4 + 2] - mu) * rs, (z[q * 4 + 3] - mu) * rs);
            *(float4*)&out_pl[(size_t)b * 16 + q * 4] = o;
        }
        g_class[b] = cls;
    }
}

// ------------------------- parent proj -------------------------
__global__ __launch_bounds__(256) void k_parent_proj(
    const float* __restrict__ pl, const float* __restrict__ w,
    const float* __restrict__ bias, float* __restrict__ out)
{
    __shared__ __align__(16) float spl[64][20];
    const int t = threadIdx.x;
    const int brow = blockIdx.x * 64;

    {
        int row = t >> 2, q = t & 3;
        float4 g = *(const float4*)&pl[(size_t)(brow + row) * 16 + q * 4];
        spl[row][q * 4 + 0] = g.x;
        spl[row][q * 4 + 1] = g.y;
        spl[row][q * 4 + 2] = g.z;
        spl[row][q * 4 + 3] = g.w;
    }
    __syncthreads();

    for (int pass = 0; pass < 2; pass++) {
        int p0 = pass * 512 + t * 2;
        float w0[16], w1[16];
        #pragma unroll
        for (int q = 0; q < 4; q++) {
            float4 a = *(const float4*)&w[(size_t)p0 * 16 + q * 4];
            w0[q * 4 + 0] = a.x; w0[q * 4 + 1] = a.y; w0[q * 4 + 2] = a.z; w0[q * 4 + 3] = a.w;
            float4 c = *(const float4*)&w[(size_t)(p0 + 1) * 16 + q * 4];
            w1[q * 4 + 0] = c.x; w1[q * 4 + 1] = c.y; w1[q * 4 + 2] = c.z; w1[q * 4 + 3] = c.w;
        }
        float b0 = bias[p0], b1 = bias[p0 + 1];

        for (int r = 0; r < 64; r++) {
            float a0 = b0, a1 = b1;
            #pragma unroll
            for (int q = 0; q < 4; q++) {
                float4 v = *(const float4*)&spl[r][q * 4];
                a0 += v.x * w0[q * 4 + 0] + v.y * w0[q * 4 + 1] + v.z * w0[q * 4 + 2] + v.w * w0[q * 4 + 3];
                a1 += v.x * w1[q * 4 + 0] + v.y * w1[q * 4 + 1] + v.z * w1[q * 4 + 2] + v.w * w1[q * 4 + 3];
            }
            float2 o = make_float2(a0, a1);
            *(float2*)&out[(size_t)(brow + r) * PP + p0] = o;
        }
    }
}

// ===========================================================================
// Child FC split-K GEMM (bf16 split-3), compact tile list. grid (80, 1, 8).
// ===========================================================================
template <int BN>
__device__ __forceinline__ void tfc_impl(
    const __nv_bfloat16* __restrict__ xh, const __nv_bfloat16* __restrict__ xl,
    const __nv_bfloat16* __restrict__ wh, const __nv_bfloat16* __restrict__ wl,
    float* __restrict__ part, int ks, char* sm, int* sidx)
{
    if (blockIdx.x >= (unsigned)g_ntiles) return;
    const int pk = g_tiles[blockIdx.x];
    const int e = pk >> 16;
    const int start = g_off[e] + (pk & 0xffff) * 128;
    const int end = g_off[e + 1];

    const int t = threadIdx.x;
    const int wid = t >> 5, lane = t & 31;
    const int wr = wid & 3, wc = wid >> 2;
    const uint32_t sb = smem_u32(sm);
    const int kbase = ks * 512;

    constexpr int AH0 = 0, AL0 = 16384, BH0 = 32768, BL0 = 32768 + BN * 128;
    constexpr int BUF = 32768 + 2 * BN * 128;
    constexpr int NGW = BN / 32;

    if (t < 128) { int gi = start + t; sidx[t] = g_sidx[gi < end ? gi : end - 1]; }
    __syncthreads();

    auto issue = [&](int kt) {
        uint32_t base = sb + (uint32_t)((kt & 1) * BUF);
        #pragma unroll
        for (int i = 0; i < 4; i++) {
            int d = t + i * 256;
            int row = d >> 3, ch = d & 7;
            uint32_t off = (uint32_t)(row * 128 + ((ch * 16) ^ ((row & 7) << 4)));
            size_t g = (size_t)sidx[row] * DD + kbase + kt * 64 + ch * 8;
            CPA(base + AH0 + off, xh + g);
            CPA(base + AL0 + off, xl + g);
        }
        #pragma unroll
        for (int i = 0; i < BN / 32; i++) {
            int d = t + i * 256;
            int row = d >> 3, ch = d & 7;
            uint32_t off = (uint32_t)(row * 128 + ((ch * 16) ^ ((row & 7) << 4)));
            size_t g = ((size_t)e * BN + row) * DD + kbase + kt * 64 + ch * 8;
            CPA(base + BH0 + off, wh + g);
            CPA(base + BL0 + off, wl + g);
        }
        CPA_COMMIT();
    };

    float accA[NGW * 8], accB[NGW * 8];
    #pragma unroll
    for (int i = 0; i < NGW * 8; i++) { accA[i] = 0.f; accB[i] = 0.f; }

    issue(0);
    const int NKT = 8;
    for (int kt = 0; kt < NKT; kt++) {
        if (kt + 1 < NKT) { issue(kt + 1); CPA_WAIT(1); }
        else              { CPA_WAIT(0); }
        __syncthreads();
        uint32_t base = sb + (uint32_t)((kt & 1) * BUF);
        mma_chunk2<NGW>(base + AH0, base + AL0,
                        base + BH0 + (uint32_t)(wc * (BN / 2) * 128),
                        base + BL0 + (uint32_t)(wc * (BN / 2) * 128),
                        wr * 32, lane, accA, accB);
        __syncthreads();
    }

    const int rA0 = wr * 32 + (lane >> 2);
    #pragma unroll
    for (int g = 0; g < NGW; g++) {
        #pragma unroll
        for (int half = 0; half < 2; half++) {
            int col = wc * (BN / 2) + (g * 2 + half) * 8 + (lane & 3) * 2;
            float* pa = accA + g * 8 + half * 4;
            float* pb = accB + g * 8 + half * 4;
            int rows[4] = {rA0, rA0 + 8, rA0 + 16, rA0 + 24};
            float* vals[4] = {pa, pa + 2, pb, pb + 2};
            #pragma unroll
            for (int rv = 0; rv < 4; rv++) {
                int p = start + rows[rv];
                if (p < end)
                    *(float2*)&part[(size_t)ks * BB * BN + (size_t)p * BN + col] =
                        make_float2(vals[rv][0], vals[rv][1]);
            }
        }
    }
}

#define FC_SMEM 131072

__global__ __launch_bounds__(256, 1) void k_tfc() {
    extern __shared__ char smx[];
    __shared__ int sidx[128];
    if (blockIdx.z < 4)
        tfc_impl<CC1>(g_xh, g_xl, g_wfc1h, g_wfc1l, g_pt1, blockIdx.z, smx, sidx);
    else
        tfc_impl<CC0>(g_xh, g_xl, g_wfc0h, g_wfc0l, g_pt0, blockIdx.z - 4, smx, sidx);
}

// ===========================================================================
// FC reduce: sum 4 partials + bias + LN + write cl + h fp16. 1 warp per row.
// ===========================================================================
template <int BN>
__device__ __forceinline__ void fcred_impl(
    const float* __restrict__ part, const float* __restrict__ bias,
    float* __restrict__ out, __half* __restrict__ hf)
{
    const int p = blockIdx.x * 8 + (threadIdx.x >> 5);
    const int lane = threadIdx.x & 31;
    const int b = g_sidx[p];
    const int e = g_class[b];
    constexpr int NC = BN / 32;

    float v[NC];
    float s = 0.f, q = 0.f;
    #pragma unroll
    for (int i = 0; i < NC; i++) {
        int col = lane + i * 32;
        size_t idx = (size_t)p * BN + col;
        float a = part[idx] + part[(size_t)BB * BN + idx]
                + part[2 * (size_t)BB * BN + idx] + part[3 * (size_t)BB * BN + idx]
                + bias[e * BN + col];
        v[i] = a;
        s += a;
        q += a * a;
    }
    #pragma unroll
    for (int o = 16; o; o >>= 1) {
        s += __shfl_xor_sync(~0u, s, o);
        q += __shfl_xor_sync(~0u, q, o);
    }
    float mu = s * (1.f / BN);
    float rs = rsqrtf(q * (1.f / BN) - mu * mu + LN_EPS);
    #pragma unroll
    for (int i = 0; i < NC; i++) {
        int col = lane + i * 32;
        float o = (v[i] - mu) * rs;
        out[(size_t)b * BN + col] = o;
        hf[(size_t)b * BN + col] = __float2half_rn(o);
    }
}

__global__ __launch_bounds__(256) void k_fcred(
    const float* __restrict__ b0, const float* __restrict__ b1,
    float* __restrict__ out)
{
    if (blockIdx.y == 0)
        fcred_impl<CC0>(g_pt0, b0, out + OFF_CL0, g_h0f);
    else
        fcred_impl<CC1>(g_pt1, b1, out + OFF_CL1, g_h1f);
}

// ===========================================================================
// Child proj (plain fp16, 1 MMA per fragment): compact tiles, A resident,
// 4 p-tiles double-buffered B. grid (80, 1, 4): z = level*2 + half.
// smem: A (NKC*16K) | B0 (NKC*16K) | B1 (NKC*16K)  -> max 96 KB (2 blocks/SM)
// ===========================================================================
template <int CK>
__device__ __forceinline__ void tproj_impl(
    const __half* __restrict__ a, const __half* __restrict__ w,
    const float* __restrict__ bias, float* __restrict__ out,
    int half4, char* sm, int* sidx)
{
    if (blockIdx.x >= (unsigned)g_ntiles) return;
    const int pk = g_tiles[blockIdx.x];
    const int e = pk >> 16;
    const int start = g_off[e] + (pk & 0xffff) * 128;
    const int end = g_off[e + 1];

    constexpr int NKC = CK / 64;
    const int t = threadIdx.x;
    const int wid = t >> 5, lane = t & 31;
    const int wr = wid & 3, wc = wid >> 2;
    const uint32_t sb = smem_u32(sm);
    constexpr uint32_t MSZ = (uint32_t)NKC * 16384u;  // A block / one B buffer
    const int pt0 = half4 * 4;

    if (t < 128) { int gi = start + t; sidx[t] = g_sidx[gi < end ? gi : end - 1]; }
    __syncthreads();

    // A (h) loads — committed together with first B
    #pragma unroll
    for (int kc = 0; kc < NKC; kc++) {
        #pragma unroll
        for (int i = 0; i < 4; i++) {
            int s = t + i * 256;
            int row = s >> 3, ch = s & 7;
            uint32_t off = (uint32_t)(kc * 16384 + row * 128 + ((ch * 16) ^ ((row & 7) << 4)));
            size_t ga = (size_t)sidx[row] * CK + kc * 64 + ch * 8;
            CPA(sb + off, a + ga);
        }
    }

    auto issueB = [&](int pi) {
        uint32_t base = sb + MSZ + (uint32_t)((pi & 1) * MSZ);
        int pt = pt0 + pi;
        #pragma unroll
        for (int kc = 0; kc < NKC; kc++) {
            #pragma unroll
            for (int i = 0; i < 4; i++) {
                int s = t + i * 256;
                int row = s >> 3, ch = s & 7;
                uint32_t off = (uint32_t)(kc * 16384 + row * 128
                                          + ((ch * 16) ^ ((row & 7) << 4)));
                size_t gb = ((size_t)(e * PP + pt * 128 + row)) * CK + kc * 64 + ch * 8;
                CPA(base + off, w + gb);
            }
        }
        CPA_COMMIT();
    };

    issueB(0);

    const int rA0 = wr * 32 + (lane >> 2);
    for (int pi = 0; pi < 4; pi++) {
        if (pi + 1 < 4) { issueB(pi + 1); CPA_WAIT(1); }
        else            { CPA_WAIT(0); }
        __syncthreads();

        float accA[32], accB[32];
        #pragma unroll
        for (int i = 0; i < 32; i++) { accA[i] = 0.f; accB[i] = 0.f; }

        uint32_t bbase = sb + MSZ + (uint32_t)((pi & 1) * MSZ);
        #pragma unroll
        for (int kc = 0; kc < NKC; kc++) {
            uint32_t ab = sb + (uint32_t)(kc * 16384);
            uint32_t bb = bbase + (uint32_t)(kc * 16384);
            mma_chunk2f<4>(ab, bb + (uint32_t)(wc * 64 * 128), wr * 32, lane, accA, accB);
        }

        int pt = pt0 + pi;
        #pragma unroll
        for (int g = 0; g < 4; g++) {
            #pragma unroll
            for (int hf = 0; hf < 2; hf++) {
                int pcol = pt * 128 + wc * 64 + (g * 2 + hf) * 8 + (lane & 3) * 2;
                float bv0 = bias[(size_t)e * PP + pcol];
                float bv1 = bias[(size_t)e * PP + pcol + 1];
                float* pa = accA + g * 8 + hf * 4;
                float* pb = accB + g * 8 + hf * 4;
                int rows[4] = {rA0, rA0 + 8, rA0 + 16, rA0 + 24};
                float* vals[4] = {pa, pa + 2, pb, pb + 2};
                #pragma unroll
                for (int rv = 0; rv < 4; rv++) {
                    if (start + rows[rv] < end) {
                        int b = sidx[rows[rv]];
                        *(float2*)&out[(size_t)b * PP + pcol] =
                            make_float2(vals[rv][0] + bv0, vals[rv][1] + bv1);
                    }
                }
            }
        }
        __syncthreads();
    }
}

#define PROJ_SMEM 98304

__global__ __launch_bounds__(256) void k_tproj(
    const float* __restrict__ bpr0, const float* __restrict__ bpr1,
    float* __restrict__ out)
{
    extern __shared__ char smx[];
    __shared__ int sidx[128];
    const int level = blockIdx.z >> 1;
    const int half4 = blockIdx.z & 1;
    if (level == 0)
        tproj_impl<CC0>(g_h0f, g_wp0f, bpr0, out + OFF_CP0, half4, smx, sidx);
    else
        tproj_impl<CC1>(g_h1f, g_wp1f, bpr1, out + OFF_CP1, half4, smx, sidx);
}

// ---------------------------------------------------------------------------

extern "C" void kernel_launch(void* const* d_in, const int* in_sizes, int n_in,
                              void* d_out, int out_size) {
    const float* x       = (const float*)d_in[0];
    const float* pw_fc   = (const float*)d_in[1];
    const float* pb_fc   = (const float*)d_in[2];
    const float* pw_proj = (const float*)d_in[3];
    const float* pb_proj = (const float*)d_in[4];
    const float* cw_fc0  = (const float*)d_in[5];
    const float* cb_fc0  = (const float*)d_in[6];
    const float* cw_pr0  = (const float*)d_in[7];
    const float* cb_pr0  = (const float*)d_in[8];
    const float* cw_fc1  = (const float*)d_in[9];
    const float* cb_fc1  = (const float*)d_in[10];
    const float* cw_pr1  = (const float*)d_in[11];
    const float* cb_pr1  = (const float*)d_in[12];
    float* out = (float*)d_out;

    static cudaStream_t sA = nullptr;
    static cudaEvent_t e0, evS, evC, evP;
    if (!sA) {
        cudaStreamCreate(&sA);
        cudaEventCreateWithFlags(&e0, cudaEventDisableTiming);
        cudaEventCreateWithFlags(&evS, cudaEventDisableTiming);
        cudaEventCreateWithFlags(&evC, cudaEventDisableTiming);
        cudaEventCreateWithFlags(&evP, cudaEventDisableTiming);
        cudaFuncSetAttribute(k_tfc, cudaFuncAttributeMaxDynamicSharedMemorySize, FC_SMEM);
        cudaFuncSetAttribute(k_tproj, cudaFuncAttributeMaxDynamicSharedMemorySize, PROJ_SMEM);
    }

    cudaEventRecord(e0, 0);
    cudaStreamWaitEvent(sA, e0, 0);

    // stream 0: parent fc -> bucket/tiles
    k_parent_fc<<<BB / 32, 128>>>(x, pw_fc, pb_fc, out + OFF_PL);
    k_scansc<<<1, 1024>>>();
    cudaEventRecord(evS, 0);

    // stream A: converts + parent proj
    k_cvtx<<<BB * DD / 4 / 256, 256, 0, sA>>>(x);
    k_cvtwfc<<<dim3(4096, 2), 256, 0, sA>>>(cw_fc0, cw_fc1);
    cudaEventRecord(evC, sA);
    cudaStreamWaitEvent(sA, evS, 0);
    k_parent_proj<<<BB / 64, 256, 0, sA>>>(out + OFF_PL, pw_proj, pb_proj, out + OFF_PP);

    // stream 0: the big child fc GEMM
    cudaStreamWaitEvent(0, evC, 0);
    k_tfc<<<dim3(80, 1, 8), 256, FC_SMEM>>>();

    // stream A: proj weight cvt (fp16, half the bytes)
    k_cvtwpr<<<dim3(2048, 2), 256, 0, sA>>>(cw_pr0, cw_pr1);
    cudaEventRecord(evP, sA);

    // stream 0
    k_fcred<<<dim3(BB / 8, 2), 256>>>(cb_fc0, cb_fc1, out);
    cudaStreamWaitEvent(0, evP, 0);
    k_tproj<<<dim3(80, 1, 4), 256, PROJ_SMEM>>>(cb_pr0, cb_pr1, out);
}

// round 15
// speedup vs baseline: 3.7828x; 1.1499x over previous
#include <cuda_runtime.h>
#include <cuda_bf16.h>
#include <cuda_fp16.h>
#include <cstdint>

#define BB 8192
#define DD 2048
#define EE 16
#define PP 1024
#define CC0 64
#define CC1 128
#define LN_EPS 1e-5f

#define OFF_PL  0
#define OFF_CL0 (BB*EE)
#define OFF_CL1 (OFF_CL0 + BB*CC0)
#define OFF_PP  (OFF_CL1 + BB*CC1)
#define OFF_CP0 (OFF_PP + BB*PP)
#define OFF_CP1 (OFF_CP0 + BB*PP)

typedef unsigned long long u64t;

// ------------------------- scratch globals -------------------------
__device__ int g_class[BB];
__device__ int g_off[EE + 1];
__device__ int g_sidx[BB];
__device__ int g_tiles[96];
__device__ int g_ntiles;

// fp16 operands everywhere in the child path (terminal-output error budget)
__device__ __half g_xf[BB * DD];
__device__ __half g_wfc0f[EE * CC0 * DD], g_wfc1f[EE * CC1 * DD];
__device__ __half g_wp0f[EE * PP * CC0], g_wp1f[EE * PP * CC1];
__device__ __half g_h0f[BB * CC0], g_h1f[BB * CC1];

__device__ float g_pt0[4 * BB * CC0];
__device__ float g_pt1[4 * BB * CC1];

// ------------------------- asm helpers (sm_80+ generic) ---------------
__device__ __forceinline__ uint32_t smem_u32(const void* p) {
    uint32_t a;
    asm("{ .reg .u64 t; cvta.to.shared.u64 t, %1; cvt.u32.u64 %0, t; }"
        : "=r"(a) : "l"(p));
    return a;
}
#define CPA(dst, src) \
    asm volatile("cp.async.cg.shared.global [%0], [%1], 16;" :: "r"(dst), "l"(src) : "memory")
#define CPA_COMMIT() asm volatile("cp.async.commit_group;" ::: "memory")
#define CPA_WAIT(n)  asm volatile("cp.async.wait_group %0;" :: "n"(n) : "memory")
#define LDM4(r, addr) \
    asm volatile("ldmatrix.sync.aligned.m8n8.x4.shared.b16 {%0,%1,%2,%3}, [%4];" \
                 : "=r"((r)[0]), "=r"((r)[1]), "=r"((r)[2]), "=r"((r)[3]) : "r"(addr))

__device__ __forceinline__ void mma_f16(float* c, const uint32_t* a,
                                        uint32_t b0, uint32_t b1) {
    asm volatile(
        "mma.sync.aligned.m16n8k16.row.col.f32.f16.f16.f32 "
        "{%0,%1,%2,%3}, {%4,%5,%6,%7}, {%8,%9}, {%0,%1,%2,%3};"
        : "+f"(c[0]), "+f"(c[1]), "+f"(c[2]), "+f"(c[3])
        : "r"(a[0]), "r"(a[1]), "r"(a[2]), "r"(a[3]), "r"(b0), "r"(b1));
}

// plain fp16, two 16-row subtiles sharing B fragments. NG groups of 16 cols.
template <int NG>
__device__ __forceinline__ void mma_chunk2f(uint32_t A, uint32_t B,
                                            int m0, int lane,
                                            float* accA, float* accB) {
    const int arow0 = m0 + (lane & 15);
    const uint32_t aoff0 = (uint32_t)arow0 * 128u;
    const uint32_t aoff1 = aoff0 + 16u * 128u;
    const uint32_t axr = (uint32_t)((arow0 & 7) << 4);
    const uint32_t acb0 = (uint32_t)((lane >> 4) << 4);
    const int brl = ((lane >> 4) & 1) * 8 + (lane & 7);
    const uint32_t bcb0 = (uint32_t)(((lane >> 3) & 1) << 4);
    #pragma unroll
    for (int ks = 0; ks < 4; ks++) {
        uint32_t acb = ((uint32_t)(ks * 32) + acb0) ^ axr;
        uint32_t a0[4], a1[4];
        LDM4(a0, A + aoff0 + acb);
        LDM4(a1, A + aoff1 + acb);
        #pragma unroll
        for (int g = 0; g < NG; g++) {
            int brow = g * 16 + brl;
            uint32_t boff = (uint32_t)brow * 128u
                            + (((uint32_t)(ks * 32) + bcb0) ^ (uint32_t)((brow & 7) << 4));
            uint32_t b[4];
            LDM4(b, B + boff);
            mma_f16(accA + g * 8,     a0, b[0], b[1]);
            mma_f16(accA + g * 8 + 4, a0, b[2], b[3]);
            mma_f16(accB + g * 8,     a1, b[0], b[1]);
            mma_f16(accB + g * 8 + 4, a1, b[2], b[3]);
        }
    }
}

// ------------------------- cvt kernels -------------------------
__global__ void k_cvtx(const float* __restrict__ src) {
    int i4 = blockIdx.x * 256 + threadIdx.x;
    if (i4 * 4 < BB * DD) {
        float4 v = ((const float4*)src)[i4];
        ((__half2*)g_xf)[i4 * 2 + 0] = __floats2half2_rn(v.x, v.y);
        ((__half2*)g_xf)[i4 * 2 + 1] = __floats2half2_rn(v.z, v.w);
    }
}

__global__ void k_cvtwfc(const float* __restrict__ sa, const float* __restrict__ sb) {
    const int sel = blockIdx.y;
    const float* src = sel ? sb : sa;
    __half* df = sel ? g_wfc1f : g_wfc0f;
    const int n = sel ? EE * CC1 * DD : EE * CC0 * DD;
    int i4 = blockIdx.x * 256 + threadIdx.x;
    if (i4 * 4 < n) {
        float4 v = ((const float4*)src)[i4];
        ((__half2*)df)[i4 * 2 + 0] = __floats2half2_rn(v.x, v.y);
        ((__half2*)df)[i4 * 2 + 1] = __floats2half2_rn(v.z, v.w);
    }
}

__global__ void k_cvtwpr(const float* __restrict__ sa, const float* __restrict__ sb) {
    const int sel = blockIdx.y;
    const float* src = sel ? sb : sa;
    __half* df = sel ? g_wp1f : g_wp0f;
    const int n = sel ? EE * PP * CC1 : EE * PP * CC0;
    int i4 = blockIdx.x * 256 + threadIdx.x;
    if (i4 * 4 < n) {
        float4 v = ((const float4*)src)[i4];
        ((__half2*)df)[i4 * 2 + 0] = __floats2half2_rn(v.x, v.y);
        ((__half2*)df)[i4 * 2 + 1] = __floats2half2_rn(v.z, v.w);
    }
}

// histogram + scan + scatter + tile list, one block
__global__ void k_scansc() {
    __shared__ int hist[EE];
    __shared__ int off[EE];
    __shared__ int cur[EE];
    const int t = threadIdx.x;
    if (t < EE) hist[t] = 0;
    __syncthreads();
    for (int b = t; b < BB; b += 1024) atomicAdd(&hist[g_class[b]], 1);
    __syncthreads();
    if (t == 0) {
        int o = 0, nt = 0;
        for (int e = 0; e < EE; e++) {
            off[e] = o;
            g_off[e] = o;
            int m = (hist[e] + 127) >> 7;
            for (int i = 0; i < m; i++) g_tiles[nt++] = (e << 16) | i;
            o += hist[e];
        }
        g_off[EE] = o;
        g_ntiles = nt;
    }
    if (t < EE) cur[t] = 0;
    __syncthreads();
    for (int b = t; b < BB; b += 1024) {
        int e = g_class[b];
        int pos = off[e] + atomicAdd(&cur[e], 1);
        g_sidx[pos] = b;
    }
}

// ------------------------- parent FC (exact fp32), BM=32 ------------------
__global__ __launch_bounds__(128) void k_parent_fc(
    const float* __restrict__ x, const float* __restrict__ w,
    const float* __restrict__ bias, float* __restrict__ out_pl)
{
    __shared__ __align__(16) float xs[32][36];
    __shared__ __align__(16) float ws[32][20];
    __shared__ float spart[4][32][17];

    const int t = threadIdx.x;
    const int rowg = t & 7;
    const int eg = (t >> 3) & 3;
    const int kg = t >> 5;
    const int brow = blockIdx.x * 32;

    float acc[4][4];
    #pragma unroll
    for (int i = 0; i < 4; i++)
        #pragma unroll
        for (int j = 0; j < 4; j++) acc[i][j] = 0.f;

    for (int kt = 0; kt < DD / 32; kt++) {
        float4 rx[2];
        float4 rw;
        #pragma unroll
        for (int i = 0; i < 2; i++) {
            int s = t + i * 128;
            int row = s >> 3, kq = s & 7;
            rx[i] = *(const float4*)&x[(size_t)(brow + row) * DD + kt * 32 + kq * 4];
        }
        {
            int e2 = t >> 3, kq = t & 7;
            rw = *(const float4*)&w[(size_t)e2 * DD + kt * 32 + kq * 4];
        }
        __syncthreads();
        #pragma unroll
        for (int i = 0; i < 2; i++) {
            int s = t + i * 128;
            int row = s >> 3, kq = s & 7;
            xs[kq * 4 + 0][row] = rx[i].x;
            xs[kq * 4 + 1][row] = rx[i].y;
            xs[kq * 4 + 2][row] = rx[i].z;
            xs[kq * 4 + 3][row] = rx[i].w;
        }
        {
            int e2 = t >> 3, kq = t & 7;
            ws[kq * 4 + 0][e2] = rw.x;
            ws[kq * 4 + 1][e2] = rw.y;
            ws[kq * 4 + 2][e2] = rw.z;
            ws[kq * 4 + 3][e2] = rw.w;
        }
        __syncthreads();
        #pragma unroll
        for (int kk2 = 0; kk2 < 8; kk2++) {
            int kk = kg * 8 + kk2;
            float4 a0 = *(const float4*)&xs[kk][rowg * 4];
            float4 bq = *(const float4*)&ws[kk][eg * 4];
            float av[4] = {a0.x, a0.y, a0.z, a0.w};
            float bv[4] = {bq.x, bq.y, bq.z, bq.w};
            #pragma unroll
            for (int i = 0; i < 4; i++)
                #pragma unroll
                for (int j = 0; j < 4; j++) acc[i][j] += av[i] * bv[j];
        }
        __syncthreads();
    }

    #pragma unroll
    for (int i = 0; i < 4; i++) {
        int r = rowg * 4 + i;
        #pragma unroll
        for (int j = 0; j < 4; j++) spart[kg][r][eg * 4 + j] = acc[i][j];
    }
    __syncthreads();

    if (t < 32) {
        int r = t;
        int b = brow + r;
        float z[16];
        float mu = 0.f;
        #pragma unroll
        for (int e2 = 0; e2 < 16; e2++) {
            float v = spart[0][r][e2] + spart[1][r][e2] + spart[2][r][e2] + spart[3][r][e2]
                      + bias[e2];
            z[e2] = v;
            mu += v;
        }
        mu *= (1.f / 16.f);
        float var = 0.f;
        #pragma unroll
        for (int e2 = 0; e2 < 16; e2++) { float d = z[e2] - mu; var += d * d; }
        var *= (1.f / 16.f);
        float rs = rsqrtf(var + LN_EPS);

        float best = z[0];
        int cls = 0;
        #pragma unroll
        for (int e2 = 1; e2 < 16; e2++)
            if (z[e2] > best) { best = z[e2]; cls = e2; }

        #pragma unroll
        for (int q = 0; q < 4; q++) {
            float4 o = make_float4((z[q * 4 + 0] - mu) * rs, (z[q * 4 + 1] - mu) * rs,
                                   (z[q * 4 + 2] - mu) * rs, (z[q * 4 + 3] - mu) * rs);
            *(float4*)&out_pl[(size_t)b * 16 + q * 4] = o;
        }
        g_class[b] = cls;
    }
}

// ------------------------- parent proj -------------------------
__global__ __launch_bounds__(256) void k_parent_proj(
    const float* __restrict__ pl, const float* __restrict__ w,
    const float* __restrict__ bias, float* __restrict__ out)
{
    __shared__ __align__(16) float spl[64][20];
    const int t = threadIdx.x;
    const int brow = blockIdx.x * 64;

    {
        int row = t >> 2, q = t & 3;
        float4 g = *(const float4*)&pl[(size_t)(brow + row) * 16 + q * 4];
        spl[row][q * 4 + 0] = g.x;
        spl[row][q * 4 + 1] = g.y;
        spl[row][q * 4 + 2] = g.z;
        spl[row][q * 4 + 3] = g.w;
    }
    __syncthreads();

    for (int pass = 0; pass < 2; pass++) {
        int p0 = pass * 512 + t * 2;
        float w0[16], w1[16];
        #pragma unroll
        for (int q = 0; q < 4; q++) {
            float4 a = *(const float4*)&w[(size_t)p0 * 16 + q * 4];
            w0[q * 4 + 0] = a.x; w0[q * 4 + 1] = a.y; w0[q * 4 + 2] = a.z; w0[q * 4 + 3] = a.w;
            float4 c = *(const float4*)&w[(size_t)(p0 + 1) * 16 + q * 4];
            w1[q * 4 + 0] = c.x; w1[q * 4 + 1] = c.y; w1[q * 4 + 2] = c.z; w1[q * 4 + 3] = c.w;
        }
        float b0 = bias[p0], b1 = bias[p0 + 1];

        for (int r = 0; r < 64; r++) {
            float a0 = b0, a1 = b1;
            #pragma unroll
            for (int q = 0; q < 4; q++) {
                float4 v = *(const float4*)&spl[r][q * 4];
                a0 += v.x * w0[q * 4 + 0] + v.y * w0[q * 4 + 1] + v.z * w0[q * 4 + 2] + v.w * w0[q * 4 + 3];
                a1 += v.x * w1[q * 4 + 0] + v.y * w1[q * 4 + 1] + v.z * w1[q * 4 + 2] + v.w * w1[q * 4 + 3];
            }
            float2 o = make_float2(a0, a1);
            *(float2*)&out[(size_t)(brow + r) * PP + p0] = o;
        }
    }
}

// ===========================================================================
// Child FC split-K GEMM (plain fp16), compact tile list. grid (80, 1, 8).
// Per buffer: A 16K | B BN*128.  CC1: 64K total (3 blocks/SM).
// ===========================================================================
template <int BN>
__device__ __forceinline__ void tfc_impl(
    const __half* __restrict__ x, const __half* __restrict__ w,
    float* __restrict__ part, int ks, char* sm, int* sidx)
{
    if (blockIdx.x >= (unsigned)g_ntiles) return;
    const int pk = g_tiles[blockIdx.x];
    const int e = pk >> 16;
    const int start = g_off[e] + (pk & 0xffff) * 128;
    const int end = g_off[e + 1];

    const int t = threadIdx.x;
    const int wid = t >> 5, lane = t & 31;
    const int wr = wid & 3, wc = wid >> 2;
    const uint32_t sb = smem_u32(sm);
    const int kbase = ks * 512;

    constexpr int B0 = 16384;
    constexpr int BUF = 16384 + BN * 128;
    constexpr int NGW = BN / 32;

    if (t < 128) { int gi = start + t; sidx[t] = g_sidx[gi < end ? gi : end - 1]; }
    __syncthreads();

    auto issue = [&](int kt) {
        uint32_t base = sb + (uint32_t)((kt & 1) * BUF);
        #pragma unroll
        for (int i = 0; i < 4; i++) {
            int d = t + i * 256;
            int row = d >> 3, ch = d & 7;
            uint32_t off = (uint32_t)(row * 128 + ((ch * 16) ^ ((row & 7) << 4)));
            size_t g = (size_t)sidx[row] * DD + kbase + kt * 64 + ch * 8;
            CPA(base + off, x + g);
        }
        #pragma unroll
        for (int i = 0; i < BN / 32; i++) {
            int d = t + i * 256;
            int row = d >> 3, ch = d & 7;
            uint32_t off = (uint32_t)(row * 128 + ((ch * 16) ^ ((row & 7) << 4)));
            size_t g = ((size_t)e * BN + row) * DD + kbase + kt * 64 + ch * 8;
            CPA(base + B0 + off, w + g);
        }
        CPA_COMMIT();
    };

    float accA[NGW * 8], accB[NGW * 8];
    #pragma unroll
    for (int i = 0; i < NGW * 8; i++) { accA[i] = 0.f; accB[i] = 0.f; }

    issue(0);
    const int NKT = 8;
    for (int kt = 0; kt < NKT; kt++) {
        if (kt + 1 < NKT) { issue(kt + 1); CPA_WAIT(1); }
        else              { CPA_WAIT(0); }
        __syncthreads();
        uint32_t base = sb + (uint32_t)((kt & 1) * BUF);
        mma_chunk2f<NGW>(base, base + B0 + (uint32_t)(wc * (BN / 2) * 128),
                         wr * 32, lane, accA, accB);
        __syncthreads();
    }

    const int rA0 = wr * 32 + (lane >> 2);
    #pragma unroll
    for (int g = 0; g < NGW; g++) {
        #pragma unroll
        for (int half = 0; half < 2; half++) {
            int col = wc * (BN / 2) + (g * 2 + half) * 8 + (lane & 3) * 2;
            float* pa = accA + g * 8 + half * 4;
            float* pb = accB + g * 8 + half * 4;
            int rows[4] = {rA0, rA0 + 8, rA0 + 16, rA0 + 24};
            float* vals[4] = {pa, pa + 2, pb, pb + 2};
            #pragma unroll
            for (int rv = 0; rv < 4; rv++) {
                int p = start + rows[rv];
                if (p < end)
                    *(float2*)&part[(size_t)ks * BB * BN + (size_t)p * BN + col] =
                        make_float2(vals[rv][0], vals[rv][1]);
            }
        }
    }
}

#define FC_SMEM 65536

__global__ __launch_bounds__(256) void k_tfc() {
    extern __shared__ char smx[];
    __shared__ int sidx[128];
    if (blockIdx.z < 4)
        tfc_impl<CC1>(g_xf, g_wfc1f, g_pt1, blockIdx.z, smx, sidx);
    else
        tfc_impl<CC0>(g_xf, g_wfc0f, g_pt0, blockIdx.z - 4, smx, sidx);
}

// ===========================================================================
// FC reduce: sum 4 partials + bias + LN + write cl + h fp16. 1 warp per row.
// ===========================================================================
template <int BN>
__device__ __forceinline__ void fcred_impl(
    const float* __restrict__ part, const float* __restrict__ bias,
    float* __restrict__ out, __half* __restrict__ hf)
{
    const int p = blockIdx.x * 8 + (threadIdx.x >> 5);
    const int lane = threadIdx.x & 31;
    const int b = g_sidx[p];
    const int e = g_class[b];
    constexpr int NC = BN / 32;

    float v[NC];
    float s = 0.f, q = 0.f;
    #pragma unroll
    for (int i = 0; i < NC; i++) {
        int col = lane + i * 32;
        size_t idx = (size_t)p * BN + col;
        float a = part[idx] + part[(size_t)BB * BN + idx]
                + part[2 * (size_t)BB * BN + idx] + part[3 * (size_t)BB * BN + idx]
                + bias[e * BN + col];
        v[i] = a;
        s += a;
        q += a * a;
    }
    #pragma unroll
    for (int o = 16; o; o >>= 1) {
        s += __shfl_xor_sync(~0u, s, o);
        q += __shfl_xor_sync(~0u, q, o);
    }
    float mu = s * (1.f / BN);
    float rs = rsqrtf(q * (1.f / BN) - mu * mu + LN_EPS);
    #pragma unroll
    for (int i = 0; i < NC; i++) {
        int col = lane + i * 32;
        float o = (v[i] - mu) * rs;
        out[(size_t)b * BN + col] = o;
        hf[(size_t)b * BN + col] = __float2half_rn(o);
    }
}

__global__ __launch_bounds__(256) void k_fcred(
    const float* __restrict__ b0, const float* __restrict__ b1,
    float* __restrict__ out)
{
    if (blockIdx.y == 0)
        fcred_impl<CC0>(g_pt0, b0, out + OFF_CL0, g_h0f);
    else
        fcred_impl<CC1>(g_pt1, b1, out + OFF_CL1, g_h1f);
}

// ===========================================================================
// Child proj (plain fp16): compact tiles, A resident, 4 p-tiles dbuf B.
// ===========================================================================
template <int CK>
__device__ __forceinline__ void tproj_impl(
    const __half* __restrict__ a, const __half* __restrict__ w,
    const float* __restrict__ bias, float* __restrict__ out,
    int half4, char* sm, int* sidx)
{
    if (blockIdx.x >= (unsigned)g_ntiles) return;
    const int pk = g_tiles[blockIdx.x];
    const int e = pk >> 16;
    const int start = g_off[e] + (pk & 0xffff) * 128;
    const int end = g_off[e + 1];

    constexpr int NKC = CK / 64;
    const int t = threadIdx.x;
    const int wid = t >> 5, lane = t & 31;
    const int wr = wid & 3, wc = wid >> 2;
    const uint32_t sb = smem_u32(sm);
    constexpr uint32_t MSZ = (uint32_t)NKC * 16384u;
    const int pt0 = half4 * 4;

    if (t < 128) { int gi = start + t; sidx[t] = g_sidx[gi < end ? gi : end - 1]; }
    __syncthreads();

    #pragma unroll
    for (int kc = 0; kc < NKC; kc++) {
        #pragma unroll
        for (int i = 0; i < 4; i++) {
            int s = t + i * 256;
            int row = s >> 3, ch = s & 7;
            uint32_t off = (uint32_t)(kc * 16384 + row * 128 + ((ch * 16) ^ ((row & 7) << 4)));
            size_t ga = (size_t)sidx[row] * CK + kc * 64 + ch * 8;
            CPA(sb + off, a + ga);
        }
    }

    auto issueB = [&](int pi) {
        uint32_t base = sb + MSZ + (uint32_t)((pi & 1) * MSZ);
        int pt = pt0 + pi;
        #pragma unroll
        for (int kc = 0; kc < NKC; kc++) {
            #pragma unroll
            for (int i = 0; i < 4; i++) {
                int s = t + i * 256;
                int row = s >> 3, ch = s & 7;
                uint32_t off = (uint32_t)(kc * 16384 + row * 128
                                          + ((ch * 16) ^ ((row & 7) << 4)));
                size_t gb = ((size_t)(e * PP + pt * 128 + row)) * CK + kc * 64 + ch * 8;
                CPA(base + off, w + gb);
            }
        }
        CPA_COMMIT();
    };

    issueB(0);

    const int rA0 = wr * 32 + (lane >> 2);
    for (int pi = 0; pi < 4; pi++) {
        if (pi + 1 < 4) { issueB(pi + 1); CPA_WAIT(1); }
        else            { CPA_WAIT(0); }
        __syncthreads();

        float accA[32], accB[32];
        #pragma unroll
        for (int i = 0; i < 32; i++) { accA[i] = 0.f; accB[i] = 0.f; }

        uint32_t bbase = sb + MSZ + (uint32_t)((pi & 1) * MSZ);
        #pragma unroll
        for (int kc = 0; kc < NKC; kc++) {
            uint32_t ab = sb + (uint32_t)(kc * 16384);
            uint32_t bb = bbase + (uint32_t)(kc * 16384);
            mma_chunk2f<4>(ab, bb + (uint32_t)(wc * 64 * 128), wr * 32, lane, accA, accB);
        }

        int pt = pt0 + pi;
        #pragma unroll
        for (int g = 0; g < 4; g++) {
            #pragma unroll
            for (int hf = 0; hf < 2; hf++) {
                int pcol = pt * 128 + wc * 64 + (g * 2 + hf) * 8 + (lane & 3) * 2;
                float bv0 = bias[(size_t)e * PP + pcol];
                float bv1 = bias[(size_t)e * PP + pcol + 1];
                float* pa = accA + g * 8 + hf * 4;
                float* pb = accB + g * 8 + hf * 4;
                int rows[4] = {rA0, rA0 + 8, rA0 + 16, rA0 + 24};
                float* vals[4] = {pa, pa + 2, pb, pb + 2};
                #pragma unroll
                for (int rv = 0; rv < 4; rv++) {
                    if (start + rows[rv] < end) {
                        int b = sidx[rows[rv]];
                        *(float2*)&out[(size_t)b * PP + pcol] =
                            make_float2(vals[rv][0] + bv0, vals[rv][1] + bv1);
                    }
                }
            }
        }
        __syncthreads();
    }
}

#define PROJ_SMEM 98304

__global__ __launch_bounds__(256) void k_tproj(
    const float* __restrict__ bpr0, const float* __restrict__ bpr1,
    float* __restrict__ out)
{
    extern __shared__ char smx[];
    __shared__ int sidx[128];
    const int level = blockIdx.z >> 1;
    const int half4 = blockIdx.z & 1;
    if (level == 0)
        tproj_impl<CC0>(g_h0f, g_wp0f, bpr0, out + OFF_CP0, half4, smx, sidx);
    else
        tproj_impl<CC1>(g_h1f, g_wp1f, bpr1, out + OFF_CP1, half4, smx, sidx);
}

// ---------------------------------------------------------------------------

extern "C" void kernel_launch(void* const* d_in, const int* in_sizes, int n_in,
                              void* d_out, int out_size) {
    const float* x       = (const float*)d_in[0];
    const float* pw_fc   = (const float*)d_in[1];
    const float* pb_fc   = (const float*)d_in[2];
    const float* pw_proj = (const float*)d_in[3];
    const float* pb_proj = (const float*)d_in[4];
    const float* cw_fc0  = (const float*)d_in[5];
    const float* cb_fc0  = (const float*)d_in[6];
    const float* cw_pr0  = (const float*)d_in[7];
    const float* cb_pr0  = (const float*)d_in[8];
    const float* cw_fc1  = (const float*)d_in[9];
    const float* cb_fc1  = (const float*)d_in[10];
    const float* cw_pr1  = (const float*)d_in[11];
    const float* cb_pr1  = (const float*)d_in[12];
    float* out = (float*)d_out;

    static cudaStream_t sA = nullptr;
    static cudaEvent_t e0, evS, evC, evP;
    if (!sA) {
        cudaStreamCreate(&sA);
        cudaEventCreateWithFlags(&e0, cudaEventDisableTiming);
        cudaEventCreateWithFlags(&evS, cudaEventDisableTiming);
        cudaEventCreateWithFlags(&evC, cudaEventDisableTiming);
        cudaEventCreateWithFlags(&evP, cudaEventDisableTiming);
        cudaFuncSetAttribute(k_tfc, cudaFuncAttributeMaxDynamicSharedMemorySize, FC_SMEM);
        cudaFuncSetAttribute(k_tproj, cudaFuncAttributeMaxDynamicSharedMemorySize, PROJ_SMEM);
    }

    cudaEventRecord(e0, 0);
    cudaStreamWaitEvent(sA, e0, 0);

    // stream 0: parent fc -> bucket/tiles
    k_parent_fc<<<BB / 32, 128>>>(x, pw_fc, pb_fc, out + OFF_PL);
    k_scansc<<<1, 1024>>>();
    cudaEventRecord(evS, 0);

    // stream A: converts + parent proj
    k_cvtx<<<BB * DD / 4 / 256, 256, 0, sA>>>(x);
    k_cvtwfc<<<dim3(4096, 2), 256, 0, sA>>>(cw_fc0, cw_fc1);
    cudaEventRecord(evC, sA);
    cudaStreamWaitEvent(sA, evS, 0);
    k_parent_proj<<<BB / 64, 256, 0, sA>>>(out + OFF_PL, pw_proj, pb_proj, out + OFF_PP);

    // stream 0: child fc GEMM (fp16, 3x fewer MMAs, 2x fewer bytes)
    cudaStreamWaitEvent(0, evC, 0);
    k_tfc<<<dim3(80, 1, 8), 256, FC_SMEM>>>();

    // stream A: proj weight cvt
    k_cvtwpr<<<dim3(2048, 2), 256, 0, sA>>>(cw_pr0, cw_pr1);
    cudaEventRecord(evP, sA);

    // stream 0
    k_fcred<<<dim3(BB / 8, 2), 256>>>(cb_fc0, cb_fc1, out);
    cudaStreamWaitEvent(0, evP, 0);
    k_tproj<<<dim3(80, 1, 4), 256, PROJ_SMEM>>>(cb_pr0, cb_pr1, out);
}

// round 17
// speedup vs baseline: 4.9402x; 1.3060x over previous
#include <cuda_runtime.h>
#include <cuda_fp16.h>
#include <cstdint>

#define BB 8192
#define DD 2048
#define EE 16
#define PP 1024
#define CC0 64
#define CC1 128
#define LN_EPS 1e-5f

#define OFF_PL  0
#define OFF_CL0 (BB*EE)
#define OFF_CL1 (OFF_CL0 + BB*CC0)
#define OFF_PP  (OFF_CL1 + BB*CC1)
#define OFF_CP0 (OFF_PP + BB*PP)
#define OFF_CP1 (OFF_CP0 + BB*PP)

typedef unsigned long long u64t;

// ------------------------- scratch globals -------------------------
__device__ int g_class[BB];
__device__ int g_cnt[EE];
__device__ int g_sidxE[EE * BB];   // per-expert buckets
__device__ int g_tiles[96];
__device__ int g_ntiles;

__device__ float g_ppart[4 * BB * EE];  // parent fc split-K partials

__device__ __half g_xf[BB * DD];
__device__ __half g_wfc0f[EE * CC0 * DD], g_wfc1f[EE * CC1 * DD];
__device__ __half g_wp0f[EE * PP * CC0], g_wp1f[EE * PP * CC1];
__device__ __half g_h0f[BB * CC0], g_h1f[BB * CC1];

__device__ float g_pt0[4 * BB * CC0];
__device__ float g_pt1[4 * BB * CC1];

// ------------------------- asm helpers (sm_80+ generic) ---------------
__device__ __forceinline__ uint32_t smem_u32(const void* p) {
    uint32_t a;
    asm("{ .reg .u64 t; cvta.to.shared.u64 t, %1; cvt.u32.u64 %0, t; }"
        : "=r"(a) : "l"(p));
    return a;
}
#define CPA(dst, src) \
    asm volatile("cp.async.cg.shared.global [%0], [%1], 16;" :: "r"(dst), "l"(src) : "memory")
#define CPA_COMMIT() asm volatile("cp.async.commit_group;" ::: "memory")
#define CPA_WAIT(n)  asm volatile("cp.async.wait_group %0;" :: "n"(n) : "memory")
#define LDM4(r, addr) \
    asm volatile("ldmatrix.sync.aligned.m8n8.x4.shared.b16 {%0,%1,%2,%3}, [%4];" \
                 : "=r"((r)[0]), "=r"((r)[1]), "=r"((r)[2]), "=r"((r)[3]) : "r"(addr))

__device__ __forceinline__ void mma_f16(float* c, const uint32_t* a,
                                        uint32_t b0, uint32_t b1) {
    asm volatile(
        "mma.sync.aligned.m16n8k16.row.col.f32.f16.f16.f32 "
        "{%0,%1,%2,%3}, {%4,%5,%6,%7}, {%8,%9}, {%0,%1,%2,%3};"
        : "+f"(c[0]), "+f"(c[1]), "+f"(c[2]), "+f"(c[3])
        : "r"(a[0]), "r"(a[1]), "r"(a[2]), "r"(a[3]), "r"(b0), "r"(b1));
}

// plain fp16, two 16-row subtiles sharing B fragments. NG groups of 16 cols.
template <int NG>
__device__ __forceinline__ void mma_chunk2f(uint32_t A, uint32_t B,
                                            int m0, int lane,
                                            float* accA, float* accB) {
    const int arow0 = m0 + (lane & 15);
    const uint32_t aoff0 = (uint32_t)arow0 * 128u;
    const uint32_t aoff1 = aoff0 + 16u * 128u;
    const uint32_t axr = (uint32_t)((arow0 & 7) << 4);
    const uint32_t acb0 = (uint32_t)((lane >> 4) << 4);
    const int brl = ((lane >> 4) & 1) * 8 + (lane & 7);
    const uint32_t bcb0 = (uint32_t)(((lane >> 3) & 1) << 4);
    #pragma unroll
    for (int ks = 0; ks < 4; ks++) {
        uint32_t acb = ((uint32_t)(ks * 32) + acb0) ^ axr;
        uint32_t a0[4], a1[4];
        LDM4(a0, A + aoff0 + acb);
        LDM4(a1, A + aoff1 + acb);
        #pragma unroll
        for (int g = 0; g < NG; g++) {
            int brow = g * 16 + brl;
            uint32_t boff = (uint32_t)brow * 128u
                            + (((uint32_t)(ks * 32) + bcb0) ^ (uint32_t)((brow & 7) << 4));
            uint32_t b[4];
            LDM4(b, B + boff);
            mma_f16(accA + g * 8,     a0, b[0], b[1]);
            mma_f16(accA + g * 8 + 4, a0, b[2], b[3]);
            mma_f16(accB + g * 8,     a1, b[0], b[1]);
            mma_f16(accB + g * 8 + 4, a1, b[2], b[3]);
        }
    }
}

// ------------------------- small/cvt kernels -------------------------
__global__ void k_init() {
    if (threadIdx.x < EE) g_cnt[threadIdx.x] = 0;
}

__global__ void k_cvtx(const float* __restrict__ src) {
    int i4 = blockIdx.x * 256 + threadIdx.x;
    if (i4 * 4 < BB * DD) {
        float4 v = ((const float4*)src)[i4];
        ((__half2*)g_xf)[i4 * 2 + 0] = __floats2half2_rn(v.x, v.y);
        ((__half2*)g_xf)[i4 * 2 + 1] = __floats2half2_rn(v.z, v.w);
    }
}

__global__ void k_cvtwfc(const float* __restrict__ sa, const float* __restrict__ sb) {
    const int sel = blockIdx.y;
    const float* src = sel ? sb : sa;
    __half* df = sel ? g_wfc1f : g_wfc0f;
    const int n = sel ? EE * CC1 * DD : EE * CC0 * DD;
    int i4 = blockIdx.x * 256 + threadIdx.x;
    if (i4 * 4 < n) {
        float4 v = ((const float4*)src)[i4];
        ((__half2*)df)[i4 * 2 + 0] = __floats2half2_rn(v.x, v.y);
        ((__half2*)df)[i4 * 2 + 1] = __floats2half2_rn(v.z, v.w);
    }
}

__global__ void k_cvtwpr(const float* __restrict__ sa, const float* __restrict__ sb) {
    const int sel = blockIdx.y;
    const float* src = sel ? sb : sa;
    __half* df = sel ? g_wp1f : g_wp0f;
    const int n = sel ? EE * PP * CC1 : EE * PP * CC0;
    int i4 = blockIdx.x * 256 + threadIdx.x;
    if (i4 * 4 < n) {
        float4 v = ((const float4*)src)[i4];
        ((__half2*)df)[i4 * 2 + 0] = __floats2half2_rn(v.x, v.y);
        ((__half2*)df)[i4 * 2 + 1] = __floats2half2_rn(v.z, v.w);
    }
}

// tile list from per-expert counts (1 warp)
__global__ void k_tiles() {
    if (threadIdx.x == 0) {
        int nt = 0;
        for (int e = 0; e < EE; e++) {
            int m = (g_cnt[e] + 127) >> 7;
            for (int i = 0; i < m; i++) g_tiles[nt++] = (e << 16) | i;
        }
        g_ntiles = nt;
    }
}

// ------------------------- parent FC split-K (exact fp32) ---------------
// grid (BB/32, 4): y = ksplit of 512. BM=32, 128 threads.
__global__ __launch_bounds__(128) void k_pfc_part(
    const float* __restrict__ x, const float* __restrict__ w)
{
    __shared__ __align__(16) float xs[32][36];
    __shared__ __align__(16) float ws[32][20];
    __shared__ float spart[4][32][17];

    const int t = threadIdx.x;
    const int rowg = t & 7;
    const int eg = (t >> 3) & 3;
    const int kg = t >> 5;
    const int brow = blockIdx.x * 32;
    const int ks = blockIdx.y;

    float acc[4][4];
    #pragma unroll
    for (int i = 0; i < 4; i++)
        #pragma unroll
        for (int j = 0; j < 4; j++) acc[i][j] = 0.f;

    for (int kt = ks * 16; kt < ks * 16 + 16; kt++) {
        float4 rx[2];
        float4 rw;
        #pragma unroll
        for (int i = 0; i < 2; i++) {
            int s = t + i * 128;
            int row = s >> 3, kq = s & 7;
            rx[i] = *(const float4*)&x[(size_t)(brow + row) * DD + kt * 32 + kq * 4];
        }
        {
            int e2 = t >> 3, kq = t & 7;
            rw = *(const float4*)&w[(size_t)e2 * DD + kt * 32 + kq * 4];
        }
        __syncthreads();
        #pragma unroll
        for (int i = 0; i < 2; i++) {
            int s = t + i * 128;
            int row = s >> 3, kq = s & 7;
            xs[kq * 4 + 0][row] = rx[i].x;
            xs[kq * 4 + 1][row] = rx[i].y;
            xs[kq * 4 + 2][row] = rx[i].z;
            xs[kq * 4 + 3][row] = rx[i].w;
        }
        {
            int e2 = t >> 3, kq = t & 7;
            ws[kq * 4 + 0][e2] = rw.x;
            ws[kq * 4 + 1][e2] = rw.y;
            ws[kq * 4 + 2][e2] = rw.z;
            ws[kq * 4 + 3][e2] = rw.w;
        }
        __syncthreads();
        #pragma unroll
        for (int kk2 = 0; kk2 < 8; kk2++) {
            int kk = kg * 8 + kk2;
            float4 a0 = *(const float4*)&xs[kk][rowg * 4];
            float4 bq = *(const float4*)&ws[kk][eg * 4];
            float av[4] = {a0.x, a0.y, a0.z, a0.w};
            float bv[4] = {bq.x, bq.y, bq.z, bq.w};
            #pragma unroll
            for (int i = 0; i < 4; i++)
                #pragma unroll
                for (int j = 0; j < 4; j++) acc[i][j] += av[i] * bv[j];
        }
        __syncthreads();
    }

    #pragma unroll
    for (int i = 0; i < 4; i++) {
        int r = rowg * 4 + i;
        #pragma unroll
        for (int j = 0; j < 4; j++) spart[kg][r][eg * 4 + j] = acc[i][j];
    }
    __syncthreads();

    if (t < 32) {
        int b = brow + t;
        #pragma unroll
        for (int q = 0; q < 4; q++) {
            float4 o;
            o.x = spart[0][t][q * 4 + 0] + spart[1][t][q * 4 + 0]
                + spart[2][t][q * 4 + 0] + spart[3][t][q * 4 + 0];
            o.y = spart[0][t][q * 4 + 1] + spart[1][t][q * 4 + 1]
                + spart[2][t][q * 4 + 1] + spart[3][t][q * 4 + 1];
            o.z = spart[0][t][q * 4 + 2] + spart[1][t][q * 4 + 2]
                + spart[2][t][q * 4 + 2] + spart[3][t][q * 4 + 2];
            o.w = spart[0][t][q * 4 + 3] + spart[1][t][q * 4 + 3]
                + spart[2][t][q * 4 + 3] + spart[3][t][q * 4 + 3];
            *(float4*)&g_ppart[((size_t)ks * BB + b) * 16 + q * 4] = o;
        }
    }
}

// reduce + bias + LN + argmax + bucket scatter. grid (BB/256, 256).
__global__ __launch_bounds__(256) void k_pfc_red(
    const float* __restrict__ bias, float* __restrict__ out_pl)
{
    const int b = blockIdx.x * 256 + threadIdx.x;
    float z[16];
    #pragma unroll
    for (int q = 0; q < 4; q++) {
        float4 s0 = *(const float4*)&g_ppart[((size_t)0 * BB + b) * 16 + q * 4];
        float4 s1 = *(const float4*)&g_ppart[((size_t)1 * BB + b) * 16 + q * 4];
        float4 s2 = *(const float4*)&g_ppart[((size_t)2 * BB + b) * 16 + q * 4];
        float4 s3 = *(const float4*)&g_ppart[((size_t)3 * BB + b) * 16 + q * 4];
        float4 bb = *(const float4*)&bias[q * 4];
        z[q * 4 + 0] = s0.x + s1.x + s2.x + s3.x + bb.x;
        z[q * 4 + 1] = s0.y + s1.y + s2.y + s3.y + bb.y;
        z[q * 4 + 2] = s0.z + s1.z + s2.z + s3.z + bb.z;
        z[q * 4 + 3] = s0.w + s1.w + s2.w + s3.w + bb.w;
    }
    float mu = 0.f;
    #pragma unroll
    for (int e = 0; e < 16; e++) mu += z[e];
    mu *= (1.f / 16.f);
    float var = 0.f;
    #pragma unroll
    for (int e = 0; e < 16; e++) { float d = z[e] - mu; var += d * d; }
    var *= (1.f / 16.f);
    float rs = rsqrtf(var + LN_EPS);

    float best = z[0];
    int cls = 0;
    #pragma unroll
    for (int e = 1; e < 16; e++)
        if (z[e] > best) { best = z[e]; cls = e; }  // first-max

    #pragma unroll
    for (int q = 0; q < 4; q++) {
        float4 o = make_float4((z[q * 4 + 0] - mu) * rs, (z[q * 4 + 1] - mu) * rs,
                               (z[q * 4 + 2] - mu) * rs, (z[q * 4 + 3] - mu) * rs);
        *(float4*)&out_pl[(size_t)b * 16 + q * 4] = o;
    }
    g_class[b] = cls;
    int pos = atomicAdd(&g_cnt[cls], 1);
    g_sidxE[cls * BB + pos] = b;
}

// ------------------------- parent proj -------------------------
__global__ __launch_bounds__(256) void k_parent_proj(
    const float* __restrict__ pl, const float* __restrict__ w,
    const float* __restrict__ bias, float* __restrict__ out)
{
    __shared__ __align__(16) float spl[64][20];
    const int t = threadIdx.x;
    const int brow = blockIdx.x * 64;

    {
        int row = t >> 2, q = t & 3;
        float4 g = *(const float4*)&pl[(size_t)(brow + row) * 16 + q * 4];
        spl[row][q * 4 + 0] = g.x;
        spl[row][q * 4 + 1] = g.y;
        spl[row][q * 4 + 2] = g.z;
        spl[row][q * 4 + 3] = g.w;
    }
    __syncthreads();

    for (int pass = 0; pass < 2; pass++) {
        int p0 = pass * 512 + t * 2;
        float w0[16], w1[16];
        #pragma unroll
        for (int q = 0; q < 4; q++) {
            float4 a = *(const float4*)&w[(size_t)p0 * 16 + q * 4];
            w0[q * 4 + 0] = a.x; w0[q * 4 + 1] = a.y; w0[q * 4 + 2] = a.z; w0[q * 4 + 3] = a.w;
            float4 c = *(const float4*)&w[(size_t)(p0 + 1) * 16 + q * 4];
            w1[q * 4 + 0] = c.x; w1[q * 4 + 1] = c.y; w1[q * 4 + 2] = c.z; w1[q * 4 + 3] = c.w;
        }
        float b0 = bias[p0], b1 = bias[p0 + 1];

        for (int r = 0; r < 64; r++) {
            float a0 = b0, a1 = b1;
            #pragma unroll
            for (int q = 0; q < 4; q++) {
                float4 v = *(const float4*)&spl[r][q * 4];
                a0 += v.x * w0[q * 4 + 0] + v.y * w0[q * 4 + 1] + v.z * w0[q * 4 + 2] + v.w * w0[q * 4 + 3];
                a1 += v.x * w1[q * 4 + 0] + v.y * w1[q * 4 + 1] + v.z * w1[q * 4 + 2] + v.w * w1[q * 4 + 3];
            }
            float2 o = make_float2(a0, a1);
            *(float2*)&out[(size_t)(brow + r) * PP + p0] = o;
        }
    }
}

// ===========================================================================
// Child FC split-K GEMM (fp16), bucket addressing. grid (80, 1, 8).
// ===========================================================================
template <int BN>
__device__ __forceinline__ void tfc_impl(
    const __half* __restrict__ x, const __half* __restrict__ w,
    float* __restrict__ part, int ks, char* sm, int* sidx)
{
    if (blockIdx.x >= (unsigned)g_ntiles) return;
    const int pk = g_tiles[blockIdx.x];
    const int e = pk >> 16;
    const int base = (pk & 0xffff) * 128;
    const int cnt = g_cnt[e];

    const int t = threadIdx.x;
    const int wid = t >> 5, lane = t & 31;
    const int wr = wid & 3, wc = wid >> 2;
    const uint32_t sb = smem_u32(sm);
    const int kbase = ks * 512;

    constexpr int B0 = 16384;
    constexpr int BUF = 16384 + BN * 128;
    constexpr int NGW = BN / 32;

    if (t < 128) {
        int gi = base + t;
        sidx[t] = g_sidxE[e * BB + (gi < cnt ? gi : cnt - 1)];
    }
    __syncthreads();

    auto issue = [&](int kt) {
        uint32_t bse = sb + (uint32_t)((kt & 1) * BUF);
        #pragma unroll
        for (int i = 0; i < 4; i++) {
            int d = t + i * 256;
            int row = d >> 3, ch = d & 7;
            uint32_t off = (uint32_t)(row * 128 + ((ch * 16) ^ ((row & 7) << 4)));
            size_t g = (size_t)sidx[row] * DD + kbase + kt * 64 + ch * 8;
            CPA(bse + off, x + g);
        }
        #pragma unroll
        for (int i = 0; i < BN / 32; i++) {
            int d = t + i * 256;
            int row = d >> 3, ch = d & 7;
            uint32_t off = (uint32_t)(row * 128 + ((ch * 16) ^ ((row & 7) << 4)));
            size_t g = ((size_t)e * BN + row) * DD + kbase + kt * 64 + ch * 8;
            CPA(bse + B0 + off, w + g);
        }
        CPA_COMMIT();
    };

    float accA[NGW * 8], accB[NGW * 8];
    #pragma unroll
    for (int i = 0; i < NGW * 8; i++) { accA[i] = 0.f; accB[i] = 0.f; }

    issue(0);
    const int NKT = 8;
    for (int kt = 0; kt < NKT; kt++) {
        if (kt + 1 < NKT) { issue(kt + 1); CPA_WAIT(1); }
        else              { CPA_WAIT(0); }
        __syncthreads();
        uint32_t bse = sb + (uint32_t)((kt & 1) * BUF);
        mma_chunk2f<NGW>(bse, bse + B0 + (uint32_t)(wc * (BN / 2) * 128),
                         wr * 32, lane, accA, accB);
        __syncthreads();
    }

    const int rA0 = wr * 32 + (lane >> 2);
    #pragma unroll
    for (int g = 0; g < NGW; g++) {
        #pragma unroll
        for (int half = 0; half < 2; half++) {
            int col = wc * (BN / 2) + (g * 2 + half) * 8 + (lane & 3) * 2;
            float* pa = accA + g * 8 + half * 4;
            float* pb = accB + g * 8 + half * 4;
            int rows[4] = {rA0, rA0 + 8, rA0 + 16, rA0 + 24};
            float* vals[4] = {pa, pa + 2, pb, pb + 2};
            #pragma unroll
            for (int rv = 0; rv < 4; rv++) {
                if (base + rows[rv] < cnt) {
                    int b = sidx[rows[rv]];
                    *(float2*)&part[(size_t)ks * BB * BN + (size_t)b * BN + col] =
                        make_float2(vals[rv][0], vals[rv][1]);
                }
            }
        }
    }
}

#define FC_SMEM 65536

__global__ __launch_bounds__(256) void k_tfc() {
    extern __shared__ char smx[];
    __shared__ int sidx[128];
    if (blockIdx.z < 4)
        tfc_impl<CC1>(g_xf, g_wfc1f, g_pt1, blockIdx.z, smx, sidx);
    else
        tfc_impl<CC0>(g_xf, g_wfc0f, g_pt0, blockIdx.z - 4, smx, sidx);
}

// ===========================================================================
// FC reduce by raw row: sum 4 partials + bias + LN + cl + h fp16.
// ===========================================================================
template <int BN>
__device__ __forceinline__ void fcred_impl(
    const float* __restrict__ part, const float* __restrict__ bias,
    float* __restrict__ out, __half* __restrict__ hf)
{
    const int b = blockIdx.x * 8 + (threadIdx.x >> 5);
    const int lane = threadIdx.x & 31;
    const int e = g_class[b];
    constexpr int NC = BN / 32;

    float v[NC];
    float s = 0.f, q = 0.f;
    #pragma unroll
    for (int i = 0; i < NC; i++) {
        int col = lane + i * 32;
        size_t idx = (size_t)b * BN + col;
        float a = part[idx] + part[(size_t)BB * BN + idx]
                + part[2 * (size_t)BB * BN + idx] + part[3 * (size_t)BB * BN + idx]
                + bias[e * BN + col];
        v[i] = a;
        s += a;
        q += a * a;
    }
    #pragma unroll
    for (int o = 16; o; o >>= 1) {
        s += __shfl_xor_sync(~0u, s, o);
        q += __shfl_xor_sync(~0u, q, o);
    }
    float mu = s * (1.f / BN);
    float rs = rsqrtf(q * (1.f / BN) - mu * mu + LN_EPS);
    #pragma unroll
    for (int i = 0; i < NC; i++) {
        int col = lane + i * 32;
        float o = (v[i] - mu) * rs;
        out[(size_t)b * BN + col] = o;
        hf[(size_t)b * BN + col] = __float2half_rn(o);
    }
}

__global__ __launch_bounds__(256) void k_fcred(
    const float* __restrict__ b0, const float* __restrict__ b1,
    float* __restrict__ out)
{
    if (blockIdx.y == 0)
        fcred_impl<CC0>(g_pt0, b0, out + OFF_CL0, g_h0f);
    else
        fcred_impl<CC1>(g_pt1, b1, out + OFF_CL1, g_h1f);
}

// ===========================================================================
// Child proj (fp16): bucket tiles, A resident, 4 p-tiles dbuf B.
// ===========================================================================
template <int CK>
__device__ __forceinline__ void tproj_impl(
    const __half* __restrict__ a, const __half* __restrict__ w,
    const float* __restrict__ bias, float* __restrict__ out,
    int half4, char* sm, int* sidx)
{
    if (blockIdx.x >= (unsigned)g_ntiles) return;
    const int pk = g_tiles[blockIdx.x];
    const int e = pk >> 16;
    const int base = (pk & 0xffff) * 128;
    const int cnt = g_cnt[e];

    constexpr int NKC = CK / 64;
    const int t = threadIdx.x;
    const int wid = t >> 5, lane = t & 31;
    const int wr = wid & 3, wc = wid >> 2;
    const uint32_t sb = smem_u32(sm);
    constexpr uint32_t MSZ = (uint32_t)NKC * 16384u;
    const int pt0 = half4 * 4;

    if (t < 128) {
        int gi = base + t;
        sidx[t] = g_sidxE[e * BB + (gi < cnt ? gi : cnt - 1)];
    }
    __syncthreads();

    #pragma unroll
    for (int kc = 0; kc < NKC; kc++) {
        #pragma unroll
        for (int i = 0; i < 4; i++) {
            int s = t + i * 256;
            int row = s >> 3, ch = s & 7;
            uint32_t off = (uint32_t)(kc * 16384 + row * 128 + ((ch * 16) ^ ((row & 7) << 4)));
            size_t ga = (size_t)sidx[row] * CK + kc * 64 + ch * 8;
            CPA(sb + off, a + ga);
        }
    }

    auto issueB = [&](int pi) {
        uint32_t bse = sb + MSZ + (uint32_t)((pi & 1) * MSZ);
        int pt = pt0 + pi;
        #pragma unroll
        for (int kc = 0; kc < NKC; kc++) {
            #pragma unroll
            for (int i = 0; i < 4; i++) {
                int s = t + i * 256;
                int row = s >> 3, ch = s & 7;
                uint32_t off = (uint32_t)(kc * 16384 + row * 128
                                          + ((ch * 16) ^ ((row & 7) << 4)));
                size_t gb = ((size_t)(e * PP + pt * 128 + row)) * CK + kc * 64 + ch * 8;
                CPA(bse + off, w + gb);
            }
        }
        CPA_COMMIT();
    };

    issueB(0);

    const int rA0 = wr * 32 + (lane >> 2);
    for (int pi = 0; pi < 4; pi++) {
        if (pi + 1 < 4) { issueB(pi + 1); CPA_WAIT(1); }
        else            { CPA_WAIT(0); }
        __syncthreads();

        float accA[32], accB[32];
        #pragma unroll
        for (int i = 0; i < 32; i++) { accA[i] = 0.f; accB[i] = 0.f; }

        uint32_t bbase = sb + MSZ + (uint32_t)((pi & 1) * MSZ);
        #pragma unroll
        for (int kc = 0; kc < NKC; kc++) {
            uint32_t ab = sb + (uint32_t)(kc * 16384);
            uint32_t bb = bbase + (uint32_t)(kc * 16384);
            mma_chunk2f<4>(ab, bb + (uint32_t)(wc * 64 * 128), wr * 32, lane, accA, accB);
        }

        int pt = pt0 + pi;
        #pragma unroll
        for (int g = 0; g < 4; g++) {
            #pragma unroll
            for (int hf = 0; hf < 2; hf++) {
                int pcol = pt * 128 + wc * 64 + (g * 2 + hf) * 8 + (lane & 3) * 2;
                float bv0 = bias[(size_t)e * PP + pcol];
                float bv1 = bias[(size_t)e * PP + pcol + 1];
                float* pa = accA + g * 8 + hf * 4;
                float* pb = accB + g * 8 + hf * 4;
                int rows[4] = {rA0, rA0 + 8, rA0 + 16, rA0 + 24};
                float* vals[4] = {pa, pa + 2, pb, pb + 2};
                #pragma unroll
                for (int rv = 0; rv < 4; rv++) {
                    if (base + rows[rv] < cnt) {
                        int b = sidx[rows[rv]];
                        *(float2*)&out[(size_t)b * PP + pcol] =
                            make_float2(vals[rv][0] + bv0, vals[rv][1] + bv1);
                    }
                }
            }
        }
        __syncthreads();
    }
}

#define PROJ_SMEM 98304

__global__ __launch_bounds__(256) void k_tproj(
    const float* __restrict__ bpr0, const float* __restrict__ bpr1,
    float* __restrict__ out)
{
    extern __shared__ char smx[];
    __shared__ int sidx[128];
    const int level = blockIdx.z >> 1;
    const int half4 = blockIdx.z & 1;
    if (level == 0)
        tproj_impl<CC0>(g_h0f, g_wp0f, bpr0, out + OFF_CP0, half4, smx, sidx);
    else
        tproj_impl<CC1>(g_h1f, g_wp1f, bpr1, out + OFF_CP1, half4, smx, sidx);
}

// ---------------------------------------------------------------------------

extern "C" void kernel_launch(void* const* d_in, const int* in_sizes, int n_in,
                              void* d_out, int out_size) {
    const float* x       = (const float*)d_in[0];
    const float* pw_fc   = (const float*)d_in[1];
    const float* pb_fc   = (const float*)d_in[2];
    const float* pw_proj = (const float*)d_in[3];
    const float* pb_proj = (const float*)d_in[4];
    const float* cw_fc0  = (const float*)d_in[5];
    const float* cb_fc0  = (const float*)d_in[6];
    const float* cw_pr0  = (const float*)d_in[7];
    const float* cb_pr0  = (const float*)d_in[8];
    const float* cw_fc1  = (const float*)d_in[9];
    const float* cb_fc1  = (const float*)d_in[10];
    const float* cw_pr1  = (const float*)d_in[11];
    const float* cb_pr1  = (const float*)d_in[12];
    float* out = (float*)d_out;

    static cudaStream_t sA = nullptr;
    static cudaEvent_t e0, evS, evC, evP, evQ;
    if (!sA) {
        cudaStreamCreate(&sA);
        cudaEventCreateWithFlags(&e0, cudaEventDisableTiming);
        cudaEventCreateWithFlags(&evS, cudaEventDisableTiming);
        cudaEventCreateWithFlags(&evC, cudaEventDisableTiming);
        cudaEventCreateWithFlags(&evP, cudaEventDisableTiming);
        cudaEventCreateWithFlags(&evQ, cudaEventDisableTiming);
        cudaFuncSetAttribute(k_tfc, cudaFuncAttributeMaxDynamicSharedMemorySize, FC_SMEM);
        cudaFuncSetAttribute(k_tproj, cudaFuncAttributeMaxDynamicSharedMemorySize, PROJ_SMEM);
    }

    cudaEventRecord(e0, 0);
    cudaStreamWaitEvent(sA, e0, 0);

    // stream 0: parent fc split-K -> reduce (LN/argmax/bucket) -> tiles
    k_init<<<1, 32>>>();
    k_pfc_part<<<dim3(BB / 32, 4), 128>>>(x, pw_fc);
    k_pfc_red<<<BB / 256, 256>>>(pb_fc, out + OFF_PL);
    cudaEventRecord(evS, 0);
    k_tiles<<<1, 32>>>();

    // stream A: converts (both), then parent proj (off critical path)
    k_cvtx<<<BB * DD / 4 / 256, 256, 0, sA>>>(x);
    k_cvtwfc<<<dim3(4096, 2), 256, 0, sA>>>(cw_fc0, cw_fc1);
    cudaEventRecord(evC, sA);
    k_cvtwpr<<<dim3(2048, 2), 256, 0, sA>>>(cw_pr0, cw_pr1);
    cudaEventRecord(evP, sA);
    cudaStreamWaitEvent(sA, evS, 0);
    k_parent_proj<<<BB / 64, 256, 0, sA>>>(out + OFF_PL, pw_proj, pb_proj, out + OFF_PP);
    cudaEventRecord(evQ, sA);  // final join event covering ALL stream-A work

    // stream 0: children
    cudaStreamWaitEvent(0, evC, 0);
    k_tfc<<<dim3(80, 1, 8), 256, FC_SMEM>>>();
    k_fcred<<<dim3(BB / 8, 2), 256>>>(cb_fc0, cb_fc1, out);
    cudaStreamWaitEvent(0, evP, 0);
    cudaStreamWaitEvent(0, evQ, 0);  // join stream A fully before last node
    k_tproj<<<dim3(80, 1, 4), 256, PROJ_SMEM>>>(cb_pr0, cb_pr1, out);
}